// round 1
// baseline (speedup 1.0000x reference)
#include <cuda_runtime.h>
#include <math.h>

// ---------------- problem constants ----------------
#define NB 8            // batch
#define NPIX 1024       // N pixels
#define NS 8            // slots
#define D 256           // feature dim
#define H 512           // hidden dim of grid_enc
#define NROWS (NB*NPIX) // 8192
#define EPSA 1e-8f
#define LNEPS 1e-5f
#define ATTN_SCALE 0.0625f   // 256^-0.5
#define GSTEP (2.0f/31.0f)

// ---------------- scratch (device globals; no runtime alloc) ----------------
__device__ float g_X [NROWS*D];
__device__ float g_K [NROWS*D];
__device__ float g_V [NROWS*D];
__device__ float g_Pk[NROWS*H];
__device__ float g_Pv[NROWS*H];
__device__ float g_statsK[NROWS*4];
__device__ float g_statsV[NROWS*4];
__device__ float g_meanK[NROWS];
__device__ float g_meanV[NROWS];
__device__ float g_U0[H], g_U1[H], g_Ub[H], g_C[H], g_G1[H];
__device__ float g_cov[16];
__device__ float g_Cond[NB*NS*260];
__device__ float g_slot[NB*NS*520];   // [0..511]=wtil, 512=qb2,513=px,514=py,515=i5x,516=i5y
__device__ float g_dots [NB*NS*NPIX];
__device__ float g_attn0[NB*NS*NPIX];
__device__ float g_red[NB*NS*4];      // [0]=inv attn denom
__device__ float g_s[NB*NS*H];

// ---------------- helpers ----------------
__device__ __forceinline__ float blockSum256(float v, float* red) {
    int t = threadIdx.x;
    #pragma unroll
    for (int o = 16; o; o >>= 1) v += __shfl_xor_sync(0xffffffffu, v, o);
    if ((t & 31) == 0) red[t >> 5] = v;
    __syncthreads();
    if (t == 0) {
        float r = 0.f;
        #pragma unroll
        for (int w = 0; w < 8; w++) r += red[w];
        red[0] = r;
    }
    __syncthreads();
    float r = red[0];
    __syncthreads();
    return r;
}

// ---------------- constants kernel ----------------
__global__ void const_kernel(const float* __restrict__ gp_w, const float* __restrict__ gp_b,
                             const float* __restrict__ lg,   const float* __restrict__ lb,
                             const float* __restrict__ W1,   const float* __restrict__ b1)
{
    __shared__ float sg0[D], sg1[D], sgb[D], slg[D], slb[D];
    __shared__ float sm[4];
    int t = threadIdx.x; // 512 threads
    if (t < D) { sg0[t]=gp_w[t]; sg1[t]=gp_w[D+t]; sgb[t]=gp_b[t]; slg[t]=lg[t]; slb[t]=lb[t]; }
    __syncthreads();
    if (t == 0) {
        float m0=0,m1=0,mb=0;
        for (int d=0; d<D; d++){ m0+=sg0[d]; m1+=sg1[d]; mb+=sgb[d]; }
        m0*= (1.f/D); m1*=(1.f/D); mb*=(1.f/D);
        float V00=0,V11=0,Vbb=0,C01=0,C0b=0,C1b=0;
        for (int d=0; d<D; d++){
            float a=sg0[d]-m0, b_=sg1[d]-m1, c=sgb[d]-mb;
            V00+=a*a; V11+=b_*b_; Vbb+=c*c; C01+=a*b_; C0b+=a*c; C1b+=b_*c;
        }
        g_cov[0]=m0; g_cov[1]=m1; g_cov[2]=mb;
        g_cov[3]=V00/D; g_cov[4]=V11/D; g_cov[5]=Vbb/D;
        g_cov[6]=C01/D; g_cov[7]=C0b/D; g_cov[8]=C1b/D;
        float s2=0;
        for (int i=0;i<32;i++){ float x=-1.f + i*GSTEP; s2+=x*x; }
        g_cov[9]=s2*32.f;  // G2 = sum_n gx^2
        sm[0]=m0; sm[1]=m1; sm[2]=mb;
    }
    __syncthreads();
    float m0=sm[0], m1=sm[1], mb=sm[2];
    // thread t = hidden index j (0..511)
    float U0=0,U1=0,Ub=0,Cc=0,G1=0;
    for (int d=0; d<D; d++){
        float w = W1[d*H + t];
        float gd = slg[d];
        U0 = fmaf((sg0[d]-m0)*gd, w, U0);
        U1 = fmaf((sg1[d]-m1)*gd, w, U1);
        Ub = fmaf((sgb[d]-mb)*gd, w, Ub);
        Cc = fmaf(slb[d], w, Cc);
        G1 = fmaf(gd, w, G1);
    }
    g_U0[t]=U0; g_U1[t]=U1; g_Ub[t]=Ub; g_C[t]=Cc + b1[t]; g_G1[t]=G1;
}

// ---------------- init conditioning copy ----------------
__global__ void init_cond(const float* __restrict__ cond){
    int i = blockIdx.x*256 + threadIdx.x;
    g_Cond[i] = cond[i];
}

// ---------------- input layernorm ----------------
__global__ void ln_kernel(const float* __restrict__ in, const float* __restrict__ gw,
                          const float* __restrict__ gb)
{
    __shared__ float red[8];
    int r = blockIdx.x, t = threadIdx.x;
    float v = in[r*D + t];
    float m = blockSum256(v, red) * (1.f/D);
    float d = v - m;
    float var = blockSum256(d*d, red) * (1.f/D);
    g_X[r*D + t] = d * rsqrtf(var + LNEPS) * gw[t] + gb[t];
}

// ---------------- tiled fp32 GEMM (M=8192 fixed, K=256 fixed) ----------------
// mode 0: g_K = g_X @ B ; mode 1: g_V = g_X @ B
// mode 2: g_Pk = (g_K*diag(scale)) @ B - meanK*G1 + Ub ; mode 3: same for V
__global__ __launch_bounds__(256) void gemm_kernel(int mode, const float* __restrict__ Bm,
                                                   const float* __restrict__ scaleV, int N)
{
    const float* A = (mode==0||mode==1) ? g_X : (mode==2 ? g_K : g_V);
    float* Cm      = (mode==0) ? g_K : (mode==1) ? g_V : (mode==2) ? g_Pk : g_Pv;
    const float* meanV = (mode==2) ? g_meanK : (mode==3) ? g_meanV : nullptr;

    __shared__ float As[16][64];
    __shared__ float Bs[16][64];
    int bm = blockIdx.y*64, bn = blockIdx.x*64;
    int tid = threadIdx.x;
    int tx = tid & 15, ty = tid >> 4;
    float acc[4][4] = {};

    for (int k0 = 0; k0 < 256; k0 += 16) {
        { // load A tile (64x16), transposed into As[k][m]
            int l = tid*4, rr = l >> 4, kk = l & 15;
            float4 a4 = *(const float4*)(A + (bm+rr)*256 + k0 + kk);
            if (scaleV && mode >= 2) {
                a4.x *= scaleV[k0+kk]; a4.y *= scaleV[k0+kk+1];
                a4.z *= scaleV[k0+kk+2]; a4.w *= scaleV[k0+kk+3];
            }
            As[kk][rr]=a4.x; As[kk+1][rr]=a4.y; As[kk+2][rr]=a4.z; As[kk+3][rr]=a4.w;
        }
        { // load B tile (16x64)
            int l = tid*4, kk = l >> 6, cc = l & 63;
            float4 b4 = *(const float4*)(Bm + (k0+kk)*N + bn + cc);
            *(float4*)&Bs[kk][cc] = b4;
        }
        __syncthreads();
        #pragma unroll
        for (int kk = 0; kk < 16; kk++) {
            float ar[4], br[4];
            #pragma unroll
            for (int i=0;i<4;i++) ar[i]=As[kk][ty*4+i];
            #pragma unroll
            for (int j=0;j<4;j++) br[j]=Bs[kk][tx*4+j];
            #pragma unroll
            for (int i=0;i<4;i++)
                #pragma unroll
                for (int j=0;j<4;j++) acc[i][j] = fmaf(ar[i], br[j], acc[i][j]);
        }
        __syncthreads();
    }
    #pragma unroll
    for (int i=0;i<4;i++){
        int r = bm + ty*4 + i;
        float mk = meanV ? meanV[r] : 0.f;
        #pragma unroll
        for (int j=0;j<4;j++){
            int c = bn + tx*4 + j;
            float val = acc[i][j];
            if (mode >= 2) val = val - mk*g_G1[c] + g_Ub[c];
            Cm[r*N + c] = val;
        }
    }
}

// ---------------- per-row stats for K and V ----------------
__global__ void stats_kernel(const float* __restrict__ gp_w, const float* __restrict__ gp_b)
{
    __shared__ float red[8];
    int r = blockIdx.x, t = threadIdx.x;
    float m0=g_cov[0], m1=g_cov[1], mb=g_cov[2];
    float Vbb=g_cov[5], C0b=g_cov[7], C1b=g_cov[8];
    float g0c = gp_w[t]-m0, g1c = gp_w[D+t]-m1, gbc = gp_b[t]-mb;

    #pragma unroll
    for (int br = 0; br < 2; br++) {
        const float* src = br ? g_V : g_K;
        float kv = src[r*D + t];
        float mk = blockSum256(kv, red) * (1.f/D);
        float d  = kv - mk;
        float Vkk = blockSum256(d*d,  red) * (1.f/D);
        float Ck0 = blockSum256(d*g0c,red) * (1.f/D);
        float Ck1 = blockSum256(d*g1c,red) * (1.f/D);
        float Ckb = blockSum256(d*gbc,red) * (1.f/D);
        if (t == 0) {
            float* st = br ? (g_statsV + r*4) : (g_statsK + r*4);
            st[0] = Vkk + Vbb + 2.f*Ckb;
            st[1] = 2.f*(Ck0 + C0b);
            st[2] = 2.f*(Ck1 + C1b);
            st[3] = 0.f;
            if (br) g_meanV[r]=mk; else g_meanK[r]=mk;
        }
        __syncthreads();
    }
}

// ---------------- per-slot: q, wtil = W2@q, qb2, pos/scl ----------------
__global__ void slot_kernel(const float* __restrict__ ns_g, const float* __restrict__ ns_b,
                            const float* __restrict__ wq,   const float* __restrict__ W2,
                            const float* __restrict__ b2)
{
    __shared__ float red[8];
    __shared__ float sh[D], sq[D];
    int s = blockIdx.x, t = threadIdx.x;
    float sv = g_Cond[s*260 + t];
    float m  = blockSum256(sv, red) * (1.f/D);
    float d0 = sv - m;
    float var = blockSum256(d0*d0, red) * (1.f/D);
    sh[t] = d0 * rsqrtf(var + LNEPS) * ns_g[t] + ns_b[t];
    __syncthreads();
    float q = 0.f;
    for (int d=0; d<D; d++) q = fmaf(sh[d], wq[d*D + t], q);
    sq[t] = q;
    __syncthreads();
    float qb2 = blockSum256(q * b2[t], red);
    for (int j = t; j < H; j += 256) {
        float acc = 0.f;
        const float* w2r = W2 + j*D;
        for (int d=0; d<D; d++) acc = fmaf(w2r[d], sq[d], acc);
        g_slot[s*520 + j] = acc;
    }
    if (t == 0) {
        float px = fminf(fmaxf(g_Cond[s*260+256], -1.f), 1.f);
        float py = fminf(fmaxf(g_Cond[s*260+257], -1.f), 1.f);
        float sx = fminf(fmaxf(g_Cond[s*260+258], 1e-3f), 2.f);
        float sy = fminf(fmaxf(g_Cond[s*260+259], 1e-3f), 2.f);
        float* o = g_slot + s*520 + 512;
        o[0]=qb2; o[1]=px; o[2]=py; o[3]=1.f/(5.f*sx); o[4]=1.f/(5.f*sy);
    }
}

// ---------------- dots: relu(preact_K) . wtil ----------------
__global__ __launch_bounds__(256) void dots_kernel(int writeRel, float* __restrict__ relOut)
{
    int b = blockIdx.y, chunk = blockIdx.x;
    int t = threadIdx.x, w = t >> 5, lane = t & 31;
    __shared__ float sC[H];
    __shared__ float sscal[NS][5];

    float u0[16], u1[16], wt[16];
    const float* wts = g_slot + (b*NS + w)*520;
    #pragma unroll
    for (int jj=0; jj<16; jj++){
        int j = (jj<<5) | lane;
        u0[jj]=g_U0[j]; u1[jj]=g_U1[j]; wt[jj]=wts[j];
    }
    for (int i=t; i<H; i+=256) sC[i]=g_C[i];
    if (t < 40) sscal[t/5][t%5] = g_slot[(b*NS + t/5)*520 + 512 + (t%5)];
    __syncthreads();

    float qb2=sscal[w][0], px=sscal[w][1], py=sscal[w][2], i5x=sscal[w][3], i5y=sscal[w][4];
    float V00=g_cov[3], V11=g_cov[4], C01_2=2.f*g_cov[6];

    for (int nn=0; nn<32; nn++){
        int n = chunk*32 + nn;
        float gx = -1.f + (float)(n>>5)*GSTEP;
        float gy = -1.f + (float)(n&31)*GSTEP;
        float a = (gx-px)*i5x, c = (gy-py)*i5y;
        const float4 st = *(const float4*)(g_statsK + ((b<<10)+n)*4);
        float var = st.x + a*st.y + c*st.z + a*a*V00 + c*c*V11 + a*c*C01_2;
        float isig = rsqrtf(var + LNEPS);
        const float* pk = g_Pk + (((size_t)(b<<10)+n)<<9);
        float acc = 0.f;
        #pragma unroll
        for (int jj=0; jj<16; jj++){
            int j = (jj<<5) | lane;
            float p = fmaf(isig, __ldg(pk+j) + a*u0[jj] + c*u1[jj], sC[j]);
            acc = fmaf(fmaxf(p, 0.f), wt[jj], acc);
        }
        #pragma unroll
        for (int o=16;o;o>>=1) acc += __shfl_xor_sync(0xffffffffu, acc, o);
        if (lane == 0){
            g_dots[((b*NS+w)<<10) + n] = ATTN_SCALE * (acc + qb2);
            if (writeRel){
                float* rp = relOut + ((((size_t)(b*NS+w)<<10)+n)<<1);
                rp[0]=a; rp[1]=c;
            }
        }
    }
}

// ---------------- softmax over slots (axis=1) ----------------
__global__ void softmax_kernel()
{
    int gi = blockIdx.x*256 + threadIdx.x;  // 0..8191
    int b = gi >> 10, n = gi & 1023;
    float d[NS]; float mx = -1e30f;
    #pragma unroll
    for (int k=0;k<NS;k++){ d[k] = g_dots[((b*NS+k)<<10)+n]; mx = fmaxf(mx, d[k]); }
    float s = 0.f;
    #pragma unroll
    for (int k=0;k<NS;k++){ d[k] = expf(d[k]-mx); s += d[k]; }
    float inv = 1.f/s;
    #pragma unroll
    for (int k=0;k<NS;k++) g_attn0[((b*NS+k)<<10)+n] = d[k]*inv;
}

// ---------------- per-slot reductions: pos_n, scl_n, attn denom ----------------
__global__ void reduce_kernel()
{
    __shared__ float red[8];
    int s = blockIdx.x, t = threadIdx.x;
    float S0=0,Sx=0,Sy=0,Sxx=0,Syy=0;
    for (int n=t; n<NPIX; n+=256){
        float a0 = g_attn0[(s<<10)+n];
        float gx = -1.f + (float)(n>>5)*GSTEP;
        float gy = -1.f + (float)(n&31)*GSTEP;
        S0+=a0; Sx+=a0*gx; Sy+=a0*gy; Sxx+=a0*gx*gx; Syy+=a0*gy*gy;
    }
    S0 = blockSum256(S0, red); Sx = blockSum256(Sx, red); Sy = blockSum256(Sy, red);
    Sxx = blockSum256(Sxx, red); Syy = blockSum256(Syy, red);
    if (t == 0){
        float px = Sx, py = Sy;
        float G2 = g_cov[9];
        float vx = Sxx - 2.f*px*Sx + px*px*S0 + EPSA*(G2 + 1024.f*px*px);
        float vy = Syy - 2.f*py*Sy + py*py*S0 + EPSA*(G2 + 1024.f*py*py);
        float sx = fminf(fmaxf(sqrtf(fmaxf(vx,0.f)), 1e-3f), 2.f);
        float sy = fminf(fmaxf(sqrtf(fmaxf(vy,0.f)), 1e-3f), 2.f);
        g_Cond[s*260+256]=px; g_Cond[s*260+257]=py;
        g_Cond[s*260+258]=sx; g_Cond[s*260+259]=sy;
        g_red[s*4] = 1.f/(S0 + 1024.f*EPSA);
    }
}

// ---------------- accumulate s = sum_n attn * relu(preact_V) ----------------
__global__ __launch_bounds__(256) void vacc_kernel()
{
    __shared__ float sa[NPIX], sc2[NPIX], sis[NPIX], sw[NPIX];
    int s = blockIdx.x, b = s >> 3, t = threadIdx.x;
    float px = g_slot[s*520+513], py = g_slot[s*520+514];
    float i5x= g_slot[s*520+515], i5y= g_slot[s*520+516];
    float invden = g_red[s*4];
    float V00=g_cov[3], V11=g_cov[4], C01_2=2.f*g_cov[6];
    for (int n=t; n<NPIX; n+=256){
        float gx = -1.f + (float)(n>>5)*GSTEP;
        float gy = -1.f + (float)(n&31)*GSTEP;
        float a = (gx-px)*i5x, c = (gy-py)*i5y;
        const float4 st = *(const float4*)(g_statsV + ((b<<10)+n)*4);
        float var = st.x + a*st.y + c*st.z + a*a*V00 + c*c*V11 + a*c*C01_2;
        sis[n] = rsqrtf(var + LNEPS);
        sa[n]=a; sc2[n]=c;
        sw[n] = (g_attn0[(s<<10)+n] + EPSA) * invden;
    }
    __syncthreads();
    int j = t, j2 = t + 256;
    float u0a=g_U0[j], u1a=g_U1[j], ca=g_C[j];
    float u0b=g_U0[j2],u1b=g_U1[j2],cb=g_C[j2];
    float acc=0.f, acc2=0.f;
    for (int n=0; n<NPIX; n++){
        const float* pv = g_Pv + (((size_t)(b<<10)+n)<<9);
        float aa=sa[n], cc=sc2[n], is=sis[n], wn=sw[n];
        float p1 = fmaf(is, pv[j]  + aa*u0a + cc*u1a, ca);
        float p2 = fmaf(is, pv[j2] + aa*u0b + cc*u1b, cb);
        acc  = fmaf(fmaxf(p1,0.f), wn, acc);
        acc2 = fmaf(fmaxf(p2,0.f), wn, acc2);
    }
    g_s[(s<<9)+j] = acc; g_s[(s<<9)+j2] = acc2;
}

// ---------------- upd = s@W2 + b2 ; GRU update of slots ----------------
__global__ void upd_kernel(const float* __restrict__ W2, const float* __restrict__ b2,
                           const float* __restrict__ Wih, const float* __restrict__ Whh,
                           const float* __restrict__ bih, const float* __restrict__ bhh)
{
    __shared__ float ss[H], su[D], so[D];
    int s = blockIdx.x, t = threadIdx.x;
    ss[t] = g_s[(s<<9)+t]; ss[t+256] = g_s[(s<<9)+t+256];
    so[t] = g_Cond[s*260 + t];
    __syncthreads();
    float u = b2[t];
    for (int j=0;j<H;j++) u = fmaf(ss[j], W2[j*D + t], u);
    su[t] = u;
    __syncthreads();
    float gx[3], gh[3];
    #pragma unroll
    for (int p=0;p<3;p++){
        int i = p*256 + t;
        float ax = bih[i], ah = bhh[i];
        const float* wi = Wih + i*D;
        const float* wh = Whh + i*D;
        for (int d=0; d<D; d++){ ax = fmaf(wi[d], su[d], ax); ah = fmaf(wh[d], so[d], ah); }
        gx[p]=ax; gh[p]=ah;
    }
    float r = 1.f/(1.f + expf(-(gx[0]+gh[0])));
    float z = 1.f/(1.f + expf(-(gx[1]+gh[1])));
    float nn = tanhf(gx[2] + r*gh[2]);
    g_Cond[s*260 + t] = (1.f - z)*nn + z*so[t];
}

// ---------------- final output assembly ----------------
__global__ void out_copy(float* __restrict__ out)
{
    int i = blockIdx.x*256 + threadIdx.x; // 0..82175
    out[i] = (i < 16640) ? g_Cond[i] : g_attn0[i - 16640];
}

// ---------------- launch ----------------
extern "C" void kernel_launch(void* const* d_in, const int* in_sizes, int n_in,
                              void* d_out, int out_size)
{
    const float* inputs = (const float*)d_in[0];
    const float* cond   = (const float*)d_in[1];
    const float* ni_g   = (const float*)d_in[2];
    const float* ni_b   = (const float*)d_in[3];
    const float* ns_g   = (const float*)d_in[4];
    const float* ns_b   = (const float*)d_in[5];
    const float* wq     = (const float*)d_in[6];
    const float* wk     = (const float*)d_in[7];
    const float* wv     = (const float*)d_in[8];
    const float* gp_w   = (const float*)d_in[9];
    const float* gp_b   = (const float*)d_in[10];
    const float* ge_ln_g= (const float*)d_in[11];
    const float* ge_ln_b= (const float*)d_in[12];
    const float* ge_w1  = (const float*)d_in[13];
    const float* ge_b1  = (const float*)d_in[14];
    const float* ge_w2  = (const float*)d_in[15];
    const float* ge_b2  = (const float*)d_in[16];
    const float* gru_wih= (const float*)d_in[17];
    const float* gru_whh= (const float*)d_in[18];
    const float* gru_bih= (const float*)d_in[19];
    const float* gru_bhh= (const float*)d_in[20];
    float* out = (float*)d_out;

    const_kernel<<<1, 512>>>(gp_w, gp_b, ge_ln_g, ge_ln_b, ge_w1, ge_b1);
    init_cond<<<65, 256>>>(cond);
    ln_kernel<<<NROWS, 256>>>(inputs, ni_g, ni_b);
    gemm_kernel<<<dim3(4,128), 256>>>(0, wk, nullptr, 256);
    gemm_kernel<<<dim3(4,128), 256>>>(1, wv, nullptr, 256);
    stats_kernel<<<NROWS, 256>>>(gp_w, gp_b);
    gemm_kernel<<<dim3(8,128), 256>>>(2, ge_w1, ge_ln_g, 512);
    gemm_kernel<<<dim3(8,128), 256>>>(3, ge_w1, ge_ln_g, 512);

    float* relOut = out + 16640 + 65536;
    for (int it = 0; it < 4; it++) {
        slot_kernel<<<64, 256>>>(ns_g, ns_b, wq, ge_w2, ge_b2);
        dots_kernel<<<dim3(32,8), 256>>>(it == 3 ? 1 : 0, relOut);
        softmax_kernel<<<32, 256>>>();
        reduce_kernel<<<64, 256>>>();
        if (it < 3) {
            vacc_kernel<<<64, 256>>>();
            upd_kernel<<<64, 256>>>(ge_w2, ge_b2, gru_wih, gru_whh, gru_bih, gru_bhh);
        }
    }
    out_copy<<<321, 256>>>(out);
}

// round 2
// speedup vs baseline: 1.5119x; 1.5119x over previous
#include <cuda_runtime.h>
#include <math.h>

// ---------------- problem constants ----------------
#define NB 8            // batch
#define NPIX 1024       // N pixels
#define NS 8            // slots
#define D 256           // feature dim
#define H 512           // hidden dim of grid_enc
#define NROWS (NB*NPIX) // 8192
#define EPSA 1e-8f
#define LNEPS 1e-5f
#define ATTN_SCALE 0.0625f   // 256^-0.5
#define GSTEP (2.0f/31.0f)

// ---------------- scratch (device globals; no runtime alloc) ----------------
__device__ float g_X [NROWS*D];
__device__ float g_K [NROWS*D];
__device__ float g_V [NROWS*D];
__device__ float g_Pk[NROWS*H];
__device__ float g_Pv[NROWS*H];
__device__ float g_statsK[NROWS*4];
__device__ float g_statsV[NROWS*4];
__device__ float g_meanK[NROWS];
__device__ float g_meanV[NROWS];
__device__ float g_U0[H], g_U1[H], g_Ub[H], g_C[H], g_G1[H];
__device__ float g_cov[16];
__device__ float g_Cond[NB*NS*260];
__device__ float g_slot[NB*NS*520];   // [0..511]=wtil, 512=qb2,513=px,514=py,515=i5x,516=i5y
__device__ float g_attn0[NB*NS*NPIX];
__device__ float g_red[NB*NS*4];      // [0]=inv attn denom
__device__ float g_part[NB*NS*32*8];  // per (slot, chunk) partial sums (5 used)
__device__ float g_spart[NB*NS*8*H];  // per (slot, chunk) partial s vectors

// ---------------- helpers ----------------
__device__ __forceinline__ float blockSum256(float v, float* red) {
    int t = threadIdx.x;
    #pragma unroll
    for (int o = 16; o; o >>= 1) v += __shfl_xor_sync(0xffffffffu, v, o);
    if ((t & 31) == 0) red[t >> 5] = v;
    __syncthreads();
    if (t == 0) {
        float r = 0.f;
        #pragma unroll
        for (int w = 0; w < 8; w++) r += red[w];
        red[0] = r;
    }
    __syncthreads();
    float r = red[0];
    __syncthreads();
    return r;
}

__device__ __forceinline__ float warpSum(float v) {
    #pragma unroll
    for (int o = 16; o; o >>= 1) v += __shfl_xor_sync(0xffffffffu, v, o);
    return v;
}

// ---------------- constants kernel ----------------
__global__ void const_kernel(const float* __restrict__ gp_w, const float* __restrict__ gp_b,
                             const float* __restrict__ lg,   const float* __restrict__ lb,
                             const float* __restrict__ W1,   const float* __restrict__ b1)
{
    __shared__ float sg0[D], sg1[D], sgb[D], slg[D], slb[D];
    __shared__ float sm[4];
    int t = threadIdx.x; // 512 threads
    if (t < D) { sg0[t]=gp_w[t]; sg1[t]=gp_w[D+t]; sgb[t]=gp_b[t]; slg[t]=lg[t]; slb[t]=lb[t]; }
    __syncthreads();
    if (t == 0) {
        float m0=0,m1=0,mb=0;
        for (int d=0; d<D; d++){ m0+=sg0[d]; m1+=sg1[d]; mb+=sgb[d]; }
        m0*= (1.f/D); m1*=(1.f/D); mb*=(1.f/D);
        float V00=0,V11=0,Vbb=0,C01=0,C0b=0,C1b=0;
        for (int d=0; d<D; d++){
            float a=sg0[d]-m0, b_=sg1[d]-m1, c=sgb[d]-mb;
            V00+=a*a; V11+=b_*b_; Vbb+=c*c; C01+=a*b_; C0b+=a*c; C1b+=b_*c;
        }
        g_cov[0]=m0; g_cov[1]=m1; g_cov[2]=mb;
        g_cov[3]=V00/D; g_cov[4]=V11/D; g_cov[5]=Vbb/D;
        g_cov[6]=C01/D; g_cov[7]=C0b/D; g_cov[8]=C1b/D;
        float s2=0;
        for (int i=0;i<32;i++){ float x=-1.f + i*GSTEP; s2+=x*x; }
        g_cov[9]=s2*32.f;  // G2 = sum_n gx^2
        sm[0]=m0; sm[1]=m1; sm[2]=mb;
    }
    __syncthreads();
    float m0=sm[0], m1=sm[1], mb=sm[2];
    float U0=0,U1=0,Ub=0,Cc=0,G1=0;
    for (int d=0; d<D; d++){
        float w = W1[d*H + t];
        float gd = slg[d];
        U0 = fmaf((sg0[d]-m0)*gd, w, U0);
        U1 = fmaf((sg1[d]-m1)*gd, w, U1);
        Ub = fmaf((sgb[d]-mb)*gd, w, Ub);
        Cc = fmaf(slb[d], w, Cc);
        G1 = fmaf(gd, w, G1);
    }
    g_U0[t]=U0; g_U1[t]=U1; g_Ub[t]=Ub; g_C[t]=Cc + b1[t]; g_G1[t]=G1;
}

// ---------------- init conditioning copy ----------------
__global__ void init_cond(const float* __restrict__ cond){
    int i = blockIdx.x*256 + threadIdx.x;
    g_Cond[i] = cond[i];
}

// ---------------- input layernorm ----------------
__global__ void ln_kernel(const float* __restrict__ in, const float* __restrict__ gw,
                          const float* __restrict__ gb)
{
    __shared__ float red[8];
    int r = blockIdx.x, t = threadIdx.x;
    float v = in[r*D + t];
    float m = blockSum256(v, red) * (1.f/D);
    float d = v - m;
    float var = blockSum256(d*d, red) * (1.f/D);
    g_X[r*D + t] = d * rsqrtf(var + LNEPS) * gw[t] + gb[t];
}

// ---------------- tiled fp32 GEMM: 128x64 tile, 8x4 per thread ----------------
// mode 0: g_K = g_X @ B ; mode 1: g_V = g_X @ B
// mode 2: g_Pk = (g_K*diag(scale)) @ B - meanK*G1 + Ub ; mode 3: same for V
__global__ __launch_bounds__(256) void gemm_kernel(int mode, const float* __restrict__ Bm,
                                                   const float* __restrict__ scaleV, int N)
{
    const float* A = (mode<2) ? g_X : (mode==2 ? g_K : g_V);
    float* Cm      = (mode==0) ? g_K : (mode==1) ? g_V : (mode==2) ? g_Pk : g_Pv;
    const float* meanV = (mode==2) ? g_meanK : (mode==3) ? g_meanV : nullptr;

    __shared__ float As[16][128];
    __shared__ float Bs[16][64];
    int bm = blockIdx.y*128, bn = blockIdx.x*64;
    int tid = threadIdx.x;
    int tx = tid & 15, ty = tid >> 4;
    float acc[8][4] = {};

    for (int k0 = 0; k0 < 256; k0 += 16) {
        { // A tile: 128 rows x 16 k, transposed. thread loads 8 elems of one row.
            int rr = tid >> 1, kk0 = (tid & 1) * 8;
            const float* ap = A + (size_t)(bm+rr)*256 + k0 + kk0;
            float4 a0 = *(const float4*)ap;
            float4 a1 = *(const float4*)(ap + 4);
            if (mode >= 2) {
                a0.x*=scaleV[k0+kk0+0]; a0.y*=scaleV[k0+kk0+1];
                a0.z*=scaleV[k0+kk0+2]; a0.w*=scaleV[k0+kk0+3];
                a1.x*=scaleV[k0+kk0+4]; a1.y*=scaleV[k0+kk0+5];
                a1.z*=scaleV[k0+kk0+6]; a1.w*=scaleV[k0+kk0+7];
            }
            As[kk0+0][rr]=a0.x; As[kk0+1][rr]=a0.y; As[kk0+2][rr]=a0.z; As[kk0+3][rr]=a0.w;
            As[kk0+4][rr]=a1.x; As[kk0+5][rr]=a1.y; As[kk0+6][rr]=a1.z; As[kk0+7][rr]=a1.w;
        }
        { // B tile: 16 k x 64 cols
            int kk = tid >> 4, cc = (tid & 15) * 4;
            *(float4*)&Bs[kk][cc] = *(const float4*)(Bm + (size_t)(k0+kk)*N + bn + cc);
        }
        __syncthreads();
        #pragma unroll
        for (int kk = 0; kk < 16; kk++) {
            float ar[8], br[4];
            #pragma unroll
            for (int i=0;i<8;i++) ar[i]=As[kk][ty*8+i];
            #pragma unroll
            for (int j=0;j<4;j++) br[j]=Bs[kk][tx*4+j];
            #pragma unroll
            for (int i=0;i<8;i++)
                #pragma unroll
                for (int j=0;j<4;j++) acc[i][j] = fmaf(ar[i], br[j], acc[i][j]);
        }
        __syncthreads();
    }
    #pragma unroll
    for (int i=0;i<8;i++){
        int r = bm + ty*8 + i;
        float mk = meanV ? meanV[r] : 0.f;
        int c0 = bn + tx*4;
        float4 v4;
        v4.x = acc[i][0]; v4.y = acc[i][1]; v4.z = acc[i][2]; v4.w = acc[i][3];
        if (mode >= 2) {
            v4.x = v4.x - mk*g_G1[c0+0] + g_Ub[c0+0];
            v4.y = v4.y - mk*g_G1[c0+1] + g_Ub[c0+1];
            v4.z = v4.z - mk*g_G1[c0+2] + g_Ub[c0+2];
            v4.w = v4.w - mk*g_G1[c0+3] + g_Ub[c0+3];
        }
        *(float4*)(Cm + (size_t)r*N + c0) = v4;
    }
}

// ---------------- per-row stats for K and V ----------------
__global__ void stats_kernel(const float* __restrict__ gp_w, const float* __restrict__ gp_b)
{
    __shared__ float red[8];
    int r = blockIdx.x, t = threadIdx.x;
    float m0=g_cov[0], m1=g_cov[1], mb=g_cov[2];
    float Vbb=g_cov[5], C0b=g_cov[7], C1b=g_cov[8];
    float g0c = gp_w[t]-m0, g1c = gp_w[D+t]-m1, gbc = gp_b[t]-mb;

    #pragma unroll
    for (int br = 0; br < 2; br++) {
        const float* src = br ? g_V : g_K;
        float kv = src[r*D + t];
        float mk = blockSum256(kv, red) * (1.f/D);
        float d  = kv - mk;
        float Vkk = blockSum256(d*d,  red) * (1.f/D);
        float Ck0 = blockSum256(d*g0c,red) * (1.f/D);
        float Ck1 = blockSum256(d*g1c,red) * (1.f/D);
        float Ckb = blockSum256(d*gbc,red) * (1.f/D);
        if (t == 0) {
            float* st = br ? (g_statsV + r*4) : (g_statsK + r*4);
            st[0] = Vkk + Vbb + 2.f*Ckb;
            st[1] = 2.f*(Ck0 + C0b);
            st[2] = 2.f*(Ck1 + C1b);
            st[3] = 0.f;
            if (br) g_meanV[r]=mk; else g_meanK[r]=mk;
        }
        __syncthreads();
    }
}

// ---------------- per-slot: q, wtil = W2@q, qb2, pos/scl ----------------
__global__ void slot_kernel(const float* __restrict__ ns_g, const float* __restrict__ ns_b,
                            const float* __restrict__ wq,   const float* __restrict__ W2,
                            const float* __restrict__ b2)
{
    __shared__ float red[8];
    __shared__ float sh[D], sq[D];
    int s = blockIdx.x, t = threadIdx.x, w = t >> 5, lane = t & 31;
    float sv = g_Cond[s*260 + t];
    float m  = blockSum256(sv, red) * (1.f/D);
    float d0 = sv - m;
    float var = blockSum256(d0*d0, red) * (1.f/D);
    sh[t] = d0 * rsqrtf(var + LNEPS) * ns_g[t] + ns_b[t];
    __syncthreads();
    float q = 0.f;
    #pragma unroll 4
    for (int d=0; d<D; d++) q = fmaf(sh[d], wq[d*D + t], q);
    sq[t] = q;
    __syncthreads();
    float qb2 = blockSum256(q * b2[t], red);
    // wtil = W2 @ q : warp-per-row (coalesced)
    for (int j = w; j < H; j += 8) {
        const float* w2r = W2 + j*D;
        float acc = 0.f;
        #pragma unroll
        for (int dd=0; dd<8; dd++) acc = fmaf(w2r[dd*32+lane], sq[dd*32+lane], acc);
        acc = warpSum(acc);
        if (lane == 0) g_slot[s*520 + j] = acc;
    }
    if (t == 0) {
        float px = fminf(fmaxf(g_Cond[s*260+256], -1.f), 1.f);
        float py = fminf(fmaxf(g_Cond[s*260+257], -1.f), 1.f);
        float sx = fminf(fmaxf(g_Cond[s*260+258], 1e-3f), 2.f);
        float sy = fminf(fmaxf(g_Cond[s*260+259], 1e-3f), 2.f);
        float* o = g_slot + s*520 + 512;
        o[0]=qb2; o[1]=px; o[2]=py; o[3]=1.f/(5.f*sx); o[4]=1.f/(5.f*sy);
    }
}

// ---------------- fused: dots + softmax + attn0 + pos/scl partials ----------------
__global__ __launch_bounds__(256) void iter1_kernel(int writeRel, float* __restrict__ relOut)
{
    int b = blockIdx.y, chunk = blockIdx.x;
    int t = threadIdx.x, w = t >> 5, lane = t & 31;
    __shared__ float sC[H];
    __shared__ float sscal[NS][5];
    __shared__ float sdots[NS][32];

    float u0[16], u1[16], wt[16];
    const float* wts = g_slot + (b*NS + w)*520;
    #pragma unroll
    for (int jj=0; jj<16; jj++){
        int j = (jj<<5) | lane;
        u0[jj]=g_U0[j]; u1[jj]=g_U1[j]; wt[jj]=wts[j];
    }
    for (int i=t; i<H; i+=256) sC[i]=g_C[i];
    if (t < 40) sscal[t/5][t%5] = g_slot[(b*NS + t/5)*520 + 512 + (t%5)];
    __syncthreads();

    float qb2=sscal[w][0], px=sscal[w][1], py=sscal[w][2], i5x=sscal[w][3], i5y=sscal[w][4];
    float V00=g_cov[3], V11=g_cov[4], C01_2=2.f*g_cov[6];
    int n0 = chunk*32;

    for (int pp=0; pp<32; pp++){
        int n = n0 + pp;
        float gx = -1.f + (float)(n>>5)*GSTEP;
        float gy = -1.f + (float)(n&31)*GSTEP;
        float a = (gx-px)*i5x, c = (gy-py)*i5y;
        const float4 st = *(const float4*)(g_statsK + ((b<<10)+n)*4);
        float var = st.x + a*st.y + c*st.z + a*a*V00 + c*c*V11 + a*c*C01_2;
        float isig = rsqrtf(var + LNEPS);
        const float* pk = g_Pk + (((size_t)(b<<10)+n)<<9);
        float ac0=0.f, ac1=0.f, ac2=0.f, ac3=0.f;
        #pragma unroll
        for (int jj=0; jj<16; jj+=4){
            int j0 = (jj<<5) | lane;
            float p0 = fmaf(isig, __ldg(pk+j0)     + a*u0[jj]   + c*u1[jj],   sC[j0]);
            float p1 = fmaf(isig, __ldg(pk+j0+32)  + a*u0[jj+1] + c*u1[jj+1], sC[j0+32]);
            float p2 = fmaf(isig, __ldg(pk+j0+64)  + a*u0[jj+2] + c*u1[jj+2], sC[j0+64]);
            float p3 = fmaf(isig, __ldg(pk+j0+96)  + a*u0[jj+3] + c*u1[jj+3], sC[j0+96]);
            ac0 = fmaf(fmaxf(p0,0.f), wt[jj],   ac0);
            ac1 = fmaf(fmaxf(p1,0.f), wt[jj+1], ac1);
            ac2 = fmaf(fmaxf(p2,0.f), wt[jj+2], ac2);
            ac3 = fmaf(fmaxf(p3,0.f), wt[jj+3], ac3);
        }
        float acc = warpSum((ac0+ac1)+(ac2+ac3));
        if (lane == 0){
            sdots[w][pp] = ATTN_SCALE * (acc + qb2);
            if (writeRel){
                float* rp = relOut + ((((size_t)(b*NS+w)<<10)+n)<<1);
                rp[0]=a; rp[1]=c;
            }
        }
    }
    __syncthreads();

    // softmax over slots: thread (w, lane) handles (slot w, pixel lane)
    int n = n0 + lane;
    float d[NS]; float mx = -1e30f;
    #pragma unroll
    for (int k=0;k<NS;k++){ d[k] = sdots[k][lane]; mx = fmaxf(mx, d[k]); }
    float sum = 0.f;
    #pragma unroll
    for (int k=0;k<NS;k++){ d[k] = expf(d[k]-mx); sum += d[k]; }
    float a0 = d[w] / sum;
    g_attn0[((b*NS+w)<<10) + n] = a0;

    // per-slot partial reductions over this chunk's 32 pixels
    float gx = -1.f + (float)(n>>5)*GSTEP;
    float gy = -1.f + (float)(n&31)*GSTEP;
    float S0 = warpSum(a0);
    float Sx = warpSum(a0*gx);
    float Sy = warpSum(a0*gy);
    float Sxx = warpSum(a0*gx*gx);
    float Syy = warpSum(a0*gy*gy);
    if (lane == 0){
        float* pp = g_part + ((size_t)((b*NS+w)*32 + chunk))*8;
        pp[0]=S0; pp[1]=Sx; pp[2]=Sy; pp[3]=Sxx; pp[4]=Syy;
    }
}

// ---------------- finalize: pos_n, scl_n, attn denom ----------------
__global__ void finz_kernel()
{
    int s = blockIdx.x, lane = threadIdx.x;  // 32 threads = 32 chunks
    const float* pp = g_part + ((size_t)(s*32 + lane))*8;
    float S0=pp[0], Sx=pp[1], Sy=pp[2], Sxx=pp[3], Syy=pp[4];
    S0=warpSum(S0); Sx=warpSum(Sx); Sy=warpSum(Sy); Sxx=warpSum(Sxx); Syy=warpSum(Syy);
    if (lane == 0){
        float px = Sx, py = Sy;
        float G2 = g_cov[9];
        float vx = Sxx - 2.f*px*Sx + px*px*S0 + EPSA*(G2 + 1024.f*px*px);
        float vy = Syy - 2.f*py*Sy + py*py*S0 + EPSA*(G2 + 1024.f*py*py);
        float sx = fminf(fmaxf(sqrtf(fmaxf(vx,0.f)), 1e-3f), 2.f);
        float sy = fminf(fmaxf(sqrtf(fmaxf(vy,0.f)), 1e-3f), 2.f);
        g_Cond[s*260+256]=px; g_Cond[s*260+257]=py;
        g_Cond[s*260+258]=sx; g_Cond[s*260+259]=sy;
        g_red[s*4] = 1.f/(S0 + 1024.f*EPSA);
    }
}

// ---------------- partial accumulate s = sum_n attn * relu(preact_V) ----------------
__global__ __launch_bounds__(512) void vacc_kernel()
{
    int s = blockIdx.y;        // 0..63
    int chunk = blockIdx.x;    // 0..7 (128 pixels each)
    int b = s >> 3;
    int t = threadIdx.x;       // j = 0..511
    __shared__ float sa[128], sc2[128], sis[128], sw[128];

    if (t < 128){
        int n = chunk*128 + t;
        float px = g_slot[s*520+513], py = g_slot[s*520+514];
        float i5x= g_slot[s*520+515], i5y= g_slot[s*520+516];
        float gx = -1.f + (float)(n>>5)*GSTEP;
        float gy = -1.f + (float)(n&31)*GSTEP;
        float a = (gx-px)*i5x, c = (gy-py)*i5y;
        const float4 st = *(const float4*)(g_statsV + ((b<<10)+n)*4);
        float V00=g_cov[3], V11=g_cov[4], C01_2=2.f*g_cov[6];
        float var = st.x + a*st.y + c*st.z + a*a*V00 + c*c*V11 + a*c*C01_2;
        sis[t] = rsqrtf(var + LNEPS);
        sa[t] = a; sc2[t] = c;
        sw[t] = (g_attn0[(s<<10)+n] + EPSA) * g_red[s*4];
    }
    __syncthreads();

    float u0 = g_U0[t], u1 = g_U1[t], C = g_C[t];
    const float* pvb = g_Pv + ((((size_t)(b<<10)) + (size_t)chunk*128) << 9) + t;
    float acc = 0.f;
    #pragma unroll 8
    for (int p=0; p<128; p++){
        float pv = pvb[(size_t)p << 9];
        float pre = fmaf(sis[p], pv + sa[p]*u0 + sc2[p]*u1, C);
        acc = fmaf(fmaxf(pre, 0.f), sw[p], acc);
    }
    g_spart[((size_t)(s*8 + chunk))*H + t] = acc;
}

// ---------------- upd = s@W2 + b2 ; GRU update of slots ----------------
__global__ __launch_bounds__(256) void upd_kernel(const float* __restrict__ W2, const float* __restrict__ b2,
                           const float* __restrict__ Wih, const float* __restrict__ Whh,
                           const float* __restrict__ bih, const float* __restrict__ bhh)
{
    __shared__ float ss[H], su[D], so[D], sgx[3*D], sgh[3*D];
    int s = blockIdx.x, t = threadIdx.x, w = t >> 5, lane = t & 31;

    // reduce vacc partials
    float r0 = 0.f, r1 = 0.f;
    #pragma unroll
    for (int c=0; c<8; c++){
        const float* sp = g_spart + ((size_t)(s*8 + c))*H;
        r0 += sp[t]; r1 += sp[t+256];
    }
    ss[t] = r0; ss[t+256] = r1;
    so[t] = g_Cond[s*260 + t];
    __syncthreads();

    // u = ss @ W2 + b2 (coalesced across t)
    float u = b2[t];
    #pragma unroll 4
    for (int j=0; j<H; j++) u = fmaf(ss[j], W2[j*D + t], u);
    su[t] = u;
    __syncthreads();

    // GRU matvecs: warp-per-row (coalesced)
    for (int i = w; i < 3*D; i += 8){
        const float* wi = Wih + i*D;
        const float* wh = Whh + i*D;
        float ax = 0.f, ah = 0.f;
        #pragma unroll
        for (int dd=0; dd<8; dd++){
            int dx = dd*32 + lane;
            ax = fmaf(wi[dx], su[dx], ax);
            ah = fmaf(wh[dx], so[dx], ah);
        }
        ax = warpSum(ax); ah = warpSum(ah);
        if (lane == 0){ sgx[i] = ax + bih[i]; sgh[i] = ah + bhh[i]; }
    }
    __syncthreads();

    float r = 1.f/(1.f + expf(-(sgx[t]       + sgh[t])));
    float z = 1.f/(1.f + expf(-(sgx[256+t]   + sgh[256+t])));
    float nn = tanhf(sgx[512+t] + r*sgh[512+t]);
    g_Cond[s*260 + t] = (1.f - z)*nn + z*so[t];
}

// ---------------- final output assembly ----------------
__global__ void out_copy(float* __restrict__ out)
{
    int i = blockIdx.x*256 + threadIdx.x; // 0..82175
    out[i] = (i < 16640) ? g_Cond[i] : g_attn0[i - 16640];
}

// ---------------- launch ----------------
extern "C" void kernel_launch(void* const* d_in, const int* in_sizes, int n_in,
                              void* d_out, int out_size)
{
    const float* inputs = (const float*)d_in[0];
    const float* cond   = (const float*)d_in[1];
    const float* ni_g   = (const float*)d_in[2];
    const float* ni_b   = (const float*)d_in[3];
    const float* ns_g   = (const float*)d_in[4];
    const float* ns_b   = (const float*)d_in[5];
    const float* wq     = (const float*)d_in[6];
    const float* wk     = (const float*)d_in[7];
    const float* wv     = (const float*)d_in[8];
    const float* gp_w   = (const float*)d_in[9];
    const float* gp_b   = (const float*)d_in[10];
    const float* ge_ln_g= (const float*)d_in[11];
    const float* ge_ln_b= (const float*)d_in[12];
    const float* ge_w1  = (const float*)d_in[13];
    const float* ge_b1  = (const float*)d_in[14];
    const float* ge_w2  = (const float*)d_in[15];
    const float* ge_b2  = (const float*)d_in[16];
    const float* gru_wih= (const float*)d_in[17];
    const float* gru_whh= (const float*)d_in[18];
    const float* gru_bih= (const float*)d_in[19];
    const float* gru_bhh= (const float*)d_in[20];
    float* out = (float*)d_out;

    const_kernel<<<1, 512>>>(gp_w, gp_b, ge_ln_g, ge_ln_b, ge_w1, ge_b1);
    init_cond<<<65, 256>>>(cond);
    ln_kernel<<<NROWS, 256>>>(inputs, ni_g, ni_b);
    gemm_kernel<<<dim3(4,64), 256>>>(0, wk, nullptr, 256);
    gemm_kernel<<<dim3(4,64), 256>>>(1, wv, nullptr, 256);
    stats_kernel<<<NROWS, 256>>>(gp_w, gp_b);
    gemm_kernel<<<dim3(8,64), 256>>>(2, ge_w1, ge_ln_g, 512);
    gemm_kernel<<<dim3(8,64), 256>>>(3, ge_w1, ge_ln_g, 512);

    float* relOut = out + 16640 + 65536;
    for (int it = 0; it < 4; it++) {
        slot_kernel<<<64, 256>>>(ns_g, ns_b, wq, ge_w2, ge_b2);
        iter1_kernel<<<dim3(32,8), 256>>>(it == 3 ? 1 : 0, relOut);
        finz_kernel<<<64, 32>>>();
        if (it < 3) {
            vacc_kernel<<<dim3(8,64), 512>>>();
            upd_kernel<<<64, 256>>>(ge_w2, ge_b2, gru_wih, gru_whh, gru_bih, gru_bhh);
        }
    }
    out_copy<<<321, 256>>>(out);
}

// round 3
// speedup vs baseline: 2.4066x; 1.5917x over previous
#include <cuda_runtime.h>
#include <math.h>

// ---------------- problem constants ----------------
#define NB 8
#define NPIX 1024
#define NS 8
#define D 256
#define H 512
#define NROWS (NB*NPIX)
#define EPSA 1e-8f
#define LNEPS 1e-5f
#define ATTN_SCALE 0.0625f
#define GSTEP (2.0f/31.0f)

// ---------------- scratch ----------------
__device__ float g_X [NROWS*D];
__device__ float g_K [NROWS*D];
__device__ float g_V [NROWS*D];
__device__ float g_Pk[NROWS*H];
__device__ float g_Pv[NROWS*H];
__device__ float g_statsK[NROWS*4];
__device__ float g_statsV[NROWS*4];
__device__ float g_meanK[NROWS];
__device__ float g_meanV[NROWS];
__device__ float g_U0[H], g_U1[H], g_Ub[H], g_C[H], g_G1[H];
__device__ float g_cov[16];
__device__ float g_Cond[NB*NS*260];
__device__ float g_slot[NB*NS*520];   // [0..511]=wtil, 512=qb2,513=px,514=py,515=i5x,516=i5y
__device__ float g_attn0[NB*NS*NPIX];
__device__ float g_part[NB*NS*32*8];
__device__ float g_spart[NB*NS*8*H];

__device__ __forceinline__ float warpSum(float v) {
    #pragma unroll
    for (int o = 16; o; o >>= 1) v += __shfl_xor_sync(0xffffffffu, v, o);
    return v;
}

// ---------------- pre: constants + cond copy ----------------
__global__ void pre_kernel(const float* __restrict__ gp_w, const float* __restrict__ gp_b,
                           const float* __restrict__ lg,   const float* __restrict__ lb,
                           const float* __restrict__ W1,   const float* __restrict__ b1,
                           const float* __restrict__ cond)
{
    if (blockIdx.x > 0) {
        int i = (blockIdx.x - 1)*512 + threadIdx.x;
        if (i < NB*NS*260) g_Cond[i] = cond[i];
        return;
    }
    __shared__ float sg0[D], sg1[D], sgb[D], slg[D], slb[D];
    __shared__ float sm[4];
    int t = threadIdx.x; // 512
    if (t < D) { sg0[t]=gp_w[t]; sg1[t]=gp_w[D+t]; sgb[t]=gp_b[t]; slg[t]=lg[t]; slb[t]=lb[t]; }
    __syncthreads();
    if (t == 0) {
        float m0=0,m1=0,mb=0;
        for (int d=0; d<D; d++){ m0+=sg0[d]; m1+=sg1[d]; mb+=sgb[d]; }
        m0*=(1.f/D); m1*=(1.f/D); mb*=(1.f/D);
        float V00=0,V11=0,Vbb=0,C01=0,C0b=0,C1b=0;
        for (int d=0; d<D; d++){
            float a=sg0[d]-m0, b_=sg1[d]-m1, c=sgb[d]-mb;
            V00+=a*a; V11+=b_*b_; Vbb+=c*c; C01+=a*b_; C0b+=a*c; C1b+=b_*c;
        }
        g_cov[0]=m0; g_cov[1]=m1; g_cov[2]=mb;
        g_cov[3]=V00/D; g_cov[4]=V11/D; g_cov[5]=Vbb/D;
        g_cov[6]=C01/D; g_cov[7]=C0b/D; g_cov[8]=C1b/D;
        float s2=0;
        for (int i=0;i<32;i++){ float x=-1.f + i*GSTEP; s2+=x*x; }
        g_cov[9]=s2*32.f;
        sm[0]=m0; sm[1]=m1; sm[2]=mb;
    }
    __syncthreads();
    float m0=sm[0], m1=sm[1], mb=sm[2];
    float U0=0,U1=0,Ub=0,Cc=0,G1=0;
    for (int d=0; d<D; d++){
        float w = W1[d*H + t];
        float gd = slg[d];
        U0 = fmaf((sg0[d]-m0)*gd, w, U0);
        U1 = fmaf((sg1[d]-m1)*gd, w, U1);
        Ub = fmaf((sgb[d]-mb)*gd, w, Ub);
        Cc = fmaf(slb[d], w, Cc);
        G1 = fmaf(gd, w, G1);
    }
    g_U0[t]=U0; g_U1[t]=U1; g_Ub[t]=Ub; g_C[t]=Cc + b1[t]; g_G1[t]=G1;
}

// ---------------- layernorm (warp-per-row) ----------------
__global__ __launch_bounds__(512) void ln2(const float* __restrict__ in,
                                           const float* __restrict__ gw, const float* __restrict__ gb)
{
    int r = blockIdx.x*16 + (threadIdx.x>>5);
    int lane = threadIdx.x & 31;
    const float* row = in + (size_t)r*D;
    float v[8]; float s = 0.f;
    #pragma unroll
    for (int k=0;k<8;k++){ v[k]=row[k*32+lane]; s+=v[k]; }
    float m = warpSum(s) * (1.f/D);
    float q = 0.f;
    #pragma unroll
    for (int k=0;k<8;k++){ float d=v[k]-m; q += d*d; }
    float is = rsqrtf(warpSum(q)*(1.f/D) + LNEPS);
    #pragma unroll
    for (int k=0;k<8;k++){
        int d = k*32+lane;
        g_X[(size_t)r*D + d] = (v[k]-m)*is*gw[d] + gb[d];
    }
}

// ---------------- GEMM: 128x128 tile, 8x8 micro, fused pair via z ----------------
// modeBase 0: z0: K = X@B0, z1: V = X@B1     (N=256)
// modeBase 2: z0: Pk = (K*scale)@B0 - meanK*G1 + Ub ; z1: Pv likewise (N=512)
__global__ __launch_bounds__(256,2) void gemm2(int modeBase, const float* __restrict__ B0,
                                               const float* __restrict__ B1,
                                               const float* __restrict__ scaleV, int N)
{
    int z = blockIdx.z;
    const float* A = (modeBase==0) ? g_X : (z==0 ? g_K : g_V);
    const float* Bm = z ? B1 : B0;
    float* Cm = (modeBase==0) ? (z ? g_V : g_K) : (z ? g_Pv : g_Pk);
    const float* meanV = (modeBase==0) ? nullptr : (z ? g_meanV : g_meanK);

    __shared__ float As[16][128];
    __shared__ float Bs[16][128];
    int bm = blockIdx.y*128, bn = blockIdx.x*128;
    int tid = threadIdx.x;
    int tx = tid & 15, ty = tid >> 4;
    int arr = tid >> 1, akk = (tid & 1) * 8;
    int bkk = tid >> 5, bcc = (tid & 31) * 4;
    float acc[8][8] = {};

    for (int k0 = 0; k0 < 256; k0 += 16) {
        const float* ap = A + (size_t)(bm+arr)*256 + k0 + akk;
        float4 a0 = *(const float4*)ap;
        float4 a1 = *(const float4*)(ap + 4);
        if (modeBase) {
            a0.x*=scaleV[k0+akk+0]; a0.y*=scaleV[k0+akk+1];
            a0.z*=scaleV[k0+akk+2]; a0.w*=scaleV[k0+akk+3];
            a1.x*=scaleV[k0+akk+4]; a1.y*=scaleV[k0+akk+5];
            a1.z*=scaleV[k0+akk+6]; a1.w*=scaleV[k0+akk+7];
        }
        float4 b0 = *(const float4*)(Bm + (size_t)(k0+bkk)*N + bn + bcc);
        float4 b1 = *(const float4*)(Bm + (size_t)(k0+bkk+8)*N + bn + bcc);
        __syncthreads();
        As[akk+0][arr]=a0.x; As[akk+1][arr]=a0.y; As[akk+2][arr]=a0.z; As[akk+3][arr]=a0.w;
        As[akk+4][arr]=a1.x; As[akk+5][arr]=a1.y; As[akk+6][arr]=a1.z; As[akk+7][arr]=a1.w;
        *(float4*)&Bs[bkk][bcc]   = b0;
        *(float4*)&Bs[bkk+8][bcc] = b1;
        __syncthreads();
        #pragma unroll
        for (int kk = 0; kk < 16; kk++) {
            float ar[8], br[8];
            *(float4*)ar     = *(const float4*)&As[kk][ty*8];
            *(float4*)(ar+4) = *(const float4*)&As[kk][ty*8+4];
            *(float4*)br     = *(const float4*)&Bs[kk][tx*8];
            *(float4*)(br+4) = *(const float4*)&Bs[kk][tx*8+4];
            #pragma unroll
            for (int i=0;i<8;i++)
                #pragma unroll
                for (int j=0;j<8;j++) acc[i][j] = fmaf(ar[i], br[j], acc[i][j]);
        }
    }
    #pragma unroll
    for (int i=0;i<8;i++){
        int r = bm + ty*8 + i;
        float mk = meanV ? meanV[r] : 0.f;
        int c0 = bn + tx*8;
        float vals[8];
        #pragma unroll
        for (int j=0;j<8;j++){
            float v = acc[i][j];
            if (modeBase) v = v - mk*g_G1[c0+j] + g_Ub[c0+j];
            vals[j] = v;
        }
        *(float4*)(Cm + (size_t)r*N + c0)     = *(float4*)vals;
        *(float4*)(Cm + (size_t)r*N + c0 + 4) = *(float4*)(vals+4);
    }
}

// ---------------- stats (warp-per-row) ----------------
__global__ __launch_bounds__(512) void stats2(const float* __restrict__ gp_w, const float* __restrict__ gp_b)
{
    int r = blockIdx.x*16 + (threadIdx.x>>5);
    int lane = threadIdx.x & 31;
    float m0=g_cov[0], m1=g_cov[1], mb=g_cov[2];
    float Vbb=g_cov[5], C0b=g_cov[7], C1b=g_cov[8];
    float g0[8], g1[8], gbv[8];
    #pragma unroll
    for (int k=0;k<8;k++){
        int d = k*32+lane;
        g0[k]=gp_w[d]-m0; g1[k]=gp_w[D+d]-m1; gbv[k]=gp_b[d]-mb;
    }
    #pragma unroll
    for (int br=0; br<2; br++){
        const float* src = br ? g_V : g_K;
        float sK=0,sK2=0,s0=0,s1=0,sb=0;
        #pragma unroll
        for (int k=0;k<8;k++){
            float x = src[(size_t)r*D + k*32 + lane];
            sK+=x; sK2=fmaf(x,x,sK2); s0=fmaf(x,g0[k],s0); s1=fmaf(x,g1[k],s1); sb=fmaf(x,gbv[k],sb);
        }
        sK=warpSum(sK); sK2=warpSum(sK2); s0=warpSum(s0); s1=warpSum(s1); sb=warpSum(sb);
        if (lane == 0){
            float mk = sK*(1.f/D);
            float Vkk = sK2*(1.f/D) - mk*mk;
            float Ck0 = s0*(1.f/D), Ck1 = s1*(1.f/D), Ckb = sb*(1.f/D);
            float* st = br ? (g_statsV + r*4) : (g_statsK + r*4);
            st[0] = Vkk + Vbb + 2.f*Ckb;
            st[1] = 2.f*(Ck0 + C0b);
            st[2] = 2.f*(Ck1 + C1b);
            st[3] = 0.f;
            if (br) g_meanV[r]=mk; else g_meanK[r]=mk;
        }
    }
}

// ---------------- per-slot q/wtil/scalars (512 threads) ----------------
__device__ __forceinline__ void slot_compute(
    int s, int t, const float* so,
    const float* __restrict__ ns_g, const float* __restrict__ ns_b,
    const float* __restrict__ wq,   const float* __restrict__ W2, const float* __restrict__ b2,
    float* sh, float* sq, float* qpart, float* red)
{
    int w = t >> 5, lane = t & 31;
    float v = (t < 256) ? so[t] : 0.f;
    float ws = warpSum(v);
    if (lane == 0 && t < 256) red[w] = ws;
    __syncthreads();
    float m = 0.f;
    #pragma unroll
    for (int i=0;i<8;i++) m += red[i];
    m *= (1.f/D);
    float d = (t < 256) ? (v - m) : 0.f;
    ws = warpSum(d*d);
    __syncthreads();
    if (lane == 0 && t < 256) red[w] = ws;
    __syncthreads();
    float var = 0.f;
    #pragma unroll
    for (int i=0;i<8;i++) var += red[i];
    var *= (1.f/D);
    if (t < 256) sh[t] = d * rsqrtf(var + LNEPS) * ns_g[t] + ns_b[t];
    __syncthreads();
    // q = sh @ wq, split-K over two halves of threads
    int tt = t & 255, half = t >> 8;
    float q = 0.f;
    #pragma unroll 4
    for (int dd = half*128; dd < half*128 + 128; dd++)
        q = fmaf(sh[dd], wq[dd*D + tt], q);
    qpart[t] = q;
    __syncthreads();
    if (t < 256) sq[t] = qpart[t] + qpart[256 + t];
    __syncthreads();
    // qb2
    float p = (t < 256) ? sq[t]*b2[t] : 0.f;
    ws = warpSum(p);
    __syncthreads();
    if (lane == 0 && t < 256) red[w] = ws;
    __syncthreads();
    // wtil = W2 @ q : warp-per-row
    for (int k = 0; k < 32; k++){
        int j = (k << 4) + w;
        const float* w2r = W2 + j*D;
        float acc = 0.f;
        #pragma unroll
        for (int dd=0; dd<8; dd++) acc = fmaf(w2r[dd*32+lane], sq[dd*32+lane], acc);
        acc = warpSum(acc);
        if (lane == 0) g_slot[s*520 + j] = acc;
    }
    if (t == 0){
        float qb2 = 0.f;
        #pragma unroll
        for (int i=0;i<8;i++) qb2 += red[i];
        float px = fminf(fmaxf(g_Cond[s*260+256], -1.f), 1.f);
        float py = fminf(fmaxf(g_Cond[s*260+257], -1.f), 1.f);
        float sx = fminf(fmaxf(g_Cond[s*260+258], 1e-3f), 2.f);
        float sy = fminf(fmaxf(g_Cond[s*260+259], 1e-3f), 2.f);
        float* o = g_slot + s*520 + 512;
        o[0]=qb2; o[1]=px; o[2]=py; o[3]=1.f/(5.f*sx); o[4]=1.f/(5.f*sy);
    }
}

__global__ __launch_bounds__(512) void slot0(const float* __restrict__ ns_g, const float* __restrict__ ns_b,
                                             const float* __restrict__ wq,   const float* __restrict__ W2,
                                             const float* __restrict__ b2)
{
    __shared__ float so[256], sh[256], sq[256], qpart[512], red[16];
    int s = blockIdx.x, t = threadIdx.x;
    if (t < 256) so[t] = g_Cond[s*260 + t];
    __syncthreads();
    slot_compute(s, t, so, ns_g, ns_b, wq, W2, b2, sh, sq, qpart, red);
}

// ---------------- fused: dots + softmax + attn0 + partials ----------------
__global__ __launch_bounds__(256) void iter1_kernel(int last, float* __restrict__ out)
{
    int b = blockIdx.y, chunk = blockIdx.x;
    int t = threadIdx.x, w = t >> 5, lane = t & 31;
    __shared__ float sC[H];
    __shared__ float sscal[NS][5];
    __shared__ float sdots[NS][32];

    float* attnDst = last ? (out + 16640) : g_attn0;
    float* relOut  = out + 16640 + 65536;

    float u0[16], u1[16], wt[16];
    const float* wts = g_slot + (b*NS + w)*520;
    #pragma unroll
    for (int jj=0; jj<16; jj++){
        int j = (jj<<5) | lane;
        u0[jj]=g_U0[j]; u1[jj]=g_U1[j]; wt[jj]=wts[j];
    }
    for (int i=t; i<H; i+=256) sC[i]=g_C[i];
    if (t < 40) sscal[t/5][t%5] = g_slot[(b*NS + t/5)*520 + 512 + (t%5)];
    __syncthreads();

    float qb2=sscal[w][0], px=sscal[w][1], py=sscal[w][2], i5x=sscal[w][3], i5y=sscal[w][4];
    float V00=g_cov[3], V11=g_cov[4], C01_2=2.f*g_cov[6];
    int n0 = chunk*32;

    for (int pp=0; pp<32; pp++){
        int n = n0 + pp;
        float gx = -1.f + (float)(n>>5)*GSTEP;
        float gy = -1.f + (float)(n&31)*GSTEP;
        float a = (gx-px)*i5x, c = (gy-py)*i5y;
        const float4 st = *(const float4*)(g_statsK + ((b<<10)+n)*4);
        float var = st.x + a*st.y + c*st.z + a*a*V00 + c*c*V11 + a*c*C01_2;
        float isig = rsqrtf(var + LNEPS);
        const float* pk = g_Pk + (((size_t)(b<<10)+n)<<9);
        float ac0=0.f, ac1=0.f, ac2=0.f, ac3=0.f;
        #pragma unroll
        for (int jj=0; jj<16; jj+=4){
            int j0 = (jj<<5) | lane;
            float p0 = fmaf(isig, __ldg(pk+j0)     + a*u0[jj]   + c*u1[jj],   sC[j0]);
            float p1 = fmaf(isig, __ldg(pk+j0+32)  + a*u0[jj+1] + c*u1[jj+1], sC[j0+32]);
            float p2 = fmaf(isig, __ldg(pk+j0+64)  + a*u0[jj+2] + c*u1[jj+2], sC[j0+64]);
            float p3 = fmaf(isig, __ldg(pk+j0+96)  + a*u0[jj+3] + c*u1[jj+3], sC[j0+96]);
            ac0 = fmaf(fmaxf(p0,0.f), wt[jj],   ac0);
            ac1 = fmaf(fmaxf(p1,0.f), wt[jj+1], ac1);
            ac2 = fmaf(fmaxf(p2,0.f), wt[jj+2], ac2);
            ac3 = fmaf(fmaxf(p3,0.f), wt[jj+3], ac3);
        }
        float acc = warpSum((ac0+ac1)+(ac2+ac3));
        if (lane == 0){
            sdots[w][pp] = ATTN_SCALE * (acc + qb2);
            if (last){
                float* rp = relOut + ((((size_t)(b*NS+w)<<10)+n)<<1);
                rp[0]=a; rp[1]=c;
            }
        }
    }
    __syncthreads();

    int n = n0 + lane;
    float d[NS]; float mx = -1e30f;
    #pragma unroll
    for (int k=0;k<NS;k++){ d[k] = sdots[k][lane]; mx = fmaxf(mx, d[k]); }
    float sum = 0.f;
    #pragma unroll
    for (int k=0;k<NS;k++){ d[k] = expf(d[k]-mx); sum += d[k]; }
    float a0 = d[w] / sum;
    attnDst[((b*NS+w)<<10) + n] = a0;

    float gx = -1.f + (float)(n>>5)*GSTEP;
    float gy = -1.f + (float)(n&31)*GSTEP;
    float S0 = warpSum(a0);
    float Sx = warpSum(a0*gx);
    float Sy = warpSum(a0*gy);
    float Sxx = warpSum(a0*gx*gx);
    float Syy = warpSum(a0*gy*gy);
    if (lane == 0){
        float* pp = g_part + ((size_t)((b*NS+w)*32 + chunk))*8;
        pp[0]=S0; pp[1]=Sx; pp[2]=Sy; pp[3]=Sxx; pp[4]=Syy;
    }
}

// ---------------- vacc + inline finalize ----------------
__global__ __launch_bounds__(512) void vaccF_kernel()
{
    int chunk = blockIdx.x;    // 0..7
    int s = blockIdx.y;        // 0..63
    int b = s >> 3;
    int t = threadIdx.x;
    __shared__ float sa[128], sc2[128], sis[128], sw[128], sden[1];

    if (t < 128){
        int n = chunk*128 + t;
        float px = g_slot[s*520+513], py = g_slot[s*520+514];
        float i5x= g_slot[s*520+515], i5y= g_slot[s*520+516];
        float gx = -1.f + (float)(n>>5)*GSTEP;
        float gy = -1.f + (float)(n&31)*GSTEP;
        float a = (gx-px)*i5x, c = (gy-py)*i5y;
        const float4 st = *(const float4*)(g_statsV + ((b<<10)+n)*4);
        float var = st.x + a*st.y + c*st.z + a*a*g_cov[3] + c*c*g_cov[4] + a*c*2.f*g_cov[6];
        sis[t] = rsqrtf(var + LNEPS);
        sa[t] = a; sc2[t] = c;
        sw[t] = g_attn0[(s<<10)+n];
    }
    if (t < 32){
        const float* pp = g_part + ((size_t)(s*32 + t))*8;
        float S0 = warpSum(pp[0]);
        float Sx = warpSum(pp[1]);
        float Sy = warpSum(pp[2]);
        float Sxx = warpSum(pp[3]);
        float Syy = warpSum(pp[4]);
        if (t == 0){
            sden[0] = 1.f/(S0 + 1024.f*EPSA);
            if (chunk == 0){
                float px = Sx, py = Sy, G2 = g_cov[9];
                float vx = Sxx - 2.f*px*Sx + px*px*S0 + EPSA*(G2 + 1024.f*px*px);
                float vy = Syy - 2.f*py*Sy + py*py*S0 + EPSA*(G2 + 1024.f*py*py);
                float sx = fminf(fmaxf(sqrtf(fmaxf(vx,0.f)), 1e-3f), 2.f);
                float sy = fminf(fmaxf(sqrtf(fmaxf(vy,0.f)), 1e-3f), 2.f);
                g_Cond[s*260+256]=px; g_Cond[s*260+257]=py;
                g_Cond[s*260+258]=sx; g_Cond[s*260+259]=sy;
            }
        }
    }
    __syncthreads();
    if (t < 128) sw[t] = (sw[t] + EPSA) * sden[0];
    __syncthreads();

    float u0 = g_U0[t], u1 = g_U1[t], C = g_C[t];
    const float* pvb = g_Pv + ((((size_t)(b<<10)) + (size_t)chunk*128) << 9) + t;
    float acc = 0.f;
    #pragma unroll 8
    for (int p=0; p<128; p++){
        float pv = pvb[(size_t)p << 9];
        float pre = fmaf(sis[p], pv + sa[p]*u0 + sc2[p]*u1, C);
        acc = fmaf(fmaxf(pre, 0.f), sw[p], acc);
    }
    g_spart[((size_t)(s*8 + chunk))*H + t] = acc;
}

// ---------------- GRU update + slot prep for next iter ----------------
__global__ __launch_bounds__(512) void updslot_kernel(
    const float* __restrict__ W2,  const float* __restrict__ b2,
    const float* __restrict__ Wih, const float* __restrict__ Whh,
    const float* __restrict__ bih, const float* __restrict__ bhh,
    const float* __restrict__ ns_g, const float* __restrict__ ns_b,
    const float* __restrict__ wq)
{
    __shared__ float ss[H], so[256], su[256], qpart[512], sgx[768], sgh[768], sh[256], sq[256], red[16];
    int s = blockIdx.x, t = threadIdx.x, w = t >> 5, lane = t & 31;

    float r0 = 0.f;
    #pragma unroll
    for (int c=0; c<8; c++) r0 += g_spart[((size_t)(s*8 + c))*H + t];
    ss[t] = r0;
    if (t < 256) so[t] = g_Cond[s*260 + t];
    __syncthreads();

    // u = ss @ W2 + b2 (split over two half-thread groups)
    int tt = t & 255, half = t >> 8;
    float u = 0.f;
    #pragma unroll 4
    for (int j = half*256; j < half*256 + 256; j++)
        u = fmaf(ss[j], W2[j*D + tt], u);
    qpart[t] = u;
    __syncthreads();
    if (t < 256) su[t] = qpart[t] + qpart[256+t] + b2[t];
    __syncthreads();

    // GRU matvecs: warp-per-row
    for (int k = 0; k < 48; k++){
        int i = (k << 4) + w;
        const float* wi = Wih + i*D;
        const float* wh = Whh + i*D;
        float ax = 0.f, ah = 0.f;
        #pragma unroll
        for (int dd=0; dd<8; dd++){
            int dx = dd*32 + lane;
            ax = fmaf(wi[dx], su[dx], ax);
            ah = fmaf(wh[dx], so[dx], ah);
        }
        ax = warpSum(ax); ah = warpSum(ah);
        if (lane == 0){ sgx[i] = ax + bih[i]; sgh[i] = ah + bhh[i]; }
    }
    __syncthreads();

    if (t < 256){
        float r = 1.f/(1.f + expf(-(sgx[t]     + sgh[t])));
        float z = 1.f/(1.f + expf(-(sgx[256+t] + sgh[256+t])));
        float nn = tanhf(sgx[512+t] + r*sgh[512+t]);
        float nv = (1.f - z)*nn + z*so[t];
        g_Cond[s*260 + t] = nv;
        so[t] = nv;
    }
    __syncthreads();

    slot_compute(s, t, so, ns_g, ns_b, wq, W2, b2, sh, sq, qpart, red);
}

// ---------------- final: pos/scl + write conditioning to out ----------------
__global__ void finz3_kernel(float* __restrict__ out)
{
    __shared__ float sres[4];
    int s = blockIdx.x, t = threadIdx.x;
    if (t < 32){
        const float* pp = g_part + ((size_t)(s*32 + t))*8;
        float S0 = warpSum(pp[0]);
        float Sx = warpSum(pp[1]);
        float Sy = warpSum(pp[2]);
        float Sxx = warpSum(pp[3]);
        float Syy = warpSum(pp[4]);
        if (t == 0){
            float px = Sx, py = Sy, G2 = g_cov[9];
            float vx = Sxx - 2.f*px*Sx + px*px*S0 + EPSA*(G2 + 1024.f*px*px);
            float vy = Syy - 2.f*py*Sy + py*py*S0 + EPSA*(G2 + 1024.f*py*py);
            float sx = fminf(fmaxf(sqrtf(fmaxf(vx,0.f)), 1e-3f), 2.f);
            float sy = fminf(fmaxf(sqrtf(fmaxf(vy,0.f)), 1e-3f), 2.f);
            sres[0]=px; sres[1]=py; sres[2]=sx; sres[3]=sy;
        }
    }
    __syncthreads();
    for (int i = t; i < 260; i += 256)
        out[s*260 + i] = (i < 256) ? g_Cond[s*260 + i] : sres[i - 256];
}

// ---------------- launch ----------------
extern "C" void kernel_launch(void* const* d_in, const int* in_sizes, int n_in,
                              void* d_out, int out_size)
{
    const float* inputs = (const float*)d_in[0];
    const float* cond   = (const float*)d_in[1];
    const float* ni_g   = (const float*)d_in[2];
    const float* ni_b   = (const float*)d_in[3];
    const float* ns_g   = (const float*)d_in[4];
    const float* ns_b   = (const float*)d_in[5];
    const float* wq     = (const float*)d_in[6];
    const float* wk     = (const float*)d_in[7];
    const float* wv     = (const float*)d_in[8];
    const float* gp_w   = (const float*)d_in[9];
    const float* gp_b   = (const float*)d_in[10];
    const float* ge_ln_g= (const float*)d_in[11];
    const float* ge_ln_b= (const float*)d_in[12];
    const float* ge_w1  = (const float*)d_in[13];
    const float* ge_b1  = (const float*)d_in[14];
    const float* ge_w2  = (const float*)d_in[15];
    const float* ge_b2  = (const float*)d_in[16];
    const float* gru_wih= (const float*)d_in[17];
    const float* gru_whh= (const float*)d_in[18];
    const float* gru_bih= (const float*)d_in[19];
    const float* gru_bhh= (const float*)d_in[20];
    float* out = (float*)d_out;

    pre_kernel<<<34, 512>>>(gp_w, gp_b, ge_ln_g, ge_ln_b, ge_w1, ge_b1, cond);
    ln2<<<512, 512>>>(inputs, ni_g, ni_b);
    gemm2<<<dim3(2,64,2), 256>>>(0, wk, wv, nullptr, 256);
    stats2<<<512, 512>>>(gp_w, gp_b);
    gemm2<<<dim3(4,64,2), 256>>>(2, ge_w1, ge_w1, ge_ln_g, 512);
    slot0<<<64, 512>>>(ns_g, ns_b, wq, ge_w2, ge_b2);

    for (int it = 0; it < 3; it++) {
        iter1_kernel<<<dim3(32,8), 256>>>(0, out);
        vaccF_kernel<<<dim3(8,64), 512>>>();
        updslot_kernel<<<64, 512>>>(ge_w2, ge_b2, gru_wih, gru_whh, gru_bih, gru_bhh,
                                    ns_g, ns_b, wq);
    }
    iter1_kernel<<<dim3(32,8), 256>>>(1, out);
    finz3_kernel<<<64, 256>>>(out);
}

// round 4
// speedup vs baseline: 2.7086x; 1.1255x over previous
#include <cuda_runtime.h>
#include <math.h>

// ---------------- problem constants ----------------
#define NB 8
#define NPIX 1024
#define NS 8
#define D 256
#define H 512
#define NROWS (NB*NPIX)
#define EPSA 1e-8f
#define LNEPS 1e-5f
#define ATTN_SCALE 0.0625f
#define GSTEP (2.0f/31.0f)

// ---------------- scratch ----------------
__device__ __align__(16) float g_K [NROWS*D];
__device__ __align__(16) float g_V [NROWS*D];
__device__ __align__(16) float g_Pk[NROWS*H];
__device__ __align__(16) float g_Pv[NROWS*H];
__device__ __align__(16) float g_statsK[NROWS*4];
__device__ __align__(16) float g_statsV[NROWS*4];
__device__ float g_meanK[NROWS];
__device__ float g_meanV[NROWS];
__device__ float g_lnM[NROWS];
__device__ float g_lnIS[NROWS];
__device__ __align__(16) float g_U0[H];
__device__ __align__(16) float g_U1[H];
__device__ __align__(16) float g_Ub[H];
__device__ __align__(16) float g_C[H];
__device__ __align__(16) float g_G1[H];
__device__ float g_cov[16];
__device__ float g_Cond[NB*NS*260];
__device__ __align__(16) float g_slot[NB*NS*520]; // [0..511]=wtil, 512=qb2,513=px,514=py,515=i5x,516=i5y
__device__ float g_attn0[NB*NS*NPIX];
__device__ float g_part[NB*NS*64*8];   // per (slot, 16px-chunk) partials (5 used)
__device__ float g_spart[NB*NS*16*H];  // per (slot, 64px-chunk) partial s vectors

__device__ __forceinline__ float warpSum(float v) {
    #pragma unroll
    for (int o = 16; o; o >>= 1) v += __shfl_xor_sync(0xffffffffu, v, o);
    return v;
}

// ---------------- pre: constants + cond copy + LN row stats ----------------
__global__ __launch_bounds__(512) void pre_kernel(
    const float* __restrict__ gp_w, const float* __restrict__ gp_b,
    const float* __restrict__ lg,   const float* __restrict__ lb,
    const float* __restrict__ W1,   const float* __restrict__ b1,
    const float* __restrict__ cond, const float* __restrict__ inputs)
{
    int bid = blockIdx.x;
    if (bid >= 34) {
        // LN row stats: 16 rows per block, warp-per-row
        int r = (bid - 34)*16 + (threadIdx.x>>5);
        int lane = threadIdx.x & 31;
        const float* row = inputs + (size_t)r*D;
        float v[8]; float s = 0.f;
        #pragma unroll
        for (int k=0;k<8;k++){ v[k]=row[k*32+lane]; s+=v[k]; }
        float m = warpSum(s) * (1.f/D);
        float q = 0.f;
        #pragma unroll
        for (int k=0;k<8;k++){ float d=v[k]-m; q += d*d; }
        float is = rsqrtf(warpSum(q)*(1.f/D) + LNEPS);
        if (lane == 0){ g_lnM[r]=m; g_lnIS[r]=is; }
        return;
    }
    if (bid > 0) {
        int i = (bid - 1)*512 + threadIdx.x;
        if (i < NB*NS*260) g_Cond[i] = cond[i];
        return;
    }
    __shared__ float sg0[D], sg1[D], sgb[D], slg[D], slb[D];
    __shared__ float sm[4];
    int t = threadIdx.x; // 512
    if (t < D) { sg0[t]=gp_w[t]; sg1[t]=gp_w[D+t]; sgb[t]=gp_b[t]; slg[t]=lg[t]; slb[t]=lb[t]; }
    __syncthreads();
    if (t == 0) {
        float m0=0,m1=0,mb=0;
        for (int d=0; d<D; d++){ m0+=sg0[d]; m1+=sg1[d]; mb+=sgb[d]; }
        m0*=(1.f/D); m1*=(1.f/D); mb*=(1.f/D);
        float V00=0,V11=0,Vbb=0,C01=0,C0b=0,C1b=0;
        for (int d=0; d<D; d++){
            float a=sg0[d]-m0, b_=sg1[d]-m1, c=sgb[d]-mb;
            V00+=a*a; V11+=b_*b_; Vbb+=c*c; C01+=a*b_; C0b+=a*c; C1b+=b_*c;
        }
        g_cov[0]=m0; g_cov[1]=m1; g_cov[2]=mb;
        g_cov[3]=V00/D; g_cov[4]=V11/D; g_cov[5]=Vbb/D;
        g_cov[6]=C01/D; g_cov[7]=C0b/D; g_cov[8]=C1b/D;
        float s2=0;
        for (int i=0;i<32;i++){ float x=-1.f + i*GSTEP; s2+=x*x; }
        g_cov[9]=s2*32.f;
        sm[0]=m0; sm[1]=m1; sm[2]=mb;
    }
    __syncthreads();
    float m0=sm[0], m1=sm[1], mb=sm[2];
    float U0=0,U1=0,Ub=0,Cc=0,G1=0;
    for (int d=0; d<D; d++){
        float w = W1[d*H + t];
        float gd = slg[d];
        U0 = fmaf((sg0[d]-m0)*gd, w, U0);
        U1 = fmaf((sg1[d]-m1)*gd, w, U1);
        Ub = fmaf((sgb[d]-mb)*gd, w, Ub);
        Cc = fmaf(slb[d], w, Cc);
        G1 = fmaf(gd, w, G1);
    }
    g_U0[t]=U0; g_U1[t]=U1; g_Ub[t]=Ub; g_C[t]=Cc + b1[t]; g_G1[t]=G1;
}

// ---------------- GEMM: 128x128 tile, 8x8 micro, fused pair via z ----------------
// modeBase 0: A = LN(inputs) applied on the fly; z0: K = A@B0, z1: V = A@B1  (N=256)
// modeBase 2: z0: Pk = (K*diag(SG))@B0 - meanK*G1 + Ub ; z1: Pv likewise     (N=512)
__global__ __launch_bounds__(256,2) void gemm2(int modeBase, const float* __restrict__ A0,
                                               const float* __restrict__ B0,
                                               const float* __restrict__ B1,
                                               const float* __restrict__ sgv,
                                               const float* __restrict__ sbv, int N)
{
    int z = blockIdx.z;
    const float* A = (modeBase==0) ? A0 : (z==0 ? g_K : g_V);
    const float* Bm = z ? B1 : B0;
    float* Cm = (modeBase==0) ? (z ? g_V : g_K) : (z ? g_Pv : g_Pk);
    const float* meanV = (modeBase==0) ? nullptr : (z ? g_meanV : g_meanK);

    __shared__ float As[16][128];
    __shared__ float Bs[16][128];
    __shared__ float SG[256], SB[256];
    int bm = blockIdx.y*128, bn = blockIdx.x*128;
    int tid = threadIdx.x;
    int tx = tid & 15, ty = tid >> 4;
    int arr = tid >> 1, akk = (tid & 1) * 8;
    int bkk = tid >> 5, bcc = (tid & 31) * 4;
    float acc[8][8] = {};

    SG[tid] = sgv[tid];
    SB[tid] = sbv ? sbv[tid] : 0.f;
    float rm = 0.f, ris = 1.f;
    if (modeBase == 0){ rm = g_lnM[bm+arr]; ris = g_lnIS[bm+arr]; }
    __syncthreads();

    for (int k0 = 0; k0 < 256; k0 += 16) {
        const float* ap = A + (size_t)(bm+arr)*256 + k0 + akk;
        float4 a0 = *(const float4*)ap;
        float4 a1 = *(const float4*)(ap + 4);
        if (modeBase) {
            a0.x*=SG[k0+akk+0]; a0.y*=SG[k0+akk+1];
            a0.z*=SG[k0+akk+2]; a0.w*=SG[k0+akk+3];
            a1.x*=SG[k0+akk+4]; a1.y*=SG[k0+akk+5];
            a1.z*=SG[k0+akk+6]; a1.w*=SG[k0+akk+7];
        } else {
            a0.x = fmaf((a0.x-rm)*ris, SG[k0+akk+0], SB[k0+akk+0]);
            a0.y = fmaf((a0.y-rm)*ris, SG[k0+akk+1], SB[k0+akk+1]);
            a0.z = fmaf((a0.z-rm)*ris, SG[k0+akk+2], SB[k0+akk+2]);
            a0.w = fmaf((a0.w-rm)*ris, SG[k0+akk+3], SB[k0+akk+3]);
            a1.x = fmaf((a1.x-rm)*ris, SG[k0+akk+4], SB[k0+akk+4]);
            a1.y = fmaf((a1.y-rm)*ris, SG[k0+akk+5], SB[k0+akk+5]);
            a1.z = fmaf((a1.z-rm)*ris, SG[k0+akk+6], SB[k0+akk+6]);
            a1.w = fmaf((a1.w-rm)*ris, SG[k0+akk+7], SB[k0+akk+7]);
        }
        float4 b0 = *(const float4*)(Bm + (size_t)(k0+bkk)*N + bn + bcc);
        float4 b1 = *(const float4*)(Bm + (size_t)(k0+bkk+8)*N + bn + bcc);
        __syncthreads();
        As[akk+0][arr]=a0.x; As[akk+1][arr]=a0.y; As[akk+2][arr]=a0.z; As[akk+3][arr]=a0.w;
        As[akk+4][arr]=a1.x; As[akk+5][arr]=a1.y; As[akk+6][arr]=a1.z; As[akk+7][arr]=a1.w;
        *(float4*)&Bs[bkk][bcc]   = b0;
        *(float4*)&Bs[bkk+8][bcc] = b1;
        __syncthreads();
        #pragma unroll
        for (int kk = 0; kk < 16; kk++) {
            float ar[8], br[8];
            *(float4*)ar     = *(const float4*)&As[kk][ty*8];
            *(float4*)(ar+4) = *(const float4*)&As[kk][ty*8+4];
            *(float4*)br     = *(const float4*)&Bs[kk][tx*8];
            *(float4*)(br+4) = *(const float4*)&Bs[kk][tx*8+4];
            #pragma unroll
            for (int i=0;i<8;i++)
                #pragma unroll
                for (int j=0;j<8;j++) acc[i][j] = fmaf(ar[i], br[j], acc[i][j]);
        }
    }
    #pragma unroll
    for (int i=0;i<8;i++){
        int r = bm + ty*8 + i;
        float mk = meanV ? meanV[r] : 0.f;
        int c0 = bn + tx*8;
        float vals[8];
        #pragma unroll
        for (int j=0;j<8;j++){
            float v = acc[i][j];
            if (modeBase) v = v - mk*g_G1[c0+j] + g_Ub[c0+j];
            vals[j] = v;
        }
        *(float4*)(Cm + (size_t)r*N + c0)     = *(float4*)vals;
        *(float4*)(Cm + (size_t)r*N + c0 + 4) = *(float4*)(vals+4);
    }
}

// ---------------- stats (warp-per-row) ----------------
__global__ __launch_bounds__(512) void stats2(const float* __restrict__ gp_w, const float* __restrict__ gp_b)
{
    int r = blockIdx.x*16 + (threadIdx.x>>5);
    int lane = threadIdx.x & 31;
    float m0=g_cov[0], m1=g_cov[1], mb=g_cov[2];
    float Vbb=g_cov[5], C0b=g_cov[7], C1b=g_cov[8];
    float g0[8], g1[8], gbv[8];
    #pragma unroll
    for (int k=0;k<8;k++){
        int d = k*32+lane;
        g0[k]=gp_w[d]-m0; g1[k]=gp_w[D+d]-m1; gbv[k]=gp_b[d]-mb;
    }
    #pragma unroll
    for (int br=0; br<2; br++){
        const float* src = br ? g_V : g_K;
        float sK=0,sK2=0,s0=0,s1=0,sb=0;
        #pragma unroll
        for (int k=0;k<8;k++){
            float x = src[(size_t)r*D + k*32 + lane];
            sK+=x; sK2=fmaf(x,x,sK2); s0=fmaf(x,g0[k],s0); s1=fmaf(x,g1[k],s1); sb=fmaf(x,gbv[k],sb);
        }
        sK=warpSum(sK); sK2=warpSum(sK2); s0=warpSum(s0); s1=warpSum(s1); sb=warpSum(sb);
        if (lane == 0){
            float mk = sK*(1.f/D);
            float Vkk = sK2*(1.f/D) - mk*mk;
            float Ck0 = s0*(1.f/D), Ck1 = s1*(1.f/D), Ckb = sb*(1.f/D);
            float* st = br ? (g_statsV + r*4) : (g_statsK + r*4);
            st[0] = Vkk + Vbb + 2.f*Ckb;
            st[1] = 2.f*(Ck0 + C0b);
            st[2] = 2.f*(Ck1 + C1b);
            st[3] = 0.f;
            if (br) g_meanV[r]=mk; else g_meanK[r]=mk;
        }
    }
}

// ---------------- per-slot q/wtil/scalars (512 threads) ----------------
__device__ __forceinline__ void slot_compute(
    int s, int t, const float* so,
    const float* __restrict__ ns_g, const float* __restrict__ ns_b,
    const float* __restrict__ wq,   const float* __restrict__ W2, const float* __restrict__ b2,
    float* sh, float* sq, float* qpart, float* red)
{
    int w = t >> 5, lane = t & 31;
    float v = (t < 256) ? so[t] : 0.f;
    float ws = warpSum(v);
    if (lane == 0 && t < 256) red[w] = ws;
    __syncthreads();
    float m = 0.f;
    #pragma unroll
    for (int i=0;i<8;i++) m += red[i];
    m *= (1.f/D);
    float d = (t < 256) ? (v - m) : 0.f;
    ws = warpSum(d*d);
    __syncthreads();
    if (lane == 0 && t < 256) red[w] = ws;
    __syncthreads();
    float var = 0.f;
    #pragma unroll
    for (int i=0;i<8;i++) var += red[i];
    var *= (1.f/D);
    if (t < 256) sh[t] = d * rsqrtf(var + LNEPS) * ns_g[t] + ns_b[t];
    __syncthreads();
    int tt = t & 255, half = t >> 8;
    float q = 0.f;
    #pragma unroll 4
    for (int dd = half*128; dd < half*128 + 128; dd++)
        q = fmaf(sh[dd], wq[dd*D + tt], q);
    qpart[t] = q;
    __syncthreads();
    if (t < 256) sq[t] = qpart[t] + qpart[256 + t];
    __syncthreads();
    float p = (t < 256) ? sq[t]*b2[t] : 0.f;
    ws = warpSum(p);
    __syncthreads();
    if (lane == 0 && t < 256) red[w] = ws;
    __syncthreads();
    for (int k = 0; k < 32; k++){
        int j = (k << 4) + w;
        const float* w2r = W2 + j*D;
        float acc = 0.f;
        #pragma unroll
        for (int dd=0; dd<8; dd++) acc = fmaf(w2r[dd*32+lane], sq[dd*32+lane], acc);
        acc = warpSum(acc);
        if (lane == 0) g_slot[s*520 + j] = acc;
    }
    if (t == 0){
        float qb2 = 0.f;
        #pragma unroll
        for (int i=0;i<8;i++) qb2 += red[i];
        float px = fminf(fmaxf(g_Cond[s*260+256], -1.f), 1.f);
        float py = fminf(fmaxf(g_Cond[s*260+257], -1.f), 1.f);
        float sx = fminf(fmaxf(g_Cond[s*260+258], 1e-3f), 2.f);
        float sy = fminf(fmaxf(g_Cond[s*260+259], 1e-3f), 2.f);
        float* o = g_slot + s*520 + 512;
        o[0]=qb2; o[1]=px; o[2]=py; o[3]=1.f/(5.f*sx); o[4]=1.f/(5.f*sy);
    }
}

__global__ __launch_bounds__(512) void slot0(const float* __restrict__ ns_g, const float* __restrict__ ns_b,
                                             const float* __restrict__ wq,   const float* __restrict__ W2,
                                             const float* __restrict__ b2)
{
    __shared__ float so[256], sh[256], sq[256], qpart[512], red[16];
    int s = blockIdx.x, t = threadIdx.x;
    if (t < 256) so[t] = g_Cond[s*260 + t];
    __syncthreads();
    slot_compute(s, t, so, ns_g, ns_b, wq, W2, b2, sh, sq, qpart, red);
}

// ---------------- fused: dots + softmax + attn0 + partials (16 px/CTA) ----------------
__global__ __launch_bounds__(256) void iter1_kernel(int last, float* __restrict__ out)
{
    int b = blockIdx.y, chunk = blockIdx.x;   // 64 chunks of 16 px
    int t = threadIdx.x, w = t >> 5, lane = t & 31;
    __shared__ float sdots[NS][16];
    __shared__ float sscal[NS][5];

    float* attnDst = last ? (out + 16640) : g_attn0;
    float* relOut  = out + 16640 + 65536;

    float4 u0v[4], u1v[4], wtv[4], cv[4];
    const float* wts = g_slot + (b*NS + w)*520;
    #pragma unroll
    for (int jj=0; jj<4; jj++){
        int j = jj*128 + lane*4;
        u0v[jj] = *(const float4*)(g_U0 + j);
        u1v[jj] = *(const float4*)(g_U1 + j);
        cv[jj]  = *(const float4*)(g_C  + j);
        wtv[jj] = *(const float4*)(wts  + j);
    }
    if (t < 40) sscal[t/5][t%5] = g_slot[(b*NS + t/5)*520 + 512 + (t%5)];
    __syncthreads();

    float qb2=sscal[w][0], px=sscal[w][1], py=sscal[w][2], i5x=sscal[w][3], i5y=sscal[w][4];
    float V00=g_cov[3], V11=g_cov[4], C01_2=2.f*g_cov[6];
    int n0 = chunk*16;

    for (int pp=0; pp<16; pp++){
        int n = n0 + pp;
        float gx = -1.f + (float)(n>>5)*GSTEP;
        float gy = -1.f + (float)(n&31)*GSTEP;
        float a = (gx-px)*i5x, c = (gy-py)*i5y;
        const float4 st = *(const float4*)(g_statsK + ((b<<10)+n)*4);
        float var = st.x + a*st.y + c*st.z + a*a*V00 + c*c*V11 + a*c*C01_2;
        float isig = rsqrtf(var + LNEPS);
        const float* pk = g_Pk + (((size_t)(b<<10)+n)<<9);
        float ac0=0.f, ac1=0.f;
        #pragma unroll
        for (int jj=0; jj<4; jj++){
            float4 p4 = __ldg((const float4*)(pk + jj*128 + lane*4));
            float e0 = fmaf(isig, fmaf(c,u1v[jj].x, fmaf(a,u0v[jj].x, p4.x)), cv[jj].x);
            float e1 = fmaf(isig, fmaf(c,u1v[jj].y, fmaf(a,u0v[jj].y, p4.y)), cv[jj].y);
            float e2 = fmaf(isig, fmaf(c,u1v[jj].z, fmaf(a,u0v[jj].z, p4.z)), cv[jj].z);
            float e3 = fmaf(isig, fmaf(c,u1v[jj].w, fmaf(a,u0v[jj].w, p4.w)), cv[jj].w);
            ac0 = fmaf(fmaxf(e0,0.f), wtv[jj].x, ac0);
            ac1 = fmaf(fmaxf(e1,0.f), wtv[jj].y, ac1);
            ac0 = fmaf(fmaxf(e2,0.f), wtv[jj].z, ac0);
            ac1 = fmaf(fmaxf(e3,0.f), wtv[jj].w, ac1);
        }
        float acc = warpSum(ac0 + ac1);
        if (lane == 0){
            sdots[w][pp] = ATTN_SCALE * (acc + qb2);
            if (last){
                float2* rp = (float2*)(relOut + ((((size_t)(b*NS+w)<<10)+n)<<1));
                *rp = make_float2(a, c);
            }
        }
    }
    __syncthreads();

    float a0 = 0.f, gx = 0.f, gy = 0.f;
    if (lane < 16){
        int n = n0 + lane;
        float dd[NS]; float mx = -1e30f;
        #pragma unroll
        for (int k=0;k<NS;k++){ dd[k] = sdots[k][lane]; mx = fmaxf(mx, dd[k]); }
        float sum = 0.f;
        #pragma unroll
        for (int k=0;k<NS;k++){ dd[k] = expf(dd[k]-mx); sum += dd[k]; }
        a0 = dd[w] / sum;
        attnDst[((b*NS+w)<<10) + n] = a0;
        gx = -1.f + (float)(n>>5)*GSTEP;
        gy = -1.f + (float)(n&31)*GSTEP;
    }
    float S0 = warpSum(a0);
    float Sx = warpSum(a0*gx);
    float Sy = warpSum(a0*gy);
    float Sxx = warpSum(a0*gx*gx);
    float Syy = warpSum(a0*gy*gy);
    if (lane == 0){
        float* pp = g_part + ((size_t)((b*NS+w)*64 + chunk))*8;
        pp[0]=S0; pp[1]=Sx; pp[2]=Sy; pp[3]=Sxx; pp[4]=Syy;
    }
}

// ---------------- slot-fused vacc + finalize (64 px/CTA, all 8 slots) ----------------
__global__ __launch_bounds__(512) void vaccF_kernel()
{
    int chunk = blockIdx.x;    // 0..15 (64 px each)
    int b = blockIdx.y;        // 0..7
    int t = threadIdx.x;
    __shared__ float4 sC4[NS][64];   // (is, is*a, is*c, w)
    __shared__ float sden[NS];

    // coefficient phase: thread t -> (slot sl, pixel p)
    int sl = t >> 6, p = t & 63;
    int n = chunk*64 + p;
    int gs = b*NS + sl;
    float rawA;
    {
        float px = g_slot[gs*520+513], py = g_slot[gs*520+514];
        float i5x= g_slot[gs*520+515], i5y= g_slot[gs*520+516];
        float gx = -1.f + (float)(n>>5)*GSTEP;
        float gy = -1.f + (float)(n&31)*GSTEP;
        float a = (gx-px)*i5x, c = (gy-py)*i5y;
        const float4 st = *(const float4*)(g_statsV + ((b<<10)+n)*4);
        float var = st.x + a*st.y + c*st.z + a*a*g_cov[3] + c*c*g_cov[4] + a*c*2.f*g_cov[6];
        float is = rsqrtf(var + LNEPS);
        rawA = g_attn0[(gs<<10)+n];
        sC4[sl][p] = make_float4(is, is*a, is*c, 0.f);
    }
    // denom (and pos/scl if chunk 0): warps 0..7 handle slots 0..7
    if (t < 256){
        int w = t >> 5, lane = t & 31;
        const float* pp0 = g_part + ((size_t)((b*NS+w)*64 + lane))*8;
        const float* pp1 = pp0 + 32*8;
        float S0 = warpSum(pp0[0] + pp1[0]);
        if (chunk == 0){
            float Sx = warpSum(pp0[1] + pp1[1]);
            float Sy = warpSum(pp0[2] + pp1[2]);
            float Sxx = warpSum(pp0[3] + pp1[3]);
            float Syy = warpSum(pp0[4] + pp1[4]);
            if (lane == 0){
                float px = Sx, py = Sy, G2 = g_cov[9];
                float vx = Sxx - 2.f*px*Sx + px*px*S0 + EPSA*(G2 + 1024.f*px*px);
                float vy = Syy - 2.f*py*Sy + py*py*S0 + EPSA*(G2 + 1024.f*py*py);
                float sx = fminf(fmaxf(sqrtf(fmaxf(vx,0.f)), 1e-3f), 2.f);
                float sy = fminf(fmaxf(sqrtf(fmaxf(vy,0.f)), 1e-3f), 2.f);
                int s2 = b*NS + w;
                g_Cond[s2*260+256]=px; g_Cond[s2*260+257]=py;
                g_Cond[s2*260+258]=sx; g_Cond[s2*260+259]=sy;
            }
        }
        if (lane == 0) sden[w] = 1.f/(S0 + 1024.f*EPSA);
    }
    __syncthreads();
    sC4[sl][p].w = (rawA + EPSA) * sden[sl];
    __syncthreads();

    // main: thread t owns hidden j = t, accumulates 8 slots over 64 pixels
    float u0 = g_U0[t], u1 = g_U1[t], C = g_C[t];
    const float* pvb = g_Pv + ((((size_t)(b<<10)) + (size_t)chunk*64) << 9) + t;
    float acc[NS] = {};
    #pragma unroll 4
    for (int q=0; q<64; q++){
        float pv = __ldg(pvb + ((size_t)q << 9));
        #pragma unroll
        for (int s2=0; s2<NS; s2++){
            float4 cf = sC4[s2][q];
            float pre = fmaf(cf.y, u0, fmaf(cf.z, u1, fmaf(cf.x, pv, C)));
            acc[s2] = fmaf(fmaxf(pre, 0.f), cf.w, acc[s2]);
        }
    }
    #pragma unroll
    for (int s2=0; s2<NS; s2++)
        g_spart[((size_t)((b*NS+s2)*16 + chunk))*H + t] = acc[s2];
}

// ---------------- GRU update + slot prep for next iter ----------------
__global__ __launch_bounds__(512) void updslot_kernel(
    const float* __restrict__ W2,  const float* __restrict__ b2,
    const float* __restrict__ Wih, const float* __restrict__ Whh,
    const float* __restrict__ bih, const float* __restrict__ bhh,
    const float* __restrict__ ns_g, const float* __restrict__ ns_b,
    const float* __restrict__ wq)
{
    __shared__ float ss[H], so[256], su[256], qpart[512], sgx[768], sgh[768], sh[256], sq[256], red[16];
    int s = blockIdx.x, t = threadIdx.x, w = t >> 5, lane = t & 31;

    float r0 = 0.f;
    #pragma unroll
    for (int c=0; c<16; c++) r0 += g_spart[((size_t)(s*16 + c))*H + t];
    ss[t] = r0;
    if (t < 256) so[t] = g_Cond[s*260 + t];
    __syncthreads();

    int tt = t & 255, half = t >> 8;
    float u = 0.f;
    #pragma unroll 4
    for (int j = half*256; j < half*256 + 256; j++)
        u = fmaf(ss[j], W2[j*D + tt], u);
    qpart[t] = u;
    __syncthreads();
    if (t < 256) su[t] = qpart[t] + qpart[256+t] + b2[t];
    __syncthreads();

    for (int k = 0; k < 48; k++){
        int i = (k << 4) + w;
        const float* wi = Wih + i*D;
        const float* wh = Whh + i*D;
        float ax = 0.f, ah = 0.f;
        #pragma unroll
        for (int dd=0; dd<8; dd++){
            int dx = dd*32 + lane;
            ax = fmaf(wi[dx], su[dx], ax);
            ah = fmaf(wh[dx], so[dx], ah);
        }
        ax = warpSum(ax); ah = warpSum(ah);
        if (lane == 0){ sgx[i] = ax + bih[i]; sgh[i] = ah + bhh[i]; }
    }
    __syncthreads();

    if (t < 256){
        float r = 1.f/(1.f + expf(-(sgx[t]     + sgh[t])));
        float z = 1.f/(1.f + expf(-(sgx[256+t] + sgh[256+t])));
        float nn = tanhf(sgx[512+t] + r*sgh[512+t]);
        float nv = (1.f - z)*nn + z*so[t];
        g_Cond[s*260 + t] = nv;
        so[t] = nv;
    }
    __syncthreads();

    slot_compute(s, t, so, ns_g, ns_b, wq, W2, b2, sh, sq, qpart, red);
}

// ---------------- final: pos/scl + write conditioning to out ----------------
__global__ void finz3_kernel(float* __restrict__ out)
{
    __shared__ float sres[4];
    int s = blockIdx.x, t = threadIdx.x;
    if (t < 32){
        const float* pp0 = g_part + ((size_t)(s*64 + t))*8;
        const float* pp1 = pp0 + 32*8;
        float S0 = warpSum(pp0[0] + pp1[0]);
        float Sx = warpSum(pp0[1] + pp1[1]);
        float Sy = warpSum(pp0[2] + pp1[2]);
        float Sxx = warpSum(pp0[3] + pp1[3]);
        float Syy = warpSum(pp0[4] + pp1[4]);
        if (t == 0){
            float px = Sx, py = Sy, G2 = g_cov[9];
            float vx = Sxx - 2.f*px*Sx + px*px*S0 + EPSA*(G2 + 1024.f*px*px);
            float vy = Syy - 2.f*py*Sy + py*py*S0 + EPSA*(G2 + 1024.f*py*py);
            float sx = fminf(fmaxf(sqrtf(fmaxf(vx,0.f)), 1e-3f), 2.f);
            float sy = fminf(fmaxf(sqrtf(fmaxf(vy,0.f)), 1e-3f), 2.f);
            sres[0]=px; sres[1]=py; sres[2]=sx; sres[3]=sy;
        }
    }
    __syncthreads();
    for (int i = t; i < 260; i += 256)
        out[s*260 + i] = (i < 256) ? g_Cond[s*260 + i] : sres[i - 256];
}

// ---------------- launch ----------------
extern "C" void kernel_launch(void* const* d_in, const int* in_sizes, int n_in,
                              void* d_out, int out_size)
{
    const float* inputs = (const float*)d_in[0];
    const float* cond   = (const float*)d_in[1];
    const float* ni_g   = (const float*)d_in[2];
    const float* ni_b   = (const float*)d_in[3];
    const float* ns_g   = (const float*)d_in[4];
    const float* ns_b   = (const float*)d_in[5];
    const float* wq     = (const float*)d_in[6];
    const float* wk     = (const float*)d_in[7];
    const float* wv     = (const float*)d_in[8];
    const float* gp_w   = (const float*)d_in[9];
    const float* gp_b   = (const float*)d_in[10];
    const float* ge_ln_g= (const float*)d_in[11];
    const float* ge_ln_b= (const float*)d_in[12];
    const float* ge_w1  = (const float*)d_in[13];
    const float* ge_b1  = (const float*)d_in[14];
    const float* ge_w2  = (const float*)d_in[15];
    const float* ge_b2  = (const float*)d_in[16];
    const float* gru_wih= (const float*)d_in[17];
    const float* gru_whh= (const float*)d_in[18];
    const float* gru_bih= (const float*)d_in[19];
    const float* gru_bhh= (const float*)d_in[20];
    float* out = (float*)d_out;

    pre_kernel<<<546, 512>>>(gp_w, gp_b, ge_ln_g, ge_ln_b, ge_w1, ge_b1, cond, inputs);
    gemm2<<<dim3(2,64,2), 256>>>(0, inputs, wk, wv, ni_g, ni_b, 256);
    stats2<<<512, 512>>>(gp_w, gp_b);
    gemm2<<<dim3(4,64,2), 256>>>(2, nullptr, ge_w1, ge_w1, ge_ln_g, nullptr, 512);
    slot0<<<64, 512>>>(ns_g, ns_b, wq, ge_w2, ge_b2);

    for (int it = 0; it < 3; it++) {
        iter1_kernel<<<dim3(64,8), 256>>>(0, out);
        vaccF_kernel<<<dim3(16,8), 512>>>();
        updslot_kernel<<<64, 512>>>(ge_w2, ge_b2, gru_wih, gru_whh, gru_bih, gru_bhh,
                                    ns_g, ns_b, wq);
    }
    iter1_kernel<<<dim3(64,8), 256>>>(1, out);
    finz3_kernel<<<64, 256>>>(out);
}

// round 5
// speedup vs baseline: 3.3677x; 1.2434x over previous
#include <cuda_runtime.h>
#include <math.h>

// ---------------- problem constants ----------------
#define NB 8
#define NPIX 1024
#define NS 8
#define D 256
#define H 512
#define NROWS (NB*NPIX)
#define EPSA 1e-8f
#define LNEPS 1e-5f
#define ATTN_SCALE 0.0625f
#define GSTEP (2.0f/31.0f)

// ---------------- scratch ----------------
__device__ __align__(16) float g_K [NROWS*D];
__device__ __align__(16) float g_V [NROWS*D];
__device__ __align__(16) float g_Pk[NROWS*H];
__device__ __align__(16) float g_Pv[NROWS*H];
__device__ __align__(16) float g_statsK[NROWS*4];
__device__ __align__(16) float g_statsV[NROWS*4];
__device__ float g_meanK[NROWS];
__device__ float g_meanV[NROWS];
__device__ float g_lnM[NROWS];
__device__ float g_lnIS[NROWS];
__device__ __align__(16) float g_U0[H];
__device__ __align__(16) float g_U1[H];
__device__ __align__(16) float g_Ub[H];
__device__ __align__(16) float g_C[H];
__device__ __align__(16) float g_G1[H];
__device__ float g_cov[16];
__device__ float g_Cond[NB*NS*260];
__device__ __align__(16) float g_slot[NB*NS*520]; // [0..511]=wtil, 512=qb2,513=px,514=py,515=i5x,516=i5y
__device__ float g_attn0[NB*NS*NPIX];
__device__ float g_part[NB*NS*64*8];   // per (slot, 16px-chunk) partials (5 used)
__device__ float g_spart[NB*NS*16*H];  // per (slot, 64px-chunk) partial s vectors

__device__ __forceinline__ float warpSum(float v) {
    #pragma unroll
    for (int o = 16; o; o >>= 1) v += __shfl_xor_sync(0xffffffffu, v, o);
    return v;
}

// ---------------- pre: constants + cond copy + LN row stats ----------------
__global__ __launch_bounds__(512) void pre_kernel(
    const float* __restrict__ gp_w, const float* __restrict__ gp_b,
    const float* __restrict__ lg,   const float* __restrict__ lb,
    const float* __restrict__ W1,   const float* __restrict__ b1,
    const float* __restrict__ cond, const float* __restrict__ inputs)
{
    int bid = blockIdx.x;
    if (bid >= 34) {
        int r = (bid - 34)*16 + (threadIdx.x>>5);
        int lane = threadIdx.x & 31;
        const float* row = inputs + (size_t)r*D;
        float v[8]; float s = 0.f;
        #pragma unroll
        for (int k=0;k<8;k++){ v[k]=row[k*32+lane]; s+=v[k]; }
        float m = warpSum(s) * (1.f/D);
        float q = 0.f;
        #pragma unroll
        for (int k=0;k<8;k++){ float d=v[k]-m; q += d*d; }
        float is = rsqrtf(warpSum(q)*(1.f/D) + LNEPS);
        if (lane == 0){ g_lnM[r]=m; g_lnIS[r]=is; }
        return;
    }
    if (bid > 0) {
        int i = (bid - 1)*512 + threadIdx.x;
        if (i < NB*NS*260) g_Cond[i] = cond[i];
        return;
    }
    __shared__ float sg0[D], sg1[D], sgb[D], slg[D], slb[D];
    __shared__ float sm[4];
    int t = threadIdx.x; // 512
    if (t < D) { sg0[t]=gp_w[t]; sg1[t]=gp_w[D+t]; sgb[t]=gp_b[t]; slg[t]=lg[t]; slb[t]=lb[t]; }
    __syncthreads();
    if (t == 0) {
        float m0=0,m1=0,mb=0;
        for (int d=0; d<D; d++){ m0+=sg0[d]; m1+=sg1[d]; mb+=sgb[d]; }
        m0*=(1.f/D); m1*=(1.f/D); mb*=(1.f/D);
        float V00=0,V11=0,Vbb=0,C01=0,C0b=0,C1b=0;
        for (int d=0; d<D; d++){
            float a=sg0[d]-m0, b_=sg1[d]-m1, c=sgb[d]-mb;
            V00+=a*a; V11+=b_*b_; Vbb+=c*c; C01+=a*b_; C0b+=a*c; C1b+=b_*c;
        }
        g_cov[0]=m0; g_cov[1]=m1; g_cov[2]=mb;
        g_cov[3]=V00/D; g_cov[4]=V11/D; g_cov[5]=Vbb/D;
        g_cov[6]=C01/D; g_cov[7]=C0b/D; g_cov[8]=C1b/D;
        float s2=0;
        for (int i=0;i<32;i++){ float x=-1.f + i*GSTEP; s2+=x*x; }
        g_cov[9]=s2*32.f;
        sm[0]=m0; sm[1]=m1; sm[2]=mb;
    }
    __syncthreads();
    float m0=sm[0], m1=sm[1], mb=sm[2];
    float U0=0,U1=0,Ub=0,Cc=0,G1=0;
    for (int d=0; d<D; d++){
        float w = W1[d*H + t];
        float gd = slg[d];
        U0 = fmaf((sg0[d]-m0)*gd, w, U0);
        U1 = fmaf((sg1[d]-m1)*gd, w, U1);
        Ub = fmaf((sgb[d]-mb)*gd, w, Ub);
        Cc = fmaf(slb[d], w, Cc);
        G1 = fmaf(gd, w, G1);
    }
    g_U0[t]=U0; g_U1[t]=U1; g_Ub[t]=Ub; g_C[t]=Cc + b1[t]; g_G1[t]=G1;
}

// ---------------- GEMM: 128x128 tile, 8x8 micro, register double-buffer ----------------
// modeBase 0: A = LN(inputs) on the fly; z0: K = A@B0, z1: V = A@B1  (N=256)
// modeBase 2: z0: Pk = (K*diag(SG))@B0 - meanK*G1 + Ub ; z1: Pv likewise (N=512)
__global__ __launch_bounds__(256,2) void gemm2(int modeBase, const float* __restrict__ A0,
                                               const float* __restrict__ B0,
                                               const float* __restrict__ B1,
                                               const float* __restrict__ sgv,
                                               const float* __restrict__ sbv, int N)
{
    int z = blockIdx.z;
    const float* A = (modeBase==0) ? A0 : (z==0 ? g_K : g_V);
    const float* Bm = z ? B1 : B0;
    float* Cm = (modeBase==0) ? (z ? g_V : g_K) : (z ? g_Pv : g_Pk);
    const float* meanV = (modeBase==0) ? nullptr : (z ? g_meanV : g_meanK);

    __shared__ float As[16][128];
    __shared__ float Bs[16][128];
    __shared__ float SG[256], SB[256];
    int bm = blockIdx.y*128, bn = blockIdx.x*128;
    int tid = threadIdx.x;
    int tx = tid & 15, ty = tid >> 4;
    int arr = tid >> 1, akk = (tid & 1) * 8;
    int bkk = tid >> 5, bcc = (tid & 31) * 4;
    float acc[8][8] = {};

    SG[tid] = sgv[tid];
    SB[tid] = sbv ? sbv[tid] : 0.f;
    float rm = 0.f, ris = 1.f;
    if (modeBase == 0){ rm = g_lnM[bm+arr]; ris = g_lnIS[bm+arr]; }
    __syncthreads();

    const float* apb = A + (size_t)(bm+arr)*256 + akk;
    const float* bpb = Bm + (size_t)bkk*N + bn + bcc;
    // prefetch k0 = 0
    float4 pa0 = *(const float4*)apb;
    float4 pa1 = *(const float4*)(apb + 4);
    float4 pb0 = *(const float4*)bpb;
    float4 pb1 = *(const float4*)(bpb + (size_t)8*N);

    #pragma unroll 1
    for (int k0 = 0; k0 < 256; k0 += 16) {
        float4 a0 = pa0, a1 = pa1, b0 = pb0, b1 = pb1;
        if (modeBase) {
            a0.x*=SG[k0+akk+0]; a0.y*=SG[k0+akk+1];
            a0.z*=SG[k0+akk+2]; a0.w*=SG[k0+akk+3];
            a1.x*=SG[k0+akk+4]; a1.y*=SG[k0+akk+5];
            a1.z*=SG[k0+akk+6]; a1.w*=SG[k0+akk+7];
        } else {
            a0.x = fmaf((a0.x-rm)*ris, SG[k0+akk+0], SB[k0+akk+0]);
            a0.y = fmaf((a0.y-rm)*ris, SG[k0+akk+1], SB[k0+akk+1]);
            a0.z = fmaf((a0.z-rm)*ris, SG[k0+akk+2], SB[k0+akk+2]);
            a0.w = fmaf((a0.w-rm)*ris, SG[k0+akk+3], SB[k0+akk+3]);
            a1.x = fmaf((a1.x-rm)*ris, SG[k0+akk+4], SB[k0+akk+4]);
            a1.y = fmaf((a1.y-rm)*ris, SG[k0+akk+5], SB[k0+akk+5]);
            a1.z = fmaf((a1.z-rm)*ris, SG[k0+akk+6], SB[k0+akk+6]);
            a1.w = fmaf((a1.w-rm)*ris, SG[k0+akk+7], SB[k0+akk+7]);
        }
        __syncthreads();
        As[akk+0][arr]=a0.x; As[akk+1][arr]=a0.y; As[akk+2][arr]=a0.z; As[akk+3][arr]=a0.w;
        As[akk+4][arr]=a1.x; As[akk+5][arr]=a1.y; As[akk+6][arr]=a1.z; As[akk+7][arr]=a1.w;
        *(float4*)&Bs[bkk][bcc]   = b0;
        *(float4*)&Bs[bkk+8][bcc] = b1;
        __syncthreads();
        if (k0 < 240){
            const float* ap = apb + k0 + 16;
            const float* bp = bpb + (size_t)(k0+16)*N;
            pa0 = *(const float4*)ap;
            pa1 = *(const float4*)(ap + 4);
            pb0 = *(const float4*)bp;
            pb1 = *(const float4*)(bp + (size_t)8*N);
        }
        #pragma unroll
        for (int kk = 0; kk < 16; kk++) {
            float ar[8], br[8];
            *(float4*)ar     = *(const float4*)&As[kk][ty*8];
            *(float4*)(ar+4) = *(const float4*)&As[kk][ty*8+4];
            *(float4*)br     = *(const float4*)&Bs[kk][tx*8];
            *(float4*)(br+4) = *(const float4*)&Bs[kk][tx*8+4];
            #pragma unroll
            for (int i=0;i<8;i++)
                #pragma unroll
                for (int j=0;j<8;j++) acc[i][j] = fmaf(ar[i], br[j], acc[i][j]);
        }
    }
    #pragma unroll
    for (int i=0;i<8;i++){
        int r = bm + ty*8 + i;
        float mk = meanV ? meanV[r] : 0.f;
        int c0 = bn + tx*8;
        float vals[8];
        #pragma unroll
        for (int j=0;j<8;j++){
            float v = acc[i][j];
            if (modeBase) v = v - mk*g_G1[c0+j] + g_Ub[c0+j];
            vals[j] = v;
        }
        *(float4*)(Cm + (size_t)r*N + c0)     = *(float4*)vals;
        *(float4*)(Cm + (size_t)r*N + c0 + 4) = *(float4*)(vals+4);
    }
}

// ---------------- stats (warp-per-row) ----------------
__global__ __launch_bounds__(512) void stats2(const float* __restrict__ gp_w, const float* __restrict__ gp_b)
{
    int r = blockIdx.x*16 + (threadIdx.x>>5);
    int lane = threadIdx.x & 31;
    float m0=g_cov[0], m1=g_cov[1], mb=g_cov[2];
    float Vbb=g_cov[5], C0b=g_cov[7], C1b=g_cov[8];
    float g0[8], g1[8], gbv[8];
    #pragma unroll
    for (int k=0;k<8;k++){
        int d = k*32+lane;
        g0[k]=gp_w[d]-m0; g1[k]=gp_w[D+d]-m1; gbv[k]=gp_b[d]-mb;
    }
    #pragma unroll
    for (int br=0; br<2; br++){
        const float* src = br ? g_V : g_K;
        float sK=0,sK2=0,s0=0,s1=0,sb=0;
        #pragma unroll
        for (int k=0;k<8;k++){
            float x = src[(size_t)r*D + k*32 + lane];
            sK+=x; sK2=fmaf(x,x,sK2); s0=fmaf(x,g0[k],s0); s1=fmaf(x,g1[k],s1); sb=fmaf(x,gbv[k],sb);
        }
        sK=warpSum(sK); sK2=warpSum(sK2); s0=warpSum(s0); s1=warpSum(s1); sb=warpSum(sb);
        if (lane == 0){
            float mk = sK*(1.f/D);
            float Vkk = sK2*(1.f/D) - mk*mk;
            float Ck0 = s0*(1.f/D), Ck1 = s1*(1.f/D), Ckb = sb*(1.f/D);
            float* st = br ? (g_statsV + r*4) : (g_statsK + r*4);
            st[0] = Vkk + Vbb + 2.f*Ckb;
            st[1] = 2.f*(Ck0 + C0b);
            st[2] = 2.f*(Ck1 + C1b);
            st[3] = 0.f;
            if (br) g_meanV[r]=mk; else g_meanK[r]=mk;
        }
    }
}

// ---------------- per-slot q/wtil/scalars (1024 threads) ----------------
__device__ __forceinline__ void slot_compute(
    int s, int t, const float* so,
    const float* __restrict__ ns_g, const float* __restrict__ ns_b,
    const float* __restrict__ wq,   const float* __restrict__ W2, const float* __restrict__ b2,
    float* sh, float* sq, float* qpart, float* red)
{
    int w = t >> 5, lane = t & 31;
    float v = (t < 256) ? so[t] : 0.f;
    float ws = warpSum(v);
    if (lane == 0 && t < 256) red[w] = ws;
    __syncthreads();
    float m = 0.f;
    #pragma unroll
    for (int i=0;i<8;i++) m += red[i];
    m *= (1.f/D);
    float d = (t < 256) ? (v - m) : 0.f;
    ws = warpSum(d*d);
    __syncthreads();
    if (lane == 0 && t < 256) red[w] = ws;
    __syncthreads();
    float var = 0.f;
    #pragma unroll
    for (int i=0;i<8;i++) var += red[i];
    var *= (1.f/D);
    if (t < 256) sh[t] = d * rsqrtf(var + LNEPS) * ns_g[t] + ns_b[t];
    __syncthreads();
    // q = sh @ wq : 4-way split-K
    int tt = t & 255, qr = t >> 8;
    float q = 0.f;
    #pragma unroll 4
    for (int dd = qr*64; dd < qr*64 + 64; dd++)
        q = fmaf(sh[dd], wq[dd*D + tt], q);
    qpart[t] = q;
    __syncthreads();
    if (t < 256) sq[t] = qpart[t] + qpart[256+t] + qpart[512+t] + qpart[768+t];
    __syncthreads();
    float p = (t < 256) ? sq[t]*b2[t] : 0.f;
    ws = warpSum(p);
    __syncthreads();
    if (lane == 0 && t < 256) red[w] = ws;
    __syncthreads();
    // wtil = W2 @ q : warp-per-row, 32 warps
    #pragma unroll 2
    for (int k = 0; k < 16; k++){
        int j = (k << 5) + w;
        const float* w2r = W2 + j*D;
        float acc = 0.f;
        #pragma unroll
        for (int dd=0; dd<8; dd++) acc = fmaf(w2r[dd*32+lane], sq[dd*32+lane], acc);
        acc = warpSum(acc);
        if (lane == 0) g_slot[s*520 + j] = acc;
    }
    if (t == 0){
        float qb2 = 0.f;
        #pragma unroll
        for (int i=0;i<8;i++) qb2 += red[i];
        float px = fminf(fmaxf(g_Cond[s*260+256], -1.f), 1.f);
        float py = fminf(fmaxf(g_Cond[s*260+257], -1.f), 1.f);
        float sx = fminf(fmaxf(g_Cond[s*260+258], 1e-3f), 2.f);
        float sy = fminf(fmaxf(g_Cond[s*260+259], 1e-3f), 2.f);
        float* o = g_slot + s*520 + 512;
        o[0]=qb2; o[1]=px; o[2]=py; o[3]=1.f/(5.f*sx); o[4]=1.f/(5.f*sy);
    }
}

__global__ __launch_bounds__(1024) void slot0(const float* __restrict__ ns_g, const float* __restrict__ ns_b,
                                              const float* __restrict__ wq,   const float* __restrict__ W2,
                                              const float* __restrict__ b2)
{
    __shared__ float so[256], sh[256], sq[256], qpart[1024], red[16];
    int s = blockIdx.x, t = threadIdx.x;
    if (t < 256) so[t] = g_Cond[s*260 + t];
    __syncthreads();
    slot_compute(s, t, so, ns_g, ns_b, wq, W2, b2, sh, sq, qpart, red);
}

// ---------------- fused: dots + softmax + attn0 + partials (16 px/CTA) ----------------
__global__ __launch_bounds__(256) void iter1_kernel(int last, float* __restrict__ out)
{
    int b = blockIdx.y, chunk = blockIdx.x;   // 64 chunks of 16 px
    int t = threadIdx.x, w = t >> 5, lane = t & 31;
    __shared__ float sdots[NS][16];
    __shared__ float sscal[NS][5];

    float* attnDst = last ? (out + 16640) : g_attn0;
    float* relOut  = out + 16640 + 65536;

    float4 u0v[4], u1v[4], wtv[4], cv[4];
    const float* wts = g_slot + (b*NS + w)*520;
    #pragma unroll
    for (int jj=0; jj<4; jj++){
        int j = jj*128 + lane*4;
        u0v[jj] = *(const float4*)(g_U0 + j);
        u1v[jj] = *(const float4*)(g_U1 + j);
        cv[jj]  = *(const float4*)(g_C  + j);
        wtv[jj] = *(const float4*)(wts  + j);
    }
    if (t < 40) sscal[t/5][t%5] = g_slot[(b*NS + t/5)*520 + 512 + (t%5)];
    __syncthreads();

    float qb2=sscal[w][0], px=sscal[w][1], py=sscal[w][2], i5x=sscal[w][3], i5y=sscal[w][4];
    float V00=g_cov[3], V11=g_cov[4], C01_2=2.f*g_cov[6];
    int n0 = chunk*16;

    for (int pp=0; pp<16; pp++){
        int n = n0 + pp;
        float gx = -1.f + (float)(n>>5)*GSTEP;
        float gy = -1.f + (float)(n&31)*GSTEP;
        float a = (gx-px)*i5x, c = (gy-py)*i5y;
        const float4 st = *(const float4*)(g_statsK + ((b<<10)+n)*4);
        float var = st.x + a*st.y + c*st.z + a*a*V00 + c*c*V11 + a*c*C01_2;
        float isig = rsqrtf(var + LNEPS);
        const float* pk = g_Pk + (((size_t)(b<<10)+n)<<9);
        float ac0=0.f, ac1=0.f;
        #pragma unroll
        for (int jj=0; jj<4; jj++){
            float4 p4 = __ldg((const float4*)(pk + jj*128 + lane*4));
            float e0 = fmaf(isig, fmaf(c,u1v[jj].x, fmaf(a,u0v[jj].x, p4.x)), cv[jj].x);
            float e1 = fmaf(isig, fmaf(c,u1v[jj].y, fmaf(a,u0v[jj].y, p4.y)), cv[jj].y);
            float e2 = fmaf(isig, fmaf(c,u1v[jj].z, fmaf(a,u0v[jj].z, p4.z)), cv[jj].z);
            float e3 = fmaf(isig, fmaf(c,u1v[jj].w, fmaf(a,u0v[jj].w, p4.w)), cv[jj].w);
            ac0 = fmaf(fmaxf(e0,0.f), wtv[jj].x, ac0);
            ac1 = fmaf(fmaxf(e1,0.f), wtv[jj].y, ac1);
            ac0 = fmaf(fmaxf(e2,0.f), wtv[jj].z, ac0);
            ac1 = fmaf(fmaxf(e3,0.f), wtv[jj].w, ac1);
        }
        float acc = warpSum(ac0 + ac1);
        if (lane == 0){
            sdots[w][pp] = ATTN_SCALE * (acc + qb2);
            if (last){
                float2* rp = (float2*)(relOut + ((((size_t)(b*NS+w)<<10)+n)<<1));
                *rp = make_float2(a, c);
            }
        }
    }
    __syncthreads();

    float a0 = 0.f, gx = 0.f, gy = 0.f;
    if (lane < 16){
        int n = n0 + lane;
        float dd[NS]; float mx = -1e30f;
        #pragma unroll
        for (int k=0;k<NS;k++){ dd[k] = sdots[k][lane]; mx = fmaxf(mx, dd[k]); }
        float sum = 0.f;
        #pragma unroll
        for (int k=0;k<NS;k++){ dd[k] = expf(dd[k]-mx); sum += dd[k]; }
        a0 = dd[w] / sum;
        attnDst[((b*NS+w)<<10) + n] = a0;
        gx = -1.f + (float)(n>>5)*GSTEP;
        gy = -1.f + (float)(n&31)*GSTEP;
    }
    float S0 = warpSum(a0);
    float Sx = warpSum(a0*gx);
    float Sy = warpSum(a0*gy);
    float Sxx = warpSum(a0*gx*gx);
    float Syy = warpSum(a0*gy*gy);
    if (lane == 0){
        float* pp = g_part + ((size_t)((b*NS+w)*64 + chunk))*8;
        pp[0]=S0; pp[1]=Sx; pp[2]=Sy; pp[3]=Sxx; pp[4]=Syy;
    }
}

// ---------------- slot-fused vacc + finalize (64 px/CTA, all 8 slots) ----------------
__global__ __launch_bounds__(512) void vaccF_kernel()
{
    int chunk = blockIdx.x;    // 0..15 (64 px each)
    int b = blockIdx.y;        // 0..7
    int t = threadIdx.x;
    __shared__ float4 sC4[NS][64];   // (is, is*a, is*c, w)
    __shared__ float sden[NS];

    int sl = t >> 6, p = t & 63;
    int n = chunk*64 + p;
    int gs = b*NS + sl;
    float rawA;
    {
        float px = g_slot[gs*520+513], py = g_slot[gs*520+514];
        float i5x= g_slot[gs*520+515], i5y= g_slot[gs*520+516];
        float gx = -1.f + (float)(n>>5)*GSTEP;
        float gy = -1.f + (float)(n&31)*GSTEP;
        float a = (gx-px)*i5x, c = (gy-py)*i5y;
        const float4 st = *(const float4*)(g_statsV + ((b<<10)+n)*4);
        float var = st.x + a*st.y + c*st.z + a*a*g_cov[3] + c*c*g_cov[4] + a*c*2.f*g_cov[6];
        float is = rsqrtf(var + LNEPS);
        rawA = g_attn0[(gs<<10)+n];
        sC4[sl][p] = make_float4(is, is*a, is*c, 0.f);
    }
    if (t < 256){
        int w = t >> 5, lane = t & 31;
        const float* pp0 = g_part + ((size_t)((b*NS+w)*64 + lane))*8;
        const float* pp1 = pp0 + 32*8;
        float S0 = warpSum(pp0[0] + pp1[0]);
        if (chunk == 0){
            float Sx = warpSum(pp0[1] + pp1[1]);
            float Sy = warpSum(pp0[2] + pp1[2]);
            float Sxx = warpSum(pp0[3] + pp1[3]);
            float Syy = warpSum(pp0[4] + pp1[4]);
            if (lane == 0){
                float px = Sx, py = Sy, G2 = g_cov[9];
                float vx = Sxx - 2.f*px*Sx + px*px*S0 + EPSA*(G2 + 1024.f*px*px);
                float vy = Syy - 2.f*py*Sy + py*py*S0 + EPSA*(G2 + 1024.f*py*py);
                float sx = fminf(fmaxf(sqrtf(fmaxf(vx,0.f)), 1e-3f), 2.f);
                float sy = fminf(fmaxf(sqrtf(fmaxf(vy,0.f)), 1e-3f), 2.f);
                int s2 = b*NS + w;
                g_Cond[s2*260+256]=px; g_Cond[s2*260+257]=py;
                g_Cond[s2*260+258]=sx; g_Cond[s2*260+259]=sy;
            }
        }
        if (lane == 0) sden[w] = 1.f/(S0 + 1024.f*EPSA);
    }
    __syncthreads();
    sC4[sl][p].w = (rawA + EPSA) * sden[sl];
    __syncthreads();

    float u0 = g_U0[t], u1 = g_U1[t], C = g_C[t];
    const float* pvb = g_Pv + ((((size_t)(b<<10)) + (size_t)chunk*64) << 9) + t;
    float acc[NS] = {};
    #pragma unroll 4
    for (int q=0; q<64; q++){
        float pv = __ldg(pvb + ((size_t)q << 9));
        #pragma unroll
        for (int s2=0; s2<NS; s2++){
            float4 cf = sC4[s2][q];
            float pre = fmaf(cf.y, u0, fmaf(cf.z, u1, fmaf(cf.x, pv, C)));
            acc[s2] = fmaf(fmaxf(pre, 0.f), cf.w, acc[s2]);
        }
    }
    #pragma unroll
    for (int s2=0; s2<NS; s2++)
        g_spart[((size_t)((b*NS+s2)*16 + chunk))*H + t] = acc[s2];
}

// ---------------- GRU update + slot prep for next iter (1024 threads) ----------------
__global__ __launch_bounds__(1024) void updslot_kernel(
    const float* __restrict__ W2,  const float* __restrict__ b2,
    const float* __restrict__ Wih, const float* __restrict__ Whh,
    const float* __restrict__ bih, const float* __restrict__ bhh,
    const float* __restrict__ ns_g, const float* __restrict__ ns_b,
    const float* __restrict__ wq)
{
    __shared__ float ss[H], so[256], su[256], qpart[1024], sgx[768], sgh[768], sh[256], sq[256], red[16];
    int s = blockIdx.x, t = threadIdx.x, w = t >> 5, lane = t & 31;

    if (t < 512){
        float r0 = 0.f;
        #pragma unroll
        for (int c=0; c<16; c++) r0 += g_spart[((size_t)(s*16 + c))*H + t];
        ss[t] = r0;
    }
    if (t < 256) so[t] = g_Cond[s*260 + t];
    __syncthreads();

    // u = ss @ W2 + b2 : 4-way split-K
    int tt = t & 255, qr = t >> 8;
    float u = 0.f;
    #pragma unroll 4
    for (int j = qr*128; j < qr*128 + 128; j++)
        u = fmaf(ss[j], W2[j*D + tt], u);
    qpart[t] = u;
    __syncthreads();
    if (t < 256) su[t] = qpart[t] + qpart[256+t] + qpart[512+t] + qpart[768+t] + b2[t];
    __syncthreads();

    // GRU matvecs: warp-per-row, 32 warps x 24 rows
    #pragma unroll 2
    for (int k = 0; k < 24; k++){
        int i = (k << 5) + w;
        const float* wi = Wih + i*D;
        const float* wh = Whh + i*D;
        float ax = 0.f, ah = 0.f;
        #pragma unroll
        for (int dd=0; dd<8; dd++){
            int dx = dd*32 + lane;
            ax = fmaf(wi[dx], su[dx], ax);
            ah = fmaf(wh[dx], so[dx], ah);
        }
        ax = warpSum(ax); ah = warpSum(ah);
        if (lane == 0){ sgx[i] = ax + bih[i]; sgh[i] = ah + bhh[i]; }
    }
    __syncthreads();

    if (t < 256){
        float r = 1.f/(1.f + expf(-(sgx[t]     + sgh[t])));
        float z = 1.f/(1.f + expf(-(sgx[256+t] + sgh[256+t])));
        float nn = tanhf(sgx[512+t] + r*sgh[512+t]);
        float nv = (1.f - z)*nn + z*so[t];
        g_Cond[s*260 + t] = nv;
        so[t] = nv;
    }
    __syncthreads();

    slot_compute(s, t, so, ns_g, ns_b, wq, W2, b2, sh, sq, qpart, red);
}

// ---------------- final: pos/scl + write conditioning to out ----------------
__global__ void finz3_kernel(float* __restrict__ out)
{
    __shared__ float sres[4];
    int s = blockIdx.x, t = threadIdx.x;
    if (t < 32){
        const float* pp0 = g_part + ((size_t)(s*64 + t))*8;
        const float* pp1 = pp0 + 32*8;
        float S0 = warpSum(pp0[0] + pp1[0]);
        float Sx = warpSum(pp0[1] + pp1[1]);
        float Sy = warpSum(pp0[2] + pp1[2]);
        float Sxx = warpSum(pp0[3] + pp1[3]);
        float Syy = warpSum(pp0[4] + pp1[4]);
        if (t == 0){
            float px = Sx, py = Sy, G2 = g_cov[9];
            float vx = Sxx - 2.f*px*Sx + px*px*S0 + EPSA*(G2 + 1024.f*px*px);
            float vy = Syy - 2.f*py*Sy + py*py*S0 + EPSA*(G2 + 1024.f*py*py);
            float sx = fminf(fmaxf(sqrtf(fmaxf(vx,0.f)), 1e-3f), 2.f);
            float sy = fminf(fmaxf(sqrtf(fmaxf(vy,0.f)), 1e-3f), 2.f);
            sres[0]=px; sres[1]=py; sres[2]=sx; sres[3]=sy;
        }
    }
    __syncthreads();
    for (int i = t; i < 260; i += 256)
        out[s*260 + i] = (i < 256) ? g_Cond[s*260 + i] : sres[i - 256];
}

// ---------------- launch ----------------
extern "C" void kernel_launch(void* const* d_in, const int* in_sizes, int n_in,
                              void* d_out, int out_size)
{
    const float* inputs = (const float*)d_in[0];
    const float* cond   = (const float*)d_in[1];
    const float* ni_g   = (const float*)d_in[2];
    const float* ni_b   = (const float*)d_in[3];
    const float* ns_g   = (const float*)d_in[4];
    const float* ns_b   = (const float*)d_in[5];
    const float* wq     = (const float*)d_in[6];
    const float* wk     = (const float*)d_in[7];
    const float* wv     = (const float*)d_in[8];
    const float* gp_w   = (const float*)d_in[9];
    const float* gp_b   = (const float*)d_in[10];
    const float* ge_ln_g= (const float*)d_in[11];
    const float* ge_ln_b= (const float*)d_in[12];
    const float* ge_w1  = (const float*)d_in[13];
    const float* ge_b1  = (const float*)d_in[14];
    const float* ge_w2  = (const float*)d_in[15];
    const float* ge_b2  = (const float*)d_in[16];
    const float* gru_wih= (const float*)d_in[17];
    const float* gru_whh= (const float*)d_in[18];
    const float* gru_bih= (const float*)d_in[19];
    const float* gru_bhh= (const float*)d_in[20];
    float* out = (float*)d_out;

    pre_kernel<<<546, 512>>>(gp_w, gp_b, ge_ln_g, ge_ln_b, ge_w1, ge_b1, cond, inputs);
    gemm2<<<dim3(2,64,2), 256>>>(0, inputs, wk, wv, ni_g, ni_b, 256);
    stats2<<<512, 512>>>(gp_w, gp_b);
    gemm2<<<dim3(4,64,2), 256>>>(2, nullptr, ge_w1, ge_w1, ge_ln_g, nullptr, 512);
    slot0<<<64, 1024>>>(ns_g, ns_b, wq, ge_w2, ge_b2);

    for (int it = 0; it < 3; it++) {
        iter1_kernel<<<dim3(64,8), 256>>>(0, out);
        vaccF_kernel<<<dim3(16,8), 512>>>();
        updslot_kernel<<<64, 1024>>>(ge_w2, ge_b2, gru_wih, gru_whh, gru_bih, gru_bhh,
                                     ns_g, ns_b, wq);
    }
    iter1_kernel<<<dim3(64,8), 256>>>(1, out);
    finz3_kernel<<<64, 256>>>(out);
}

// round 6
// speedup vs baseline: 3.5384x; 1.0507x over previous
#include <cuda_runtime.h>
#include <math.h>

// ---------------- problem constants ----------------
#define NB 8
#define NPIX 1024
#define NS 8
#define D 256
#define H 512
#define NROWS (NB*NPIX)
#define EPSA 1e-8f
#define LNEPS 1e-5f
#define ATTN_SCALE 0.0625f
#define GSTEP (2.0f/31.0f)

// ---------------- scratch ----------------
__device__ __align__(16) float g_K [NROWS*D];
__device__ __align__(16) float g_V [NROWS*D];
__device__ __align__(16) float g_Pk[NROWS*H];
__device__ __align__(16) float g_Pv[NROWS*H];
__device__ __align__(16) float g_statsK[NROWS*4];
__device__ __align__(16) float g_statsV[NROWS*4];
__device__ float g_meanK[NROWS];
__device__ float g_meanV[NROWS];
__device__ float g_lnM[NROWS];
__device__ float g_lnIS[NROWS];
__device__ __align__(16) float g_U0[H];
__device__ __align__(16) float g_U1[H];
__device__ __align__(16) float g_Ub[H];
__device__ __align__(16) float g_C[H];
__device__ __align__(16) float g_G1[H];
__device__ float g_cov[16];
__device__ float g_Cond[NB*NS*260];
__device__ __align__(16) float g_slot[NB*NS*520]; // [0..511]=wtil, 512=qb2,513=px,514=py,515=i5x,516=i5y
__device__ float g_attn0[NB*NS*NPIX];
__device__ float g_part[NB*NS*64*8];   // per (slot, 16px-chunk) partials (5 used)
__device__ float g_spart[NB*NS*16*H];  // per (slot, 64px-chunk) partial s vectors

__device__ __forceinline__ float warpSum(float v) {
    #pragma unroll
    for (int o = 16; o; o >>= 1) v += __shfl_xor_sync(0xffffffffu, v, o);
    return v;
}

// ---------------- pre: constants + cond copy + LN row stats ----------------
__global__ __launch_bounds__(512) void pre_kernel(
    const float* __restrict__ gp_w, const float* __restrict__ gp_b,
    const float* __restrict__ lg,   const float* __restrict__ lb,
    const float* __restrict__ W1,   const float* __restrict__ b1,
    const float* __restrict__ cond, const float* __restrict__ inputs)
{
    int bid = blockIdx.x;
    if (bid >= 34) {
        int r = (bid - 34)*16 + (threadIdx.x>>5);
        int lane = threadIdx.x & 31;
        const float* row = inputs + (size_t)r*D;
        float v[8]; float s = 0.f;
        #pragma unroll
        for (int k=0;k<8;k++){ v[k]=row[k*32+lane]; s+=v[k]; }
        float m = warpSum(s) * (1.f/D);
        float q = 0.f;
        #pragma unroll
        for (int k=0;k<8;k++){ float d=v[k]-m; q += d*d; }
        float is = rsqrtf(warpSum(q)*(1.f/D) + LNEPS);
        if (lane == 0){ g_lnM[r]=m; g_lnIS[r]=is; }
        return;
    }
    if (bid > 0) {
        int i = (bid - 1)*512 + threadIdx.x;
        if (i < NB*NS*260) g_Cond[i] = cond[i];
        return;
    }
    __shared__ float sg0[D], sg1[D], sgb[D], slg[D], slb[D];
    __shared__ float sm[4];
    int t = threadIdx.x; // 512
    if (t < D) { sg0[t]=gp_w[t]; sg1[t]=gp_w[D+t]; sgb[t]=gp_b[t]; slg[t]=lg[t]; slb[t]=lb[t]; }
    __syncthreads();
    if (t == 0) {
        float m0=0,m1=0,mb=0;
        for (int d=0; d<D; d++){ m0+=sg0[d]; m1+=sg1[d]; mb+=sgb[d]; }
        m0*=(1.f/D); m1*=(1.f/D); mb*=(1.f/D);
        float V00=0,V11=0,Vbb=0,C01=0,C0b=0,C1b=0;
        for (int d=0; d<D; d++){
            float a=sg0[d]-m0, b_=sg1[d]-m1, c=sgb[d]-mb;
            V00+=a*a; V11+=b_*b_; Vbb+=c*c; C01+=a*b_; C0b+=a*c; C1b+=b_*c;
        }
        g_cov[0]=m0; g_cov[1]=m1; g_cov[2]=mb;
        g_cov[3]=V00/D; g_cov[4]=V11/D; g_cov[5]=Vbb/D;
        g_cov[6]=C01/D; g_cov[7]=C0b/D; g_cov[8]=C1b/D;
        float s2=0;
        for (int i=0;i<32;i++){ float x=-1.f + i*GSTEP; s2+=x*x; }
        g_cov[9]=s2*32.f;
        sm[0]=m0; sm[1]=m1; sm[2]=mb;
    }
    __syncthreads();
    float m0=sm[0], m1=sm[1], mb=sm[2];
    float U0=0,U1=0,Ub=0,Cc=0,G1=0;
    for (int d=0; d<D; d++){
        float w = W1[d*H + t];
        float gd = slg[d];
        U0 = fmaf((sg0[d]-m0)*gd, w, U0);
        U1 = fmaf((sg1[d]-m1)*gd, w, U1);
        Ub = fmaf((sgb[d]-mb)*gd, w, Ub);
        Cc = fmaf(slb[d], w, Cc);
        G1 = fmaf(gd, w, G1);
    }
    g_U0[t]=U0; g_U1[t]=U1; g_Ub[t]=Ub; g_C[t]=Cc + b1[t]; g_G1[t]=G1;
}

// ---------------- GEMM: 128x128 tile, 8x8 micro, smem double-buffer ----------------
__global__ __launch_bounds__(256,2) void gemm2(int modeBase, const float* __restrict__ A0,
                                               const float* __restrict__ B0,
                                               const float* __restrict__ B1,
                                               const float* __restrict__ sgv,
                                               const float* __restrict__ sbv, int N)
{
    int z = blockIdx.z;
    const float* A = (modeBase==0) ? A0 : (z==0 ? g_K : g_V);
    const float* Bm = z ? B1 : B0;
    float* Cm = (modeBase==0) ? (z ? g_V : g_K) : (z ? g_Pv : g_Pk);
    const float* meanV = (modeBase==0) ? nullptr : (z ? g_meanV : g_meanK);

    __shared__ float As[2][16][128];
    __shared__ float Bs[2][16][128];
    __shared__ float SG[256], SB[256];
    int bm = blockIdx.y*128, bn = blockIdx.x*128;
    int tid = threadIdx.x;
    int tx = tid & 15, ty = tid >> 4;
    int arr = tid >> 1, akk = (tid & 1) * 8;
    int bkk = tid >> 5, bcc = (tid & 31) * 4;
    float acc[8][8] = {};

    SG[tid] = sgv[tid];
    SB[tid] = sbv ? sbv[tid] : 0.f;
    float rm = 0.f, ris = 1.f;
    if (modeBase == 0){ rm = g_lnM[bm+arr]; ris = g_lnIS[bm+arr]; }
    __syncthreads();

    const float* apb = A + (size_t)(bm+arr)*256 + akk;
    const float* bpb = Bm + (size_t)bkk*N + bn + bcc;

    // prologue: load + scale + store tile 0 into buf 0
    {
        float4 a0 = *(const float4*)apb;
        float4 a1 = *(const float4*)(apb + 4);
        float4 b0 = *(const float4*)bpb;
        float4 b1 = *(const float4*)(bpb + (size_t)8*N);
        if (modeBase) {
            a0.x*=SG[akk+0]; a0.y*=SG[akk+1]; a0.z*=SG[akk+2]; a0.w*=SG[akk+3];
            a1.x*=SG[akk+4]; a1.y*=SG[akk+5]; a1.z*=SG[akk+6]; a1.w*=SG[akk+7];
        } else {
            a0.x = fmaf((a0.x-rm)*ris, SG[akk+0], SB[akk+0]);
            a0.y = fmaf((a0.y-rm)*ris, SG[akk+1], SB[akk+1]);
            a0.z = fmaf((a0.z-rm)*ris, SG[akk+2], SB[akk+2]);
            a0.w = fmaf((a0.w-rm)*ris, SG[akk+3], SB[akk+3]);
            a1.x = fmaf((a1.x-rm)*ris, SG[akk+4], SB[akk+4]);
            a1.y = fmaf((a1.y-rm)*ris, SG[akk+5], SB[akk+5]);
            a1.z = fmaf((a1.z-rm)*ris, SG[akk+6], SB[akk+6]);
            a1.w = fmaf((a1.w-rm)*ris, SG[akk+7], SB[akk+7]);
        }
        As[0][akk+0][arr]=a0.x; As[0][akk+1][arr]=a0.y; As[0][akk+2][arr]=a0.z; As[0][akk+3][arr]=a0.w;
        As[0][akk+4][arr]=a1.x; As[0][akk+5][arr]=a1.y; As[0][akk+6][arr]=a1.z; As[0][akk+7][arr]=a1.w;
        *(float4*)&Bs[0][bkk][bcc]   = b0;
        *(float4*)&Bs[0][bkk+8][bcc] = b1;
    }
    __syncthreads();

    int buf = 0;
    #pragma unroll 1
    for (int k0 = 0; k0 < 256; k0 += 16) {
        float4 na0, na1, nb0, nb1;
        if (k0 < 240){
            const float* ap = apb + k0 + 16;
            const float* bp = bpb + (size_t)(k0+16)*N;
            na0 = *(const float4*)ap;
            na1 = *(const float4*)(ap + 4);
            nb0 = *(const float4*)bp;
            nb1 = *(const float4*)(bp + (size_t)8*N);
        }
        #pragma unroll
        for (int kk = 0; kk < 16; kk++) {
            float ar[8], br[8];
            *(float4*)ar     = *(const float4*)&As[buf][kk][ty*8];
            *(float4*)(ar+4) = *(const float4*)&As[buf][kk][ty*8+4];
            *(float4*)br     = *(const float4*)&Bs[buf][kk][tx*8];
            *(float4*)(br+4) = *(const float4*)&Bs[buf][kk][tx*8+4];
            #pragma unroll
            for (int i=0;i<8;i++)
                #pragma unroll
                for (int j=0;j<8;j++) acc[i][j] = fmaf(ar[i], br[j], acc[i][j]);
        }
        if (k0 < 240){
            int kb = k0 + 16;
            if (modeBase) {
                na0.x*=SG[kb+akk+0]; na0.y*=SG[kb+akk+1]; na0.z*=SG[kb+akk+2]; na0.w*=SG[kb+akk+3];
                na1.x*=SG[kb+akk+4]; na1.y*=SG[kb+akk+5]; na1.z*=SG[kb+akk+6]; na1.w*=SG[kb+akk+7];
            } else {
                na0.x = fmaf((na0.x-rm)*ris, SG[kb+akk+0], SB[kb+akk+0]);
                na0.y = fmaf((na0.y-rm)*ris, SG[kb+akk+1], SB[kb+akk+1]);
                na0.z = fmaf((na0.z-rm)*ris, SG[kb+akk+2], SB[kb+akk+2]);
                na0.w = fmaf((na0.w-rm)*ris, SG[kb+akk+3], SB[kb+akk+3]);
                na1.x = fmaf((na1.x-rm)*ris, SG[kb+akk+4], SB[kb+akk+4]);
                na1.y = fmaf((na1.y-rm)*ris, SG[kb+akk+5], SB[kb+akk+5]);
                na1.z = fmaf((na1.z-rm)*ris, SG[kb+akk+6], SB[kb+akk+6]);
                na1.w = fmaf((na1.w-rm)*ris, SG[kb+akk+7], SB[kb+akk+7]);
            }
            int nb = buf ^ 1;
            As[nb][akk+0][arr]=na0.x; As[nb][akk+1][arr]=na0.y; As[nb][akk+2][arr]=na0.z; As[nb][akk+3][arr]=na0.w;
            As[nb][akk+4][arr]=na1.x; As[nb][akk+5][arr]=na1.y; As[nb][akk+6][arr]=na1.z; As[nb][akk+7][arr]=na1.w;
            *(float4*)&Bs[nb][bkk][bcc]   = nb0;
            *(float4*)&Bs[nb][bkk+8][bcc] = nb1;
            __syncthreads();
            buf = nb;
        }
    }
    #pragma unroll
    for (int i=0;i<8;i++){
        int r = bm + ty*8 + i;
        float mk = meanV ? meanV[r] : 0.f;
        int c0 = bn + tx*8;
        float vals[8];
        #pragma unroll
        for (int j=0;j<8;j++){
            float v = acc[i][j];
            if (modeBase) v = v - mk*g_G1[c0+j] + g_Ub[c0+j];
            vals[j] = v;
        }
        *(float4*)(Cm + (size_t)r*N + c0)     = *(float4*)vals;
        *(float4*)(Cm + (size_t)r*N + c0 + 4) = *(float4*)(vals+4);
    }
}

// ---------------- stats (warp-per-row) ----------------
__global__ __launch_bounds__(512) void stats2(const float* __restrict__ gp_w, const float* __restrict__ gp_b)
{
    int r = blockIdx.x*16 + (threadIdx.x>>5);
    int lane = threadIdx.x & 31;
    float m0=g_cov[0], m1=g_cov[1], mb=g_cov[2];
    float Vbb=g_cov[5], C0b=g_cov[7], C1b=g_cov[8];
    float g0[8], g1[8], gbv[8];
    #pragma unroll
    for (int k=0;k<8;k++){
        int d = k*32+lane;
        g0[k]=gp_w[d]-m0; g1[k]=gp_w[D+d]-m1; gbv[k]=gp_b[d]-mb;
    }
    #pragma unroll
    for (int br=0; br<2; br++){
        const float* src = br ? g_V : g_K;
        float sK=0,sK2=0,s0=0,s1=0,sb=0;
        #pragma unroll
        for (int k=0;k<8;k++){
            float x = src[(size_t)r*D + k*32 + lane];
            sK+=x; sK2=fmaf(x,x,sK2); s0=fmaf(x,g0[k],s0); s1=fmaf(x,g1[k],s1); sb=fmaf(x,gbv[k],sb);
        }
        sK=warpSum(sK); sK2=warpSum(sK2); s0=warpSum(s0); s1=warpSum(s1); sb=warpSum(sb);
        if (lane == 0){
            float mk = sK*(1.f/D);
            float Vkk = sK2*(1.f/D) - mk*mk;
            float Ck0 = s0*(1.f/D), Ck1 = s1*(1.f/D), Ckb = sb*(1.f/D);
            float* st = br ? (g_statsV + r*4) : (g_statsK + r*4);
            st[0] = Vkk + Vbb + 2.f*Ckb;
            st[1] = 2.f*(Ck0 + C0b);
            st[2] = 2.f*(Ck1 + C1b);
            st[3] = 0.f;
            if (br) g_meanV[r]=mk; else g_meanK[r]=mk;
        }
    }
}

// ---------------- per-slot q/wtil/scalars (1024 threads) ----------------
__device__ __forceinline__ void slot_compute(
    int s, int t, const float* so,
    const float* __restrict__ ns_g, const float* __restrict__ ns_b,
    const float* __restrict__ wq,   const float* __restrict__ W2, const float* __restrict__ b2,
    float* sh, float* sq, float* qpart, float* red)
{
    int w = t >> 5, lane = t & 31;
    float v = (t < 256) ? so[t] : 0.f;
    float ws = warpSum(v);
    if (lane == 0 && t < 256) red[w] = ws;
    __syncthreads();
    float m = 0.f;
    #pragma unroll
    for (int i=0;i<8;i++) m += red[i];
    m *= (1.f/D);
    float d = (t < 256) ? (v - m) : 0.f;
    ws = warpSum(d*d);
    __syncthreads();
    if (lane == 0 && t < 256) red[w] = ws;
    __syncthreads();
    float var = 0.f;
    #pragma unroll
    for (int i=0;i<8;i++) var += red[i];
    var *= (1.f/D);
    if (t < 256) sh[t] = d * rsqrtf(var + LNEPS) * ns_g[t] + ns_b[t];
    __syncthreads();
    int tt = t & 255, qr = t >> 8;
    float q = 0.f;
    #pragma unroll 4
    for (int dd = qr*64; dd < qr*64 + 64; dd++)
        q = fmaf(sh[dd], wq[dd*D + tt], q);
    qpart[t] = q;
    __syncthreads();
    if (t < 256) sq[t] = qpart[t] + qpart[256+t] + qpart[512+t] + qpart[768+t];
    __syncthreads();
    float p = (t < 256) ? sq[t]*b2[t] : 0.f;
    ws = warpSum(p);
    __syncthreads();
    if (lane == 0 && t < 256) red[w] = ws;
    __syncthreads();
    #pragma unroll 2
    for (int k = 0; k < 16; k++){
        int j = (k << 5) + w;
        const float* w2r = W2 + j*D;
        float acc = 0.f;
        #pragma unroll
        for (int dd=0; dd<8; dd++) acc = fmaf(w2r[dd*32+lane], sq[dd*32+lane], acc);
        acc = warpSum(acc);
        if (lane == 0) g_slot[s*520 + j] = acc;
    }
    if (t == 0){
        float qb2 = 0.f;
        #pragma unroll
        for (int i=0;i<8;i++) qb2 += red[i];
        float px = fminf(fmaxf(g_Cond[s*260+256], -1.f), 1.f);
        float py = fminf(fmaxf(g_Cond[s*260+257], -1.f), 1.f);
        float sx = fminf(fmaxf(g_Cond[s*260+258], 1e-3f), 2.f);
        float sy = fminf(fmaxf(g_Cond[s*260+259], 1e-3f), 2.f);
        float* o = g_slot + s*520 + 512;
        o[0]=qb2; o[1]=px; o[2]=py; o[3]=1.f/(5.f*sx); o[4]=1.f/(5.f*sy);
    }
}

__global__ __launch_bounds__(1024) void slot0(const float* __restrict__ ns_g, const float* __restrict__ ns_b,
                                              const float* __restrict__ wq,   const float* __restrict__ W2,
                                              const float* __restrict__ b2)
{
    __shared__ float so[256], sh[256], sq[256], qpart[1024], red[16];
    int s = blockIdx.x, t = threadIdx.x;
    if (t < 256) so[t] = g_Cond[s*260 + t];
    __syncthreads();
    slot_compute(s, t, so, ns_g, ns_b, wq, W2, b2, sh, sq, qpart, red);
}

// ---------------- fused: dots + softmax + attn0 + partials (16 px/CTA, smem-staged Pk) ----------------
__global__ __launch_bounds__(256) void iter1_kernel(int last, float* __restrict__ out)
{
    int b = blockIdx.y, chunk = blockIdx.x;   // 64 chunks of 16 px
    int t = threadIdx.x, w = t >> 5, lane = t & 31;
    __shared__ float sPk[16*512];             // 32 KB
    __shared__ float sdots[NS][16];
    __shared__ float sscal[NS][5];

    float* attnDst = last ? (out + 16640) : g_attn0;
    float* relOut  = out + 16640 + 65536;
    int n0 = chunk*16;

    // stage Pk tile: 16 px x 512 floats, coalesced
    {
        const float4* src = (const float4*)(g_Pk + (((size_t)(b<<10) + n0)<<9));
        float4* dst = (float4*)sPk;
        #pragma unroll
        for (int i=0;i<8;i++) dst[t + i*256] = __ldg(src + t + i*256);
    }

    float4 u0v[4], u1v[4], wtv[4], cv[4];
    const float* wts = g_slot + (b*NS + w)*520;
    #pragma unroll
    for (int jj=0; jj<4; jj++){
        int j = jj*128 + lane*4;
        u0v[jj] = *(const float4*)(g_U0 + j);
        u1v[jj] = *(const float4*)(g_U1 + j);
        cv[jj]  = *(const float4*)(g_C  + j);
        wtv[jj] = *(const float4*)(wts  + j);
    }
    if (t < 40) sscal[t/5][t%5] = g_slot[(b*NS + t/5)*520 + 512 + (t%5)];
    __syncthreads();

    float qb2=sscal[w][0], px=sscal[w][1], py=sscal[w][2], i5x=sscal[w][3], i5y=sscal[w][4];
    float V00=g_cov[3], V11=g_cov[4], C01_2=2.f*g_cov[6];

    for (int pp=0; pp<16; pp++){
        int n = n0 + pp;
        float gx = -1.f + (float)(n>>5)*GSTEP;
        float gy = -1.f + (float)(n&31)*GSTEP;
        float a = (gx-px)*i5x, c = (gy-py)*i5y;
        const float4 st = *(const float4*)(g_statsK + ((b<<10)+n)*4);
        float var = st.x + a*st.y + c*st.z + a*a*V00 + c*c*V11 + a*c*C01_2;
        float isig = rsqrtf(var + LNEPS);
        const float* pk = sPk + pp*512;
        float ac0=0.f, ac1=0.f;
        #pragma unroll
        for (int jj=0; jj<4; jj++){
            float4 p4 = *(const float4*)(pk + jj*128 + lane*4);
            float e0 = fmaf(isig, fmaf(c,u1v[jj].x, fmaf(a,u0v[jj].x, p4.x)), cv[jj].x);
            float e1 = fmaf(isig, fmaf(c,u1v[jj].y, fmaf(a,u0v[jj].y, p4.y)), cv[jj].y);
            float e2 = fmaf(isig, fmaf(c,u1v[jj].z, fmaf(a,u0v[jj].z, p4.z)), cv[jj].z);
            float e3 = fmaf(isig, fmaf(c,u1v[jj].w, fmaf(a,u0v[jj].w, p4.w)), cv[jj].w);
            ac0 = fmaf(fmaxf(e0,0.f), wtv[jj].x, ac0);
            ac1 = fmaf(fmaxf(e1,0.f), wtv[jj].y, ac1);
            ac0 = fmaf(fmaxf(e2,0.f), wtv[jj].z, ac0);
            ac1 = fmaf(fmaxf(e3,0.f), wtv[jj].w, ac1);
        }
        float acc = warpSum(ac0 + ac1);
        if (lane == 0){
            sdots[w][pp] = ATTN_SCALE * (acc + qb2);
            if (last){
                float2* rp = (float2*)(relOut + ((((size_t)(b*NS+w)<<10)+n)<<1));
                *rp = make_float2(a, c);
            }
        }
    }
    __syncthreads();

    float a0 = 0.f, gx = 0.f, gy = 0.f;
    if (lane < 16){
        int n = n0 + lane;
        float dd[NS]; float mx = -1e30f;
        #pragma unroll
        for (int k=0;k<NS;k++){ dd[k] = sdots[k][lane]; mx = fmaxf(mx, dd[k]); }
        float sum = 0.f;
        #pragma unroll
        for (int k=0;k<NS;k++){ dd[k] = expf(dd[k]-mx); sum += dd[k]; }
        a0 = dd[w] / sum;
        attnDst[((b*NS+w)<<10) + n] = a0;
        gx = -1.f + (float)(n>>5)*GSTEP;
        gy = -1.f + (float)(n&31)*GSTEP;
    }
    float S0 = warpSum(a0);
    float Sx = warpSum(a0*gx);
    float Sy = warpSum(a0*gy);
    float Sxx = warpSum(a0*gx*gx);
    float Syy = warpSum(a0*gy*gy);
    if (lane == 0){
        float* pp = g_part + ((size_t)((b*NS+w)*64 + chunk))*8;
        pp[0]=S0; pp[1]=Sx; pp[2]=Sy; pp[3]=Sxx; pp[4]=Syy;
    }
}

// ---------------- slot-fused vacc + finalize (64 px/CTA, all 8 slots) ----------------
__global__ __launch_bounds__(512) void vaccF_kernel()
{
    int chunk = blockIdx.x;    // 0..15 (64 px each)
    int b = blockIdx.y;        // 0..7
    int t = threadIdx.x;
    __shared__ float4 sC4[NS][64];   // (is, is*a, is*c, w)
    __shared__ float sden[NS];

    int sl = t >> 6, p = t & 63;
    int n = chunk*64 + p;
    int gs = b*NS + sl;
    float rawA;
    {
        float px = g_slot[gs*520+513], py = g_slot[gs*520+514];
        float i5x= g_slot[gs*520+515], i5y= g_slot[gs*520+516];
        float gx = -1.f + (float)(n>>5)*GSTEP;
        float gy = -1.f + (float)(n&31)*GSTEP;
        float a = (gx-px)*i5x, c = (gy-py)*i5y;
        const float4 st = *(const float4*)(g_statsV + ((b<<10)+n)*4);
        float var = st.x + a*st.y + c*st.z + a*a*g_cov[3] + c*c*g_cov[4] + a*c*2.f*g_cov[6];
        float is = rsqrtf(var + LNEPS);
        rawA = g_attn0[(gs<<10)+n];
        sC4[sl][p] = make_float4(is, is*a, is*c, 0.f);
    }
    if (t < 256){
        int w = t >> 5, lane = t & 31;
        const float* pp0 = g_part + ((size_t)((b*NS+w)*64 + lane))*8;
        const float* pp1 = pp0 + 32*8;
        float S0 = warpSum(pp0[0] + pp1[0]);
        if (chunk == 0){
            float Sx = warpSum(pp0[1] + pp1[1]);
            float Sy = warpSum(pp0[2] + pp1[2]);
            float Sxx = warpSum(pp0[3] + pp1[3]);
            float Syy = warpSum(pp0[4] + pp1[4]);
            if (lane == 0){
                float px = Sx, py = Sy, G2 = g_cov[9];
                float vx = Sxx - 2.f*px*Sx + px*px*S0 + EPSA*(G2 + 1024.f*px*px);
                float vy = Syy - 2.f*py*Sy + py*py*S0 + EPSA*(G2 + 1024.f*py*py);
                float sx = fminf(fmaxf(sqrtf(fmaxf(vx,0.f)), 1e-3f), 2.f);
                float sy = fminf(fmaxf(sqrtf(fmaxf(vy,0.f)), 1e-3f), 2.f);
                int s2 = b*NS + w;
                g_Cond[s2*260+256]=px; g_Cond[s2*260+257]=py;
                g_Cond[s2*260+258]=sx; g_Cond[s2*260+259]=sy;
            }
        }
        if (lane == 0) sden[w] = 1.f/(S0 + 1024.f*EPSA);
    }
    __syncthreads();
    sC4[sl][p].w = (rawA + EPSA) * sden[sl];
    __syncthreads();

    float u0 = g_U0[t], u1 = g_U1[t], C = g_C[t];
    const float* pvb = g_Pv + ((((size_t)(b<<10)) + (size_t)chunk*64) << 9) + t;
    float acc[NS] = {};
    #pragma unroll 4
    for (int q=0; q<64; q++){
        float pv = __ldg(pvb + ((size_t)q << 9));
        #pragma unroll
        for (int s2=0; s2<NS; s2++){
            float4 cf = sC4[s2][q];
            float pre = fmaf(cf.y, u0, fmaf(cf.z, u1, fmaf(cf.x, pv, C)));
            acc[s2] = fmaf(fmaxf(pre, 0.f), cf.w, acc[s2]);
        }
    }
    #pragma unroll
    for (int s2=0; s2<NS; s2++)
        g_spart[((size_t)((b*NS+s2)*16 + chunk))*H + t] = acc[s2];
}

// ---------------- GRU update + slot prep for next iter (1024 threads) ----------------
__global__ __launch_bounds__(1024) void updslot_kernel(
    const float* __restrict__ W2,  const float* __restrict__ b2,
    const float* __restrict__ Wih, const float* __restrict__ Whh,
    const float* __restrict__ bih, const float* __restrict__ bhh,
    const float* __restrict__ ns_g, const float* __restrict__ ns_b,
    const float* __restrict__ wq)
{
    __shared__ float ss[H], so[256], su[256], qpart[1024], sgx[768], sgh[768], sh[256], sq[256], red[16];
    int s = blockIdx.x, t = threadIdx.x, w = t >> 5, lane = t & 31;

    if (t < 512){
        float r0 = 0.f;
        #pragma unroll
        for (int c=0; c<16; c++) r0 += g_spart[((size_t)(s*16 + c))*H + t];
        ss[t] = r0;
    }
    if (t < 256) so[t] = g_Cond[s*260 + t];
    __syncthreads();

    int tt = t & 255, qr = t >> 8;
    float u = 0.f;
    #pragma unroll 4
    for (int j = qr*128; j < qr*128 + 128; j++)
        u = fmaf(ss[j], W2[j*D + tt], u);
    qpart[t] = u;
    __syncthreads();
    if (t < 256) su[t] = qpart[t] + qpart[256+t] + qpart[512+t] + qpart[768+t] + b2[t];
    __syncthreads();

    #pragma unroll 2
    for (int k = 0; k < 24; k++){
        int i = (k << 5) + w;
        const float* wi = Wih + i*D;
        const float* wh = Whh + i*D;
        float ax = 0.f, ah = 0.f;
        #pragma unroll
        for (int dd=0; dd<8; dd++){
            int dx = dd*32 + lane;
            ax = fmaf(wi[dx], su[dx], ax);
            ah = fmaf(wh[dx], so[dx], ah);
        }
        ax = warpSum(ax); ah = warpSum(ah);
        if (lane == 0){ sgx[i] = ax + bih[i]; sgh[i] = ah + bhh[i]; }
    }
    __syncthreads();

    if (t < 256){
        float r = 1.f/(1.f + expf(-(sgx[t]     + sgh[t])));
        float z = 1.f/(1.f + expf(-(sgx[256+t] + sgh[256+t])));
        float nn = tanhf(sgx[512+t] + r*sgh[512+t]);
        float nv = (1.f - z)*nn + z*so[t];
        g_Cond[s*260 + t] = nv;
        so[t] = nv;
    }
    __syncthreads();

    slot_compute(s, t, so, ns_g, ns_b, wq, W2, b2, sh, sq, qpart, red);
}

// ---------------- final: pos/scl + write conditioning to out ----------------
__global__ void finz3_kernel(float* __restrict__ out)
{
    __shared__ float sres[4];
    int s = blockIdx.x, t = threadIdx.x;
    if (t < 32){
        const float* pp0 = g_part + ((size_t)(s*64 + t))*8;
        const float* pp1 = pp0 + 32*8;
        float S0 = warpSum(pp0[0] + pp1[0]);
        float Sx = warpSum(pp0[1] + pp1[1]);
        float Sy = warpSum(pp0[2] + pp1[2]);
        float Sxx = warpSum(pp0[3] + pp1[3]);
        float Syy = warpSum(pp0[4] + pp1[4]);
        if (t == 0){
            float px = Sx, py = Sy, G2 = g_cov[9];
            float vx = Sxx - 2.f*px*Sx + px*px*S0 + EPSA*(G2 + 1024.f*px*px);
            float vy = Syy - 2.f*py*Sy + py*py*S0 + EPSA*(G2 + 1024.f*py*py);
            float sx = fminf(fmaxf(sqrtf(fmaxf(vx,0.f)), 1e-3f), 2.f);
            float sy = fminf(fmaxf(sqrtf(fmaxf(vy,0.f)), 1e-3f), 2.f);
            sres[0]=px; sres[1]=py; sres[2]=sx; sres[3]=sy;
        }
    }
    __syncthreads();
    for (int i = t; i < 260; i += 256)
        out[s*260 + i] = (i < 256) ? g_Cond[s*260 + i] : sres[i - 256];
}

// ---------------- launch ----------------
extern "C" void kernel_launch(void* const* d_in, const int* in_sizes, int n_in,
                              void* d_out, int out_size)
{
    const float* inputs = (const float*)d_in[0];
    const float* cond   = (const float*)d_in[1];
    const float* ni_g   = (const float*)d_in[2];
    const float* ni_b   = (const float*)d_in[3];
    const float* ns_g   = (const float*)d_in[4];
    const float* ns_b   = (const float*)d_in[5];
    const float* wq     = (const float*)d_in[6];
    const float* wk     = (const float*)d_in[7];
    const float* wv     = (const float*)d_in[8];
    const float* gp_w   = (const float*)d_in[9];
    const float* gp_b   = (const float*)d_in[10];
    const float* ge_ln_g= (const float*)d_in[11];
    const float* ge_ln_b= (const float*)d_in[12];
    const float* ge_w1  = (const float*)d_in[13];
    const float* ge_b1  = (const float*)d_in[14];
    const float* ge_w2  = (const float*)d_in[15];
    const float* ge_b2  = (const float*)d_in[16];
    const float* gru_wih= (const float*)d_in[17];
    const float* gru_whh= (const float*)d_in[18];
    const float* gru_bih= (const float*)d_in[19];
    const float* gru_bhh= (const float*)d_in[20];
    float* out = (float*)d_out;

    pre_kernel<<<546, 512>>>(gp_w, gp_b, ge_ln_g, ge_ln_b, ge_w1, ge_b1, cond, inputs);
    gemm2<<<dim3(2,64,2), 256>>>(0, inputs, wk, wv, ni_g, ni_b, 256);
    stats2<<<512, 512>>>(gp_w, gp_b);
    gemm2<<<dim3(4,64,2), 256>>>(2, nullptr, ge_w1, ge_w1, ge_ln_g, nullptr, 512);
    slot0<<<64, 1024>>>(ns_g, ns_b, wq, ge_w2, ge_b2);

    for (int it = 0; it < 3; it++) {
        iter1_kernel<<<dim3(64,8), 256>>>(0, out);
        vaccF_kernel<<<dim3(16,8), 512>>>();
        updslot_kernel<<<64, 1024>>>(ge_w2, ge_b2, gru_wih, gru_whh, gru_bih, gru_bhh,
                                     ns_g, ns_b, wq);
    }
    iter1_kernel<<<dim3(64,8), 256>>>(1, out);
    finz3_kernel<<<64, 256>>>(out);
}

// round 7
// speedup vs baseline: 3.6062x; 1.0192x over previous
#include <cuda_runtime.h>
#include <math.h>

// ---------------- problem constants ----------------
#define NB 8
#define NPIX 1024
#define NS 8
#define D 256
#define H 512
#define NROWS (NB*NPIX)
#define EPSA 1e-8f
#define LNEPS 1e-5f
#define ATTN_SCALE 0.0625f
#define GSTEP (2.0f/31.0f)

// ---------------- scratch ----------------
__device__ __align__(16) float g_K [NROWS*D];
__device__ __align__(16) float g_V [NROWS*D];
__device__ __align__(16) float g_Pk[NROWS*H];
__device__ __align__(16) float g_Pv[NROWS*H];
__device__ __align__(16) float g_statsK[NROWS*4];
__device__ __align__(16) float g_statsV[NROWS*4];
__device__ float g_meanK[NROWS];
__device__ float g_meanV[NROWS];
__device__ float g_lnM[NROWS];
__device__ float g_lnIS[NROWS];
__device__ __align__(16) float g_U0[H];
__device__ __align__(16) float g_U1[H];
__device__ __align__(16) float g_Ub[H];
__device__ __align__(16) float g_C[H];
__device__ __align__(16) float g_G1[H];
__device__ float g_cov[16];
__device__ float g_Cond[NB*NS*260];
__device__ __align__(16) float g_slot[NB*NS*520]; // [0..511]=wtil, 512=qb2,513=px,514=py,515=i5x,516=i5y
__device__ float g_attn0[NB*NS*NPIX];
__device__ float g_part[NB*NS*64*8];   // per (slot, 16px-chunk) partials (5 used)
__device__ float g_spart[NB*NS*16*H];  // per (slot, 64px-chunk) partial s vectors

__device__ __forceinline__ float warpSum(float v) {
    #pragma unroll
    for (int o = 16; o; o >>= 1) v += __shfl_xor_sync(0xffffffffu, v, o);
    return v;
}

// ---------------- pre: constants + cond copy + LN row stats ----------------
__global__ __launch_bounds__(512) void pre_kernel(
    const float* __restrict__ gp_w, const float* __restrict__ gp_b,
    const float* __restrict__ lg,   const float* __restrict__ lb,
    const float* __restrict__ W1,   const float* __restrict__ b1,
    const float* __restrict__ cond, const float* __restrict__ inputs)
{
    int bid = blockIdx.x;
    if (bid >= 34) {
        int r = (bid - 34)*16 + (threadIdx.x>>5);
        int lane = threadIdx.x & 31;
        const float* row = inputs + (size_t)r*D;
        float v[8]; float s = 0.f;
        #pragma unroll
        for (int k=0;k<8;k++){ v[k]=row[k*32+lane]; s+=v[k]; }
        float m = warpSum(s) * (1.f/D);
        float q = 0.f;
        #pragma unroll
        for (int k=0;k<8;k++){ float d=v[k]-m; q += d*d; }
        float is = rsqrtf(warpSum(q)*(1.f/D) + LNEPS);
        if (lane == 0){ g_lnM[r]=m; g_lnIS[r]=is; }
        return;
    }
    if (bid > 0) {
        int i = (bid - 1)*512 + threadIdx.x;
        if (i < NB*NS*260) g_Cond[i] = cond[i];
        return;
    }
    __shared__ float sg0[D], sg1[D], sgb[D], slg[D], slb[D];
    __shared__ float sm[4];
    int t = threadIdx.x; // 512
    if (t < D) { sg0[t]=gp_w[t]; sg1[t]=gp_w[D+t]; sgb[t]=gp_b[t]; slg[t]=lg[t]; slb[t]=lb[t]; }
    __syncthreads();
    if (t == 0) {
        float m0=0,m1=0,mb=0;
        for (int d=0; d<D; d++){ m0+=sg0[d]; m1+=sg1[d]; mb+=sgb[d]; }
        m0*=(1.f/D); m1*=(1.f/D); mb*=(1.f/D);
        float V00=0,V11=0,Vbb=0,C01=0,C0b=0,C1b=0;
        for (int d=0; d<D; d++){
            float a=sg0[d]-m0, b_=sg1[d]-m1, c=sgb[d]-mb;
            V00+=a*a; V11+=b_*b_; Vbb+=c*c; C01+=a*b_; C0b+=a*c; C1b+=b_*c;
        }
        g_cov[0]=m0; g_cov[1]=m1; g_cov[2]=mb;
        g_cov[3]=V00/D; g_cov[4]=V11/D; g_cov[5]=Vbb/D;
        g_cov[6]=C01/D; g_cov[7]=C0b/D; g_cov[8]=C1b/D;
        float s2=0;
        for (int i=0;i<32;i++){ float x=-1.f + i*GSTEP; s2+=x*x; }
        g_cov[9]=s2*32.f;
        sm[0]=m0; sm[1]=m1; sm[2]=mb;
    }
    __syncthreads();
    float m0=sm[0], m1=sm[1], mb=sm[2];
    float U0=0,U1=0,Ub=0,Cc=0,G1=0;
    for (int d=0; d<D; d++){
        float w = W1[d*H + t];
        float gd = slg[d];
        U0 = fmaf((sg0[d]-m0)*gd, w, U0);
        U1 = fmaf((sg1[d]-m1)*gd, w, U1);
        Ub = fmaf((sgb[d]-mb)*gd, w, Ub);
        Cc = fmaf(slb[d], w, Cc);
        G1 = fmaf(gd, w, G1);
    }
    g_U0[t]=U0; g_U1[t]=U1; g_Ub[t]=Ub; g_C[t]=Cc + b1[t]; g_G1[t]=G1;
}

// ---------------- GEMM: 128x128 tile, 8x8 micro, smem double-buffer, 8x4 lane map ----------------
__global__ __launch_bounds__(256,2) void gemm2(int modeBase, const float* __restrict__ A0,
                                               const float* __restrict__ B0,
                                               const float* __restrict__ B1,
                                               const float* __restrict__ sgv,
                                               const float* __restrict__ sbv, int N)
{
    int z = blockIdx.z;
    const float* A = (modeBase==0) ? A0 : (z==0 ? g_K : g_V);
    const float* Bm = z ? B1 : B0;
    float* Cm = (modeBase==0) ? (z ? g_V : g_K) : (z ? g_Pv : g_Pk);
    const float* meanV = (modeBase==0) ? nullptr : (z ? g_meanV : g_meanK);

    __shared__ float As[2][16][128];
    __shared__ float Bs[2][16][128];
    __shared__ float SG[256], SB[256];
    int bm = blockIdx.y*128, bn = blockIdx.x*128;
    int tid = threadIdx.x;
    int lane = tid & 31, wrp = tid >> 5;
    // 8 tx x 4 ty per warp: fewer LDS wavefronts (B spans 256B, A spans 128B)
    int tx = ((wrp & 1) << 3) | (lane & 7);    // 0..15
    int ty = ((wrp >> 1) << 2) | (lane >> 3);  // 0..15
    int arr = tid >> 1, akk = (tid & 1) * 8;
    int bkk = tid >> 5, bcc = (tid & 31) * 4;
    float acc[8][8] = {};

    SG[tid] = sgv[tid];
    SB[tid] = sbv ? sbv[tid] : 0.f;
    float rm = 0.f, ris = 1.f;
    if (modeBase == 0){ rm = g_lnM[bm+arr]; ris = g_lnIS[bm+arr]; }
    __syncthreads();

    const float* apb = A + (size_t)(bm+arr)*256 + akk;
    const float* bpb = Bm + (size_t)bkk*N + bn + bcc;

    // prologue: tile 0 -> buf 0
    {
        float4 a0 = *(const float4*)apb;
        float4 a1 = *(const float4*)(apb + 4);
        float4 b0 = *(const float4*)bpb;
        float4 b1 = *(const float4*)(bpb + (size_t)8*N);
        if (modeBase) {
            a0.x*=SG[akk+0]; a0.y*=SG[akk+1]; a0.z*=SG[akk+2]; a0.w*=SG[akk+3];
            a1.x*=SG[akk+4]; a1.y*=SG[akk+5]; a1.z*=SG[akk+6]; a1.w*=SG[akk+7];
        } else {
            a0.x = fmaf((a0.x-rm)*ris, SG[akk+0], SB[akk+0]);
            a0.y = fmaf((a0.y-rm)*ris, SG[akk+1], SB[akk+1]);
            a0.z = fmaf((a0.z-rm)*ris, SG[akk+2], SB[akk+2]);
            a0.w = fmaf((a0.w-rm)*ris, SG[akk+3], SB[akk+3]);
            a1.x = fmaf((a1.x-rm)*ris, SG[akk+4], SB[akk+4]);
            a1.y = fmaf((a1.y-rm)*ris, SG[akk+5], SB[akk+5]);
            a1.z = fmaf((a1.z-rm)*ris, SG[akk+6], SB[akk+6]);
            a1.w = fmaf((a1.w-rm)*ris, SG[akk+7], SB[akk+7]);
        }
        As[0][akk+0][arr]=a0.x; As[0][akk+1][arr]=a0.y; As[0][akk+2][arr]=a0.z; As[0][akk+3][arr]=a0.w;
        As[0][akk+4][arr]=a1.x; As[0][akk+5][arr]=a1.y; As[0][akk+6][arr]=a1.z; As[0][akk+7][arr]=a1.w;
        *(float4*)&Bs[0][bkk][bcc]   = b0;
        *(float4*)&Bs[0][bkk+8][bcc] = b1;
    }
    __syncthreads();

    int buf = 0;
    #pragma unroll 1
    for (int k0 = 0; k0 < 256; k0 += 16) {
        float4 na0, na1, nb0, nb1;
        if (k0 < 240){
            const float* ap = apb + k0 + 16;
            const float* bp = bpb + (size_t)(k0+16)*N;
            na0 = *(const float4*)ap;
            na1 = *(const float4*)(ap + 4);
            nb0 = *(const float4*)bp;
            nb1 = *(const float4*)(bp + (size_t)8*N);
        }
        #pragma unroll
        for (int kk = 0; kk < 16; kk++) {
            float ar[8], br[8];
            *(float4*)ar     = *(const float4*)&As[buf][kk][ty*8];
            *(float4*)(ar+4) = *(const float4*)&As[buf][kk][ty*8+4];
            *(float4*)br     = *(const float4*)&Bs[buf][kk][tx*8];
            *(float4*)(br+4) = *(const float4*)&Bs[buf][kk][tx*8+4];
            #pragma unroll
            for (int i=0;i<8;i++)
                #pragma unroll
                for (int j=0;j<8;j++) acc[i][j] = fmaf(ar[i], br[j], acc[i][j]);
        }
        if (k0 < 240){
            int kb = k0 + 16;
            if (modeBase) {
                na0.x*=SG[kb+akk+0]; na0.y*=SG[kb+akk+1]; na0.z*=SG[kb+akk+2]; na0.w*=SG[kb+akk+3];
                na1.x*=SG[kb+akk+4]; na1.y*=SG[kb+akk+5]; na1.z*=SG[kb+akk+6]; na1.w*=SG[kb+akk+7];
            } else {
                na0.x = fmaf((na0.x-rm)*ris, SG[kb+akk+0], SB[kb+akk+0]);
                na0.y = fmaf((na0.y-rm)*ris, SG[kb+akk+1], SB[kb+akk+1]);
                na0.z = fmaf((na0.z-rm)*ris, SG[kb+akk+2], SB[kb+akk+2]);
                na0.w = fmaf((na0.w-rm)*ris, SG[kb+akk+3], SB[kb+akk+3]);
                na1.x = fmaf((na1.x-rm)*ris, SG[kb+akk+4], SB[kb+akk+4]);
                na1.y = fmaf((na1.y-rm)*ris, SG[kb+akk+5], SB[kb+akk+5]);
                na1.z = fmaf((na1.z-rm)*ris, SG[kb+akk+6], SB[kb+akk+6]);
                na1.w = fmaf((na1.w-rm)*ris, SG[kb+akk+7], SB[kb+akk+7]);
            }
            int nb = buf ^ 1;
            As[nb][akk+0][arr]=na0.x; As[nb][akk+1][arr]=na0.y; As[nb][akk+2][arr]=na0.z; As[nb][akk+3][arr]=na0.w;
            As[nb][akk+4][arr]=na1.x; As[nb][akk+5][arr]=na1.y; As[nb][akk+6][arr]=na1.z; As[nb][akk+7][arr]=na1.w;
            *(float4*)&Bs[nb][bkk][bcc]   = nb0;
            *(float4*)&Bs[nb][bkk+8][bcc] = nb1;
            __syncthreads();
            buf = nb;
        }
    }
    #pragma unroll
    for (int i=0;i<8;i++){
        int r = bm + ty*8 + i;
        float mk = meanV ? meanV[r] : 0.f;
        int c0 = bn + tx*8;
        float vals[8];
        #pragma unroll
        for (int j=0;j<8;j++){
            float v = acc[i][j];
            if (modeBase) v = v - mk*g_G1[c0+j] + g_Ub[c0+j];
            vals[j] = v;
        }
        *(float4*)(Cm + (size_t)r*N + c0)     = *(float4*)vals;
        *(float4*)(Cm + (size_t)r*N + c0 + 4) = *(float4*)(vals+4);
    }
}

// ---------------- stats (warp-per-row) ----------------
__global__ __launch_bounds__(512) void stats2(const float* __restrict__ gp_w, const float* __restrict__ gp_b)
{
    int r = blockIdx.x*16 + (threadIdx.x>>5);
    int lane = threadIdx.x & 31;
    float m0=g_cov[0], m1=g_cov[1], mb=g_cov[2];
    float Vbb=g_cov[5], C0b=g_cov[7], C1b=g_cov[8];
    float g0[8], g1[8], gbv[8];
    #pragma unroll
    for (int k=0;k<8;k++){
        int d = k*32+lane;
        g0[k]=gp_w[d]-m0; g1[k]=gp_w[D+d]-m1; gbv[k]=gp_b[d]-mb;
    }
    #pragma unroll
    for (int br=0; br<2; br++){
        const float* src = br ? g_V : g_K;
        float sK=0,sK2=0,s0=0,s1=0,sb=0;
        #pragma unroll
        for (int k=0;k<8;k++){
            float x = src[(size_t)r*D + k*32 + lane];
            sK+=x; sK2=fmaf(x,x,sK2); s0=fmaf(x,g0[k],s0); s1=fmaf(x,g1[k],s1); sb=fmaf(x,gbv[k],sb);
        }
        sK=warpSum(sK); sK2=warpSum(sK2); s0=warpSum(s0); s1=warpSum(s1); sb=warpSum(sb);
        if (lane == 0){
            float mk = sK*(1.f/D);
            float Vkk = sK2*(1.f/D) - mk*mk;
            float Ck0 = s0*(1.f/D), Ck1 = s1*(1.f/D), Ckb = sb*(1.f/D);
            float* st = br ? (g_statsV + r*4) : (g_statsK + r*4);
            st[0] = Vkk + Vbb + 2.f*Ckb;
            st[1] = 2.f*(Ck0 + C0b);
            st[2] = 2.f*(Ck1 + C1b);
            st[3] = 0.f;
            if (br) g_meanV[r]=mk; else g_meanK[r]=mk;
        }
    }
}

// ---------------- per-slot q/wtil/scalars (1024 threads) ----------------
__device__ __forceinline__ void slot_compute(
    int s, int t, const float* so,
    const float* __restrict__ ns_g, const float* __restrict__ ns_b,
    const float* __restrict__ wq,   const float* __restrict__ W2, const float* __restrict__ b2,
    float* sh, float* sq, float* qpart, float* red)
{
    int w = t >> 5, lane = t & 31;
    float v = (t < 256) ? so[t] : 0.f;
    float ws = warpSum(v);
    if (lane == 0 && t < 256) red[w] = ws;
    __syncthreads();
    float m = 0.f;
    #pragma unroll
    for (int i=0;i<8;i++) m += red[i];
    m *= (1.f/D);
    float d = (t < 256) ? (v - m) : 0.f;
    ws = warpSum(d*d);
    __syncthreads();
    if (lane == 0 && t < 256) red[w] = ws;
    __syncthreads();
    float var = 0.f;
    #pragma unroll
    for (int i=0;i<8;i++) var += red[i];
    var *= (1.f/D);
    if (t < 256) sh[t] = d * rsqrtf(var + LNEPS) * ns_g[t] + ns_b[t];
    __syncthreads();
    int tt = t & 255, qr = t >> 8;
    float q = 0.f;
    #pragma unroll 4
    for (int dd = qr*64; dd < qr*64 + 64; dd++)
        q = fmaf(sh[dd], wq[dd*D + tt], q);
    qpart[t] = q;
    __syncthreads();
    if (t < 256) sq[t] = qpart[t] + qpart[256+t] + qpart[512+t] + qpart[768+t];
    __syncthreads();
    float p = (t < 256) ? sq[t]*b2[t] : 0.f;
    ws = warpSum(p);
    __syncthreads();
    if (lane == 0 && t < 256) red[w] = ws;
    __syncthreads();
    // wtil = W2 @ q : warp-per-row, 2 rows per iter for shuffle ILP
    #pragma unroll
    for (int k = 0; k < 8; k++){
        int j0 = (k << 6) + w;
        int j1 = j0 + 32;
        const float* w2a = W2 + j0*D;
        const float* w2b = W2 + j1*D;
        float acc0 = 0.f, acc1 = 0.f;
        #pragma unroll
        for (int dd=0; dd<8; dd++){
            float qv = sq[dd*32+lane];
            acc0 = fmaf(w2a[dd*32+lane], qv, acc0);
            acc1 = fmaf(w2b[dd*32+lane], qv, acc1);
        }
        acc0 = warpSum(acc0); acc1 = warpSum(acc1);
        if (lane == 0){ g_slot[s*520 + j0] = acc0; g_slot[s*520 + j1] = acc1; }
    }
    if (t == 0){
        float qb2 = 0.f;
        #pragma unroll
        for (int i=0;i<8;i++) qb2 += red[i];
        float px = fminf(fmaxf(g_Cond[s*260+256], -1.f), 1.f);
        float py = fminf(fmaxf(g_Cond[s*260+257], -1.f), 1.f);
        float sx = fminf(fmaxf(g_Cond[s*260+258], 1e-3f), 2.f);
        float sy = fminf(fmaxf(g_Cond[s*260+259], 1e-3f), 2.f);
        float* o = g_slot + s*520 + 512;
        o[0]=qb2; o[1]=px; o[2]=py; o[3]=1.f/(5.f*sx); o[4]=1.f/(5.f*sy);
    }
}

__global__ __launch_bounds__(1024) void slot0(const float* __restrict__ ns_g, const float* __restrict__ ns_b,
                                              const float* __restrict__ wq,   const float* __restrict__ W2,
                                              const float* __restrict__ b2)
{
    __shared__ float so[256], sh[256], sq[256], qpart[1024], red[16];
    int s = blockIdx.x, t = threadIdx.x;
    if (t < 256) so[t] = g_Cond[s*260 + t];
    __syncthreads();
    slot_compute(s, t, so, ns_g, ns_b, wq, W2, b2, sh, sq, qpart, red);
}

// ---------------- fused: dots + softmax + attn0 + partials (16 px/CTA, smem-staged Pk) ----------------
__global__ __launch_bounds__(256) void iter1_kernel(int last, float* __restrict__ out)
{
    int b = blockIdx.y, chunk = blockIdx.x;   // 64 chunks of 16 px
    int t = threadIdx.x, w = t >> 5, lane = t & 31;
    __shared__ float sPk[16*512];             // 32 KB
    __shared__ float sdots[NS][16];
    __shared__ float sscal[NS][5];

    float* attnDst = last ? (out + 16640) : g_attn0;
    float* relOut  = out + 16640 + 65536;
    int n0 = chunk*16;

    {
        const float4* src = (const float4*)(g_Pk + (((size_t)(b<<10) + n0)<<9));
        float4* dst = (float4*)sPk;
        #pragma unroll
        for (int i=0;i<8;i++) dst[t + i*256] = __ldg(src + t + i*256);
    }

    float4 u0v[4], u1v[4], wtv[4], cv[4];
    const float* wts = g_slot + (b*NS + w)*520;
    #pragma unroll
    for (int jj=0; jj<4; jj++){
        int j = jj*128 + lane*4;
        u0v[jj] = *(const float4*)(g_U0 + j);
        u1v[jj] = *(const float4*)(g_U1 + j);
        cv[jj]  = *(const float4*)(g_C  + j);
        wtv[jj] = *(const float4*)(wts  + j);
    }
    if (t < 40) sscal[t/5][t%5] = g_slot[(b*NS + t/5)*520 + 512 + (t%5)];
    __syncthreads();

    float qb2=sscal[w][0], px=sscal[w][1], py=sscal[w][2], i5x=sscal[w][3], i5y=sscal[w][4];
    float V00=g_cov[3], V11=g_cov[4], C01_2=2.f*g_cov[6];

    for (int pp=0; pp<16; pp++){
        int n = n0 + pp;
        float gx = -1.f + (float)(n>>5)*GSTEP;
        float gy = -1.f + (float)(n&31)*GSTEP;
        float a = (gx-px)*i5x, c = (gy-py)*i5y;
        const float4 st = *(const float4*)(g_statsK + ((b<<10)+n)*4);
        float var = st.x + a*st.y + c*st.z + a*a*V00 + c*c*V11 + a*c*C01_2;
        float isig = rsqrtf(var + LNEPS);
        const float* pk = sPk + pp*512;
        float ac0=0.f, ac1=0.f;
        #pragma unroll
        for (int jj=0; jj<4; jj++){
            float4 p4 = *(const float4*)(pk + jj*128 + lane*4);
            float e0 = fmaf(isig, fmaf(c,u1v[jj].x, fmaf(a,u0v[jj].x, p4.x)), cv[jj].x);
            float e1 = fmaf(isig, fmaf(c,u1v[jj].y, fmaf(a,u0v[jj].y, p4.y)), cv[jj].y);
            float e2 = fmaf(isig, fmaf(c,u1v[jj].z, fmaf(a,u0v[jj].z, p4.z)), cv[jj].z);
            float e3 = fmaf(isig, fmaf(c,u1v[jj].w, fmaf(a,u0v[jj].w, p4.w)), cv[jj].w);
            ac0 = fmaf(fmaxf(e0,0.f), wtv[jj].x, ac0);
            ac1 = fmaf(fmaxf(e1,0.f), wtv[jj].y, ac1);
            ac0 = fmaf(fmaxf(e2,0.f), wtv[jj].z, ac0);
            ac1 = fmaf(fmaxf(e3,0.f), wtv[jj].w, ac1);
        }
        float acc = warpSum(ac0 + ac1);
        if (lane == 0){
            sdots[w][pp] = ATTN_SCALE * (acc + qb2);
            if (last){
                float2* rp = (float2*)(relOut + ((((size_t)(b*NS+w)<<10)+n)<<1));
                *rp = make_float2(a, c);
            }
        }
    }
    __syncthreads();

    float a0 = 0.f, gx = 0.f, gy = 0.f;
    if (lane < 16){
        int n = n0 + lane;
        float dd[NS]; float mx = -1e30f;
        #pragma unroll
        for (int k=0;k<NS;k++){ dd[k] = sdots[k][lane]; mx = fmaxf(mx, dd[k]); }
        float sum = 0.f;
        #pragma unroll
        for (int k=0;k<NS;k++){ dd[k] = expf(dd[k]-mx); sum += dd[k]; }
        a0 = dd[w] / sum;
        attnDst[((b*NS+w)<<10) + n] = a0;
        gx = -1.f + (float)(n>>5)*GSTEP;
        gy = -1.f + (float)(n&31)*GSTEP;
    }
    float S0 = warpSum(a0);
    float Sx = warpSum(a0*gx);
    float Sy = warpSum(a0*gy);
    float Sxx = warpSum(a0*gx*gx);
    float Syy = warpSum(a0*gy*gy);
    if (lane == 0){
        float* pp = g_part + ((size_t)((b*NS+w)*64 + chunk))*8;
        pp[0]=S0; pp[1]=Sx; pp[2]=Sy; pp[3]=Sxx; pp[4]=Syy;
    }
}

// ---------------- slot-fused vacc + finalize (64 px/CTA, all 8 slots) ----------------
__global__ __launch_bounds__(512) void vaccF_kernel()
{
    int chunk = blockIdx.x;    // 0..15 (64 px each)
    int b = blockIdx.y;        // 0..7
    int t = threadIdx.x;
    __shared__ float4 sC4[NS][64];   // (is, is*a, is*c, w)
    __shared__ float sden[NS];

    int sl = t >> 6, p = t & 63;
    int n = chunk*64 + p;
    int gs = b*NS + sl;
    float rawA;
    {
        float px = g_slot[gs*520+513], py = g_slot[gs*520+514];
        float i5x= g_slot[gs*520+515], i5y= g_slot[gs*520+516];
        float gx = -1.f + (float)(n>>5)*GSTEP;
        float gy = -1.f + (float)(n&31)*GSTEP;
        float a = (gx-px)*i5x, c = (gy-py)*i5y;
        const float4 st = *(const float4*)(g_statsV + ((b<<10)+n)*4);
        float var = st.x + a*st.y + c*st.z + a*a*g_cov[3] + c*c*g_cov[4] + a*c*2.f*g_cov[6];
        float is = rsqrtf(var + LNEPS);
        rawA = g_attn0[(gs<<10)+n];
        sC4[sl][p] = make_float4(is, is*a, is*c, 0.f);
    }
    if (t < 256){
        int w = t >> 5, lane = t & 31;
        const float* pp0 = g_part + ((size_t)((b*NS+w)*64 + lane))*8;
        const float* pp1 = pp0 + 32*8;
        float S0 = warpSum(pp0[0] + pp1[0]);
        if (chunk == 0){
            float Sx = warpSum(pp0[1] + pp1[1]);
            float Sy = warpSum(pp0[2] + pp1[2]);
            float Sxx = warpSum(pp0[3] + pp1[3]);
            float Syy = warpSum(pp0[4] + pp1[4]);
            if (lane == 0){
                float px = Sx, py = Sy, G2 = g_cov[9];
                float vx = Sxx - 2.f*px*Sx + px*px*S0 + EPSA*(G2 + 1024.f*px*px);
                float vy = Syy - 2.f*py*Sy + py*py*S0 + EPSA*(G2 + 1024.f*py*py);
                float sx = fminf(fmaxf(sqrtf(fmaxf(vx,0.f)), 1e-3f), 2.f);
                float sy = fminf(fmaxf(sqrtf(fmaxf(vy,0.f)), 1e-3f), 2.f);
                int s2 = b*NS + w;
                g_Cond[s2*260+256]=px; g_Cond[s2*260+257]=py;
                g_Cond[s2*260+258]=sx; g_Cond[s2*260+259]=sy;
            }
        }
        if (lane == 0) sden[w] = 1.f/(S0 + 1024.f*EPSA);
    }
    __syncthreads();
    sC4[sl][p].w = (rawA + EPSA) * sden[sl];
    __syncthreads();

    float u0 = g_U0[t], u1 = g_U1[t], C = g_C[t];
    const float* pvb = g_Pv + ((((size_t)(b<<10)) + (size_t)chunk*64) << 9) + t;
    float acc[NS] = {};
    #pragma unroll 4
    for (int q=0; q<64; q++){
        float pv = __ldg(pvb + ((size_t)q << 9));
        #pragma unroll
        for (int s2=0; s2<NS; s2++){
            float4 cf = sC4[s2][q];
            float pre = fmaf(cf.y, u0, fmaf(cf.z, u1, fmaf(cf.x, pv, C)));
            acc[s2] = fmaf(fmaxf(pre, 0.f), cf.w, acc[s2]);
        }
    }
    #pragma unroll
    for (int s2=0; s2<NS; s2++)
        g_spart[((size_t)((b*NS+s2)*16 + chunk))*H + t] = acc[s2];
}

// ---------------- GRU update + slot prep for next iter (1024 threads) ----------------
__global__ __launch_bounds__(1024) void updslot_kernel(
    const float* __restrict__ W2,  const float* __restrict__ b2,
    const float* __restrict__ Wih, const float* __restrict__ Whh,
    const float* __restrict__ bih, const float* __restrict__ bhh,
    const float* __restrict__ ns_g, const float* __restrict__ ns_b,
    const float* __restrict__ wq)
{
    __shared__ float ss[H], so[256], su[256], qpart[1024], sgx[768], sgh[768], sh[256], sq[256], red[16];
    int s = blockIdx.x, t = threadIdx.x, w = t >> 5, lane = t & 31;

    if (t < 512){
        float r0 = 0.f;
        #pragma unroll
        for (int c=0; c<16; c++) r0 += g_spart[((size_t)(s*16 + c))*H + t];
        ss[t] = r0;
    }
    if (t < 256) so[t] = g_Cond[s*260 + t];
    __syncthreads();

    int tt = t & 255, qr = t >> 8;
    float u = 0.f;
    #pragma unroll 4
    for (int j = qr*128; j < qr*128 + 128; j++)
        u = fmaf(ss[j], W2[j*D + tt], u);
    qpart[t] = u;
    __syncthreads();
    if (t < 256) su[t] = qpart[t] + qpart[256+t] + qpart[512+t] + qpart[768+t] + b2[t];
    __syncthreads();

    // GRU matvecs: warp-per-row, 2 rows per iter for shuffle ILP (32 warps x 12 iters x 2 rows)
    #pragma unroll
    for (int k = 0; k < 12; k++){
        int i0 = (k << 6) + w;
        int i1 = i0 + 32;
        const float* wi0 = Wih + i0*D; const float* wh0 = Whh + i0*D;
        const float* wi1 = Wih + i1*D; const float* wh1 = Whh + i1*D;
        float ax0=0.f, ah0=0.f, ax1=0.f, ah1=0.f;
        #pragma unroll
        for (int dd=0; dd<8; dd++){
            int dx = dd*32 + lane;
            float suv = su[dx], sov = so[dx];
            ax0 = fmaf(wi0[dx], suv, ax0);
            ah0 = fmaf(wh0[dx], sov, ah0);
            ax1 = fmaf(wi1[dx], suv, ax1);
            ah1 = fmaf(wh1[dx], sov, ah1);
        }
        ax0 = warpSum(ax0); ah0 = warpSum(ah0);
        ax1 = warpSum(ax1); ah1 = warpSum(ah1);
        if (lane == 0){
            sgx[i0] = ax0 + bih[i0]; sgh[i0] = ah0 + bhh[i0];
            sgx[i1] = ax1 + bih[i1]; sgh[i1] = ah1 + bhh[i1];
        }
    }
    __syncthreads();

    if (t < 256){
        float r = 1.f/(1.f + expf(-(sgx[t]     + sgh[t])));
        float z = 1.f/(1.f + expf(-(sgx[256+t] + sgh[256+t])));
        float nn = tanhf(sgx[512+t] + r*sgh[512+t]);
        float nv = (1.f - z)*nn + z*so[t];
        g_Cond[s*260 + t] = nv;
        so[t] = nv;
    }
    __syncthreads();

    slot_compute(s, t, so, ns_g, ns_b, wq, W2, b2, sh, sq, qpart, red);
}

// ---------------- final: pos/scl + write conditioning to out ----------------
__global__ void finz3_kernel(float* __restrict__ out)
{
    __shared__ float sres[4];
    int s = blockIdx.x, t = threadIdx.x;
    if (t < 32){
        const float* pp0 = g_part + ((size_t)(s*64 + t))*8;
        const float* pp1 = pp0 + 32*8;
        float S0 = warpSum(pp0[0] + pp1[0]);
        float Sx = warpSum(pp0[1] + pp1[1]);
        float Sy = warpSum(pp0[2] + pp1[2]);
        float Sxx = warpSum(pp0[3] + pp1[3]);
        float Syy = warpSum(pp0[4] + pp1[4]);
        if (t == 0){
            float px = Sx, py = Sy, G2 = g_cov[9];
            float vx = Sxx - 2.f*px*Sx + px*px*S0 + EPSA*(G2 + 1024.f*px*px);
            float vy = Syy - 2.f*py*Sy + py*py*S0 + EPSA*(G2 + 1024.f*py*py);
            float sx = fminf(fmaxf(sqrtf(fmaxf(vx,0.f)), 1e-3f), 2.f);
            float sy = fminf(fmaxf(sqrtf(fmaxf(vy,0.f)), 1e-3f), 2.f);
            sres[0]=px; sres[1]=py; sres[2]=sx; sres[3]=sy;
        }
    }
    __syncthreads();
    for (int i = t; i < 260; i += 256)
        out[s*260 + i] = (i < 256) ? g_Cond[s*260 + i] : sres[i - 256];
}

// ---------------- launch ----------------
extern "C" void kernel_launch(void* const* d_in, const int* in_sizes, int n_in,
                              void* d_out, int out_size)
{
    const float* inputs = (const float*)d_in[0];
    const float* cond   = (const float*)d_in[1];
    const float* ni_g   = (const float*)d_in[2];
    const float* ni_b   = (const float*)d_in[3];
    const float* ns_g   = (const float*)d_in[4];
    const float* ns_b   = (const float*)d_in[5];
    const float* wq     = (const float*)d_in[6];
    const float* wk     = (const float*)d_in[7];
    const float* wv     = (const float*)d_in[8];
    const float* gp_w   = (const float*)d_in[9];
    const float* gp_b   = (const float*)d_in[10];
    const float* ge_ln_g= (const float*)d_in[11];
    const float* ge_ln_b= (const float*)d_in[12];
    const float* ge_w1  = (const float*)d_in[13];
    const float* ge_b1  = (const float*)d_in[14];
    const float* ge_w2  = (const float*)d_in[15];
    const float* ge_b2  = (const float*)d_in[16];
    const float* gru_wih= (const float*)d_in[17];
    const float* gru_whh= (const float*)d_in[18];
    const float* gru_bih= (const float*)d_in[19];
    const float* gru_bhh= (const float*)d_in[20];
    float* out = (float*)d_out;

    pre_kernel<<<546, 512>>>(gp_w, gp_b, ge_ln_g, ge_ln_b, ge_w1, ge_b1, cond, inputs);
    gemm2<<<dim3(2,64,2), 256>>>(0, inputs, wk, wv, ni_g, ni_b, 256);
    stats2<<<512, 512>>>(gp_w, gp_b);
    gemm2<<<dim3(4,64,2), 256>>>(2, nullptr, ge_w1, ge_w1, ge_ln_g, nullptr, 512);
    slot0<<<64, 1024>>>(ns_g, ns_b, wq, ge_w2, ge_b2);

    for (int it = 0; it < 3; it++) {
        iter1_kernel<<<dim3(64,8), 256>>>(0, out);
        vaccF_kernel<<<dim3(16,8), 512>>>();
        updslot_kernel<<<64, 1024>>>(ge_w2, ge_b2, gru_wih, gru_whh, gru_bih, gru_bhh,
                                     ns_g, ns_b, wq);
    }
    iter1_kernel<<<dim3(64,8), 256>>>(1, out);
    finz3_kernel<<<64, 256>>>(out);
}